// round 7
// baseline (speedup 1.0000x reference)
#include <cuda_runtime.h>
#include <cuda_bf16.h>
#include <mma.h>
#include <math.h>
#include <cstdint>
#include <cstddef>
using namespace nvcuda;

#define LNUM 6
#define DMOD 768
#define HNUM 12
#define DKH  64
#define FFD  3072
#define VOC  50257
#define SEQ  1024
#define BAT  2
#define MTOK (BAT*SEQ)   // 2048
#define QKVN (3*DMOD)    // 2304

// ---------------- device scratch ----------------
__device__ float g_x  [MTOK*DMOD];
__device__ float g_qkv[MTOK*QKVN];
__device__ __nv_bfloat16 g_h_h [MTOK*DMOD],  g_h_l [MTOK*DMOD];
__device__ __nv_bfloat16 g_att_h[MTOK*DMOD], g_att_l[MTOK*DMOD];
__device__ __nv_bfloat16 g_ff_h[MTOK*FFD],   g_ff_l[MTOK*FFD];
// pre-split weights
__device__ __nv_bfloat16 g_wqkv_h[LNUM*DMOD*QKVN], g_wqkv_l[LNUM*DMOD*QKVN];
__device__ __nv_bfloat16 g_wo_h [LNUM*DMOD*DMOD],  g_wo_l [LNUM*DMOD*DMOD];
__device__ __nv_bfloat16 g_w1_h [LNUM*DMOD*FFD],   g_w1_l [LNUM*DMOD*FFD];
__device__ __nv_bfloat16 g_w2_h [LNUM*FFD*DMOD],   g_w2_l [LNUM*FFD*DMOD];
__device__ __nv_bfloat16 g_emb_h[VOC*DMOD],        g_emb_l[VOC*DMOD];

// ---------------- helpers ----------------
__device__ __forceinline__ uint32_t smem_u32(const void* p) {
    uint32_t a;
    asm("{ .reg .u64 t; cvta.to.shared.u64 t, %1; cvt.u32.u64 %0, t; }" : "=r"(a) : "l"(p));
    return a;
}
__device__ __forceinline__ void cpa16(uint32_t dst, const void* src) {
    asm volatile("cp.async.cg.shared.global [%0], [%1], 16;" :: "r"(dst), "l"(src));
}
#define CP_COMMIT() asm volatile("cp.async.commit_group;" ::: "memory")
#define CP_WAIT1()  asm volatile("cp.async.wait_group 1;" ::: "memory")

__device__ __forceinline__ void split2(float v, __nv_bfloat16& hi, __nv_bfloat16& lo) {
    hi = __float2bfloat16(v);
    lo = __float2bfloat16(v - __bfloat162float(hi));
}

// ---------------- merged prepass split kernel ----------------
#define N_QKV (LNUM*DMOD*QKVN)
#define N_WO  (LNUM*DMOD*DMOD)
#define N_W1  (LNUM*DMOD*FFD)
#define N_W2  (LNUM*FFD*DMOD)
#define N_EMB (VOC*DMOD)
#define N_SPLIT_TOT (N_QKV + N_WO + N_W1 + N_W2 + N_EMB)

__global__ void split_all_kernel(const float* __restrict__ wq, const float* __restrict__ wk,
                                 const float* __restrict__ wv, const float* __restrict__ wo,
                                 const float* __restrict__ w1, const float* __restrict__ w2,
                                 const float* __restrict__ emb,
                                 __nv_bfloat16* __restrict__ qkv_h, __nv_bfloat16* __restrict__ qkv_l,
                                 __nv_bfloat16* __restrict__ wo_h,  __nv_bfloat16* __restrict__ wo_l,
                                 __nv_bfloat16* __restrict__ w1_h,  __nv_bfloat16* __restrict__ w1_l,
                                 __nv_bfloat16* __restrict__ w2_h,  __nv_bfloat16* __restrict__ w2_l,
                                 __nv_bfloat16* __restrict__ emb_h, __nv_bfloat16* __restrict__ emb_l) {
    int i = blockIdx.x * blockDim.x + threadIdx.x;
    if (i >= N_SPLIT_TOT) return;
    if (i < N_QKV) {
        int l = i / (DMOD * QKVN);
        int rem = i % (DMOD * QKVN);
        int k = rem / QKVN, j = rem % QKVN;
        const float* s = (j < DMOD) ? wq : (j < 2 * DMOD) ? wk : wv;
        float v = s[(size_t)l * DMOD * DMOD + (size_t)k * DMOD + (j % DMOD)];
        split2(v, qkv_h[i], qkv_l[i]);
        return;
    }
    i -= N_QKV;
    if (i < N_WO)  { split2(wo[i],  wo_h[i],  wo_l[i]);  return; }
    i -= N_WO;
    if (i < N_W1)  { split2(w1[i],  w1_h[i],  w1_l[i]);  return; }
    i -= N_W1;
    if (i < N_W2)  { split2(w2[i],  w2_h[i],  w2_l[i]);  return; }
    i -= N_W2;
    split2(emb[i], emb_h[i], emb_l[i]);
}

// ---------------- embedding ----------------
__global__ void embed_kernel(const int* __restrict__ ids, const float* __restrict__ emb,
                             const float* __restrict__ pe, float* __restrict__ X) {
    int i = blockIdx.x * blockDim.x + threadIdx.x;
    if (i >= MTOK * DMOD) return;
    int d = i % DMOD, t = i / DMOD, s = t % SEQ;
    X[i] = emb[(size_t)ids[t] * DMOD + d] + pe[s * DMOD + d];
}

// ---------------- layernorm -> bf16 hi/lo ----------------
__global__ void ln_kernel(const float* __restrict__ X, const float* __restrict__ w,
                          const float* __restrict__ bvec,
                          __nv_bfloat16* __restrict__ Yh, __nv_bfloat16* __restrict__ Yl) {
    __shared__ float red[256];
    int row = blockIdx.x, tid = threadIdx.x;
    const float* x = X + (size_t)row * DMOD;
    float s = 0.f;
    for (int i = tid; i < DMOD; i += 256) s += x[i];
    red[tid] = s; __syncthreads();
    for (int o = 128; o > 0; o >>= 1) { if (tid < o) red[tid] += red[tid + o]; __syncthreads(); }
    float mu = red[0] * (1.0f / DMOD); __syncthreads();
    float v = 0.f;
    for (int i = tid; i < DMOD; i += 256) { float t = x[i] - mu; v += t * t; }
    red[tid] = v; __syncthreads();
    for (int o = 128; o > 0; o >>= 1) { if (tid < o) red[tid] += red[tid + o]; __syncthreads(); }
    float rstd = rsqrtf(red[0] * (1.0f / DMOD) + 1e-5f);
    for (int i = tid; i < DMOD; i += 256) {
        float y = (x[i] - mu) * rstd * w[i] + bvec[i];
        __nv_bfloat16 hi, lo; split2(y, hi, lo);
        Yh[(size_t)row * DMOD + i] = hi;
        Yl[(size_t)row * DMOD + i] = lo;
    }
}

// ---------------- GEMM: pre-split bf16, cp.async 3-stage, WMMA 3-term, 2 CTAs/SM ----------------
#define EP_BIAS 1
#define EP_GELU 2
#define EP_RES  4

__device__ __forceinline__ float gelu_exact(float x) {
    return 0.5f * x * (1.0f + erff(x * 0.70710678118654752f));
}

template<int EP, bool BCOL, bool NG, int TN, bool WH>
__global__ void __launch_bounds__(256, 2)
gemm_tc(const __nv_bfloat16* __restrict__ Ah_g, const __nv_bfloat16* __restrict__ Al_g,
        const __nv_bfloat16* __restrict__ Bh_g, const __nv_bfloat16* __restrict__ Bl_g,
        const float* __restrict__ bias, const float* __restrict__ res,
        float* __restrict__ C, __nv_bfloat16* __restrict__ Chi, __nv_bfloat16* __restrict__ Clo,
        int M, int N, int K, int ldb, int ldc) {
    constexpr int ALD = 40;
    constexpr int BLD = BCOL ? 40 : (TN + 8);
    constexpr int ABYTES = 128 * ALD * 2;
    constexpr int BBYTES = BCOL ? (TN * 40 * 2) : (32 * BLD * 2);
    constexpr int STAGEB = 2 * (ABYTES + BBYTES);
    constexpr int NJ = TN / 32;      // j-subtiles per warp

    extern __shared__ char smem[];
    uint32_t sbase = smem_u32(smem);

    int tid = threadIdx.x, lane = tid & 31, wid = tid >> 5;
    int warp_m = wid & 3, warp_n = wid >> 2;
    int bm, bn;
    if (BCOL) { bm = blockIdx.x * 128; bn = blockIdx.y * TN; }   // m fastest -> L2 reuse of B
    else      { bm = blockIdx.y * 128; bn = blockIdx.x * TN; }
    int nch = K >> 5;

    wmma::fragment<wmma::accumulator, 16, 16, 16, float> acc[2][NJ];
    #pragma unroll
    for (int i = 0; i < 2; i++)
        #pragma unroll
        for (int j = 0; j < NJ; j++) wmma::fill_fragment(acc[i][j], 0.f);

    auto load_stage = [&](int s, int c) {
        int k0 = c * 32;
        uint32_t abase = sbase + s * STAGEB;
        #pragma unroll
        for (int hn = 0; hn < 2; hn++) {
            const __nv_bfloat16* g = hn ? Al_g : Ah_g;
            uint32_t db = abase + hn * ABYTES;
            #pragma unroll
            for (int i = 0; i < 2; i++) {
                int cid = tid + i * 256;
                int r = cid >> 2, seg = cid & 3;
                cpa16(db + (uint32_t)(r * ALD + seg * 8) * 2,
                      g + (size_t)(bm + r) * K + k0 + seg * 8);
            }
        }
        uint32_t bbase = abase + 2 * ABYTES;
        if (BCOL) {
            constexpr int NITB = (TN * 4) / 256;
            #pragma unroll
            for (int hn = 0; hn < 2; hn++) {
                const __nv_bfloat16* g = hn ? Bl_g : Bh_g;
                uint32_t db = bbase + hn * BBYTES;
                #pragma unroll
                for (int i = 0; i < NITB; i++) {
                    int cid = tid + i * 256;
                    int r = cid >> 2, seg = cid & 3;
                    int gn = bn + r;
                    uint32_t d = db + (uint32_t)(r * 40 + seg * 8) * 2;
                    if (!NG || gn < N)
                        cpa16(d, g + (size_t)gn * ldb + k0 + seg * 8);
                    else
                        *reinterpret_cast<uint4*>(smem + (d - sbase)) = make_uint4(0, 0, 0, 0);
                }
            }
        } else {
            constexpr int CH = TN / 8;
            constexpr int NIT = (32 * CH) / 256;
            #pragma unroll
            for (int hn = 0; hn < 2; hn++) {
                const __nv_bfloat16* g = hn ? Bl_g : Bh_g;
                uint32_t db = bbase + hn * BBYTES;
                #pragma unroll
                for (int i = 0; i < NIT; i++) {
                    int cid = tid + i * 256;
                    int kr = cid / CH, seg = cid % CH;
                    cpa16(db + (uint32_t)(kr * BLD + seg * 8) * 2,
                          g + (size_t)(k0 + kr) * ldb + bn + seg * 8);
                }
            }
        }
        CP_COMMIT();
    };

    auto do_mma = [&](int s) {
        char* base = smem + s * STAGEB;
        __nv_bfloat16* Ah = reinterpret_cast<__nv_bfloat16*>(base);
        __nv_bfloat16* Al = reinterpret_cast<__nv_bfloat16*>(base + ABYTES);
        __nv_bfloat16* Bh = reinterpret_cast<__nv_bfloat16*>(base + 2 * ABYTES);
        __nv_bfloat16* Bl = reinterpret_cast<__nv_bfloat16*>(base + 2 * ABYTES + BBYTES);
        #pragma unroll
        for (int kk = 0; kk < 2; kk++) {
            wmma::fragment<wmma::matrix_a, 16, 16, 16, __nv_bfloat16, wmma::row_major> ah[2], al[2];
            #pragma unroll
            for (int i = 0; i < 2; i++) {
                wmma::load_matrix_sync(ah[i], Ah + (warp_m * 32 + i * 16) * ALD + kk * 16, ALD);
                wmma::load_matrix_sync(al[i], Al + (warp_m * 32 + i * 16) * ALD + kk * 16, ALD);
            }
            #pragma unroll
            for (int j = 0; j < NJ; j++) {
                if (BCOL) {
                    wmma::fragment<wmma::matrix_b, 16, 16, 16, __nv_bfloat16, wmma::col_major> bh, bl;
                    wmma::load_matrix_sync(bh, Bh + (warp_n * (TN / 2) + j * 16) * 40 + kk * 16, 40);
                    wmma::load_matrix_sync(bl, Bl + (warp_n * (TN / 2) + j * 16) * 40 + kk * 16, 40);
                    #pragma unroll
                    for (int i = 0; i < 2; i++) {
                        wmma::mma_sync(acc[i][j], ah[i], bh, acc[i][j]);
                        wmma::mma_sync(acc[i][j], ah[i], bl, acc[i][j]);
                        wmma::mma_sync(acc[i][j], al[i], bh, acc[i][j]);
                    }
                } else {
                    wmma::fragment<wmma::matrix_b, 16, 16, 16, __nv_bfloat16, wmma::row_major> bh, bl;
                    wmma::load_matrix_sync(bh, Bh + (kk * 16) * BLD + warp_n * (TN / 2) + j * 16, BLD);
                    wmma::load_matrix_sync(bl, Bl + (kk * 16) * BLD + warp_n * (TN / 2) + j * 16, BLD);
                    #pragma unroll
                    for (int i = 0; i < 2; i++) {
                        wmma::mma_sync(acc[i][j], ah[i], bh, acc[i][j]);
                        wmma::mma_sync(acc[i][j], ah[i], bl, acc[i][j]);
                        wmma::mma_sync(acc[i][j], al[i], bh, acc[i][j]);
                    }
                }
            }
        }
    };

    // 3-stage pipeline, ONE barrier per chunk
    load_stage(0, 0);
    load_stage(1, 1);
    for (int c = 0; c < nch; c++) {
        CP_WAIT1();           // stage c's loads complete
        __syncthreads();      // also: all warps done consuming stage (c-1) => safe to refill (c+2)%3
        if (c + 2 < nch) load_stage((c + 2) % 3, c + 2);
        else CP_COMMIT();     // keep group counting exact
        do_mma(c % 3);
    }
    __syncthreads();

    // epilogue: per-warp smem staging (reuse stage 0)
    float* stg = reinterpret_cast<float*>(smem) + wid * (16 * 20);
    int r = lane >> 1, cb = (lane & 1) * 8;
    #pragma unroll
    for (int i = 0; i < 2; i++) {
        #pragma unroll
        for (int j = 0; j < NJ; j++) {
            wmma::store_matrix_sync(stg, acc[i][j], 20, wmma::mem_row_major);
            __syncwarp();
            int m = bm + warp_m * 32 + i * 16 + r;
            int n0 = bn + warp_n * (TN / 2) + j * 16 + cb;
            #pragma unroll
            for (int q = 0; q < 8; q++) {
                int n = n0 + q;
                float v = stg[r * 20 + cb + q];
                if (EP & EP_BIAS) v += bias[n];
                if (EP & EP_GELU) v = gelu_exact(v);
                if (EP & EP_RES)  v += res[(size_t)m * ldc + n];
                if (!NG || n < N) {
                    if (WH) {
                        __nv_bfloat16 hi, lo; split2(v, hi, lo);
                        Chi[(size_t)m * ldc + n] = hi;
                        Clo[(size_t)m * ldc + n] = lo;
                    } else {
                        C[(size_t)m * ldc + n] = v;
                    }
                }
            }
            __syncwarp();
        }
    }
}

// ---------------- flash-style SIMT attention ----------------
#define APD 68
#define ATT_SMEM ((4*64*APD + 3*64)*4 + 64*4)

__global__ void __launch_bounds__(256)
attn_kernel(const float* __restrict__ QKV, const int* __restrict__ amask,
            __nv_bfloat16* __restrict__ Oh, __nv_bfloat16* __restrict__ Ol) {
    extern __shared__ char asmem[];
    float* Qt = reinterpret_cast<float*>(asmem);            // [d][i]
    float* Kt = Qt + 64 * APD;                              // [d][j]
    float* Vs = Kt + 64 * APD;                              // [j][d]
    float* Pt = Vs + 64 * APD;                              // [j][i]
    float* sm_m = Pt + 64 * APD;
    float* sm_l = sm_m + 64;
    float* sm_s = sm_l + 64;
    int*   msk  = reinterpret_cast<int*>(sm_s + 64);

    int b = blockIdx.z, h = blockIdx.y, qt = blockIdx.x;
    int tid = threadIdx.x;
    int q0 = qt * 64;
    int ty = tid >> 4, tx = tid & 15;

    for (int idx = tid; idx < 64 * 64; idx += 256) {
        int i = idx >> 6, d = idx & 63;
        Qt[d * APD + i] = QKV[(size_t)(b * SEQ + q0 + i) * QKVN + h * DKH + d] * 0.125f;
    }
    if (tid < 64) { sm_m[tid] = -1e30f; sm_l[tid] = 0.f; }

    float o[4][4] = {};
    int ntile = qt + 1;

    for (int kt = 0; kt < ntile; kt++) {
        int k0 = kt * 64;
        __syncthreads();
        for (int idx = tid; idx < 64 * 64; idx += 256) {
            int j = idx >> 6, d = idx & 63;
            Kt[d * APD + j] = QKV[(size_t)(b * SEQ + k0 + j) * QKVN + DMOD + h * DKH + d];
        }
        for (int idx = tid; idx < 64 * 16; idx += 256) {
            int j = idx >> 4, s4 = idx & 15;
            float4 vv = *reinterpret_cast<const float4*>(
                &QKV[(size_t)(b * SEQ + k0 + j) * QKVN + 2 * DMOD + h * DKH + s4 * 4]);
            *reinterpret_cast<float4*>(&Vs[j * APD + s4 * 4]) = vv;
        }
        if (tid < 64) msk[tid] = amask[b * SEQ + k0 + tid];
        __syncthreads();

        float s[4][4] = {};
        for (int d = 0; d < 64; d++) {
            float4 qv = *reinterpret_cast<float4*>(&Qt[d * APD + ty * 4]);
            float4 kv = *reinterpret_cast<float4*>(&Kt[d * APD + tx * 4]);
            float qa[4] = {qv.x, qv.y, qv.z, qv.w};
            float ka[4] = {kv.x, kv.y, kv.z, kv.w};
            #pragma unroll
            for (int rr = 0; rr < 4; rr++)
                #pragma unroll
                for (int cc = 0; cc < 4; cc++) s[rr][cc] += qa[rr] * ka[cc];
        }
        #pragma unroll
        for (int rr = 0; rr < 4; rr++)
            #pragma unroll
            for (int cc = 0; cc < 4; cc++) {
                int i = ty * 4 + rr, j = tx * 4 + cc;
                float v = s[rr][cc];
                if (msk[j] == 0 || (k0 + j) > (q0 + i)) v = -1e9f;
                Pt[j * APD + i] = v;
            }
        __syncthreads();

        {
            int row = tid >> 2, qq = tid & 3;
            float tmax = -1e30f;
            #pragma unroll
            for (int jj = 0; jj < 16; jj++) tmax = fmaxf(tmax, Pt[(qq * 16 + jj) * APD + row]);
            tmax = fmaxf(tmax, __shfl_xor_sync(0xffffffff, tmax, 1));
            tmax = fmaxf(tmax, __shfl_xor_sync(0xffffffff, tmax, 2));
            float mold = sm_m[row];
            float newm = fmaxf(mold, tmax);
            float psum = 0.f;
            #pragma unroll
            for (int jj = 0; jj < 16; jj++) {
                int j = qq * 16 + jj;
                float p = __expf(Pt[j * APD + row] - newm);
                Pt[j * APD + row] = p;
                psum += p;
            }
            psum += __shfl_xor_sync(0xffffffff, psum, 1);
            psum += __shfl_xor_sync(0xffffffff, psum, 2);
            if (qq == 0) {
                float sc = __expf(mold - newm);
                sm_s[row] = sc;
                sm_l[row] = sm_l[row] * sc + psum;
                sm_m[row] = newm;
            }
        }
        __syncthreads();

        {
            float sc[4];
            #pragma unroll
            for (int rr = 0; rr < 4; rr++) sc[rr] = sm_s[ty * 4 + rr];
            #pragma unroll
            for (int rr = 0; rr < 4; rr++)
                #pragma unroll
                for (int cc = 0; cc < 4; cc++) o[rr][cc] *= sc[rr];
            for (int j = 0; j < 64; j++) {
                float4 pv = *reinterpret_cast<float4*>(&Pt[j * APD + ty * 4]);
                float4 vv = *reinterpret_cast<float4*>(&Vs[j * APD + tx * 4]);
                float pa[4] = {pv.x, pv.y, pv.z, pv.w};
                float va[4] = {vv.x, vv.y, vv.z, vv.w};
                #pragma unroll
                for (int rr = 0; rr < 4; rr++)
                    #pragma unroll
                    for (int cc = 0; cc < 4; cc++) o[rr][cc] += pa[rr] * va[cc];
            }
        }
    }
    __syncthreads();
    {
        float inv[4];
        #pragma unroll
        for (int rr = 0; rr < 4; rr++) inv[rr] = 1.0f / sm_l[ty * 4 + rr];
        #pragma unroll
        for (int rr = 0; rr < 4; rr++)
            #pragma unroll
            for (int cc = 0; cc < 4; cc++) {
                size_t off = (size_t)(b * SEQ + q0 + ty * 4 + rr) * DMOD + h * DKH + tx * 4 + cc;
                float v = o[rr][cc] * inv[rr];
                __nv_bfloat16 hi, lo; split2(v, hi, lo);
                Oh[off] = hi; Ol[off] = lo;
            }
    }
}

// ---------------- launch ----------------
extern "C" void kernel_launch(void* const* d_in, const int* in_sizes, int n_in,
                              void* d_out, int out_size) {
    const int*   ids   = (const int*)  d_in[0];
    const int*   amask = (const int*)  d_in[1];
    const float* emb   = (const float*)d_in[2];
    const float* pe    = (const float*)d_in[3];
    const float* wq    = (const float*)d_in[4];
    const float* wk    = (const float*)d_in[5];
    const float* wv    = (const float*)d_in[6];
    const float* wo    = (const float*)d_in[7];
    const float* ln1w  = (const float*)d_in[8];
    const float* ln1b  = (const float*)d_in[9];
    const float* ln2w  = (const float*)d_in[10];
    const float* ln2b  = (const float*)d_in[11];
    const float* w1    = (const float*)d_in[12];
    const float* b1    = (const float*)d_in[13];
    const float* w2    = (const float*)d_in[14];
    const float* b2    = (const float*)d_in[15];
    const float* lnfw  = (const float*)d_in[16];
    const float* lnfb  = (const float*)d_in[17];
    float* out = (float*)d_out;

    float *x, *qkv;
    __nv_bfloat16 *h_h, *h_l, *att_h, *att_l, *ff_h, *ff_l;
    __nv_bfloat16 *wqkv_h, *wqkv_l, *wo_h, *wo_l, *w1_h, *w1_l, *w2_h, *w2_l, *emb_h, *emb_l;
    cudaGetSymbolAddress((void**)&x,     g_x);
    cudaGetSymbolAddress((void**)&qkv,   g_qkv);
    cudaGetSymbolAddress((void**)&h_h,   g_h_h);   cudaGetSymbolAddress((void**)&h_l,   g_h_l);
    cudaGetSymbolAddress((void**)&att_h, g_att_h); cudaGetSymbolAddress((void**)&att_l, g_att_l);
    cudaGetSymbolAddress((void**)&ff_h,  g_ff_h);  cudaGetSymbolAddress((void**)&ff_l,  g_ff_l);
    cudaGetSymbolAddress((void**)&wqkv_h, g_wqkv_h); cudaGetSymbolAddress((void**)&wqkv_l, g_wqkv_l);
    cudaGetSymbolAddress((void**)&wo_h,  g_wo_h);  cudaGetSymbolAddress((void**)&wo_l,  g_wo_l);
    cudaGetSymbolAddress((void**)&w1_h,  g_w1_h);  cudaGetSymbolAddress((void**)&w1_l,  g_w1_l);
    cudaGetSymbolAddress((void**)&w2_h,  g_w2_h);  cudaGetSymbolAddress((void**)&w2_l,  g_w2_l);
    cudaGetSymbolAddress((void**)&emb_h, g_emb_h); cudaGetSymbolAddress((void**)&emb_l, g_emb_l);

    // smem per variant (3-stage)
    const int SM_T128 = 3 * (2 * (128 * 40 * 2) + 2 * (32 * 136 * 2));   // 113664
    const int SM_T64  = 3 * (2 * (128 * 40 * 2) + 2 * (32 * 72 * 2));    // 89088
    const int SM_C64  = 3 * (2 * (128 * 40 * 2) + 2 * (64 * 40 * 2));    // 92160

    cudaFuncSetAttribute(gemm_tc<0, false, false, 128, false>,                cudaFuncAttributeMaxDynamicSharedMemorySize, SM_T128);
    cudaFuncSetAttribute(gemm_tc<EP_RES, false, false, 64, false>,            cudaFuncAttributeMaxDynamicSharedMemorySize, SM_T64);
    cudaFuncSetAttribute(gemm_tc<EP_BIAS | EP_GELU, false, false, 128, true>, cudaFuncAttributeMaxDynamicSharedMemorySize, SM_T128);
    cudaFuncSetAttribute(gemm_tc<EP_BIAS | EP_RES, false, false, 64, false>,  cudaFuncAttributeMaxDynamicSharedMemorySize, SM_T64);
    cudaFuncSetAttribute(gemm_tc<0, true, true, 64, false>,                   cudaFuncAttributeMaxDynamicSharedMemorySize, SM_C64);
    cudaFuncSetAttribute(attn_kernel, cudaFuncAttributeMaxDynamicSharedMemorySize, ATT_SMEM);

    // prepass (1 launch) + embedding
    split_all_kernel<<<(N_SPLIT_TOT + 255) / 256, 256>>>(
        wq, wk, wv, wo, w1, w2, emb,
        wqkv_h, wqkv_l, wo_h, wo_l, w1_h, w1_l, w2_h, w2_l, emb_h, emb_l);
    { int n = MTOK * DMOD; embed_kernel<<<(n + 255) / 256, 256>>>(ids, emb, pe, x); }

    dim3 gQKV(QKVN / 128, MTOK / 128);   // 18 x 16
    dim3 gD64(DMOD / 64, MTOK / 128);    // 12 x 16
    dim3 gF(FFD / 128, MTOK / 128);      // 24 x 16

    for (int l = 0; l < LNUM; l++) {
        ln_kernel<<<MTOK, 256>>>(x, ln1w + l * DMOD, ln1b + l * DMOD, h_h, h_l);

        gemm_tc<0, false, false, 128, false><<<gQKV, 256, SM_T128>>>(
            h_h, h_l, wqkv_h + (size_t)l * DMOD * QKVN, wqkv_l + (size_t)l * DMOD * QKVN,
            nullptr, nullptr, qkv, nullptr, nullptr, MTOK, QKVN, DMOD, QKVN, QKVN);

        attn_kernel<<<dim3(SEQ / 64, HNUM, BAT), 256, ATT_SMEM>>>(qkv, amask, att_h, att_l);

        gemm_tc<EP_RES, false, false, 64, false><<<gD64, 256, SM_T64>>>(
            att_h, att_l, wo_h + (size_t)l * DMOD * DMOD, wo_l + (size_t)l * DMOD * DMOD,
            nullptr, x, x, nullptr, nullptr, MTOK, DMOD, DMOD, DMOD, DMOD);

        ln_kernel<<<MTOK, 256>>>(x, ln2w + l * DMOD, ln2b + l * DMOD, h_h, h_l);

        gemm_tc<EP_BIAS | EP_GELU, false, false, 128, true><<<gF, 256, SM_T128>>>(
            h_h, h_l, w1_h + (size_t)l * DMOD * FFD, w1_l + (size_t)l * DMOD * FFD,
            b1 + (size_t)l * FFD, nullptr, nullptr, ff_h, ff_l, MTOK, FFD, DMOD, FFD, FFD);

        gemm_tc<EP_BIAS | EP_RES, false, false, 64, false><<<gD64, 256, SM_T64>>>(
            ff_h, ff_l, w2_h + (size_t)l * FFD * DMOD, w2_l + (size_t)l * FFD * DMOD,
            b2 + (size_t)l * DMOD, x, x, nullptr, nullptr, MTOK, DMOD, FFD, DMOD, DMOD);
    }

    ln_kernel<<<MTOK, 256>>>(x, lnfw, lnfb, h_h, h_l);

    // lm_head: TN=64, m-tiles fastest (blockIdx.x) so each wave reuses B slices from L2
    dim3 gV(MTOK / 128, (VOC + 63) / 64);
    gemm_tc<0, true, true, 64, false><<<gV, 256, SM_C64>>>(
        h_h, h_l, emb_h, emb_l, nullptr, nullptr, out, nullptr, nullptr, MTOK, VOC, DMOD, DMOD, VOC);
}

// round 8
// speedup vs baseline: 1.1241x; 1.1241x over previous
#include <cuda_runtime.h>
#include <cuda_bf16.h>
#include <mma.h>
#include <math.h>
#include <cstdint>
#include <cstddef>
using namespace nvcuda;

#define LNUM 6
#define DMOD 768
#define HNUM 12
#define DKH  64
#define FFD  3072
#define VOC  50257
#define SEQ  1024
#define BAT  2
#define MTOK (BAT*SEQ)   // 2048
#define QKVN (3*DMOD)    // 2304

// ---------------- device scratch ----------------
__device__ float g_x  [MTOK*DMOD];
__device__ __nv_bfloat16 g_qkvh[MTOK*QKVN], g_qkvl[MTOK*QKVN];
__device__ __nv_bfloat16 g_h_h [MTOK*DMOD],  g_h_l [MTOK*DMOD];
__device__ __nv_bfloat16 g_att_h[MTOK*DMOD], g_att_l[MTOK*DMOD];
__device__ __nv_bfloat16 g_ff_h[MTOK*FFD],   g_ff_l[MTOK*FFD];
__device__ __nv_bfloat16 g_wqkv_h[LNUM*DMOD*QKVN], g_wqkv_l[LNUM*DMOD*QKVN];
__device__ __nv_bfloat16 g_wo_h [LNUM*DMOD*DMOD],  g_wo_l [LNUM*DMOD*DMOD];
__device__ __nv_bfloat16 g_w1_h [LNUM*DMOD*FFD],   g_w1_l [LNUM*DMOD*FFD];
__device__ __nv_bfloat16 g_w2_h [LNUM*FFD*DMOD],   g_w2_l [LNUM*FFD*DMOD];
__device__ __nv_bfloat16 g_emb_h[VOC*DMOD],        g_emb_l[VOC*DMOD];

// ---------------- helpers ----------------
__device__ __forceinline__ uint32_t smem_u32(const void* p) {
    uint32_t a;
    asm("{ .reg .u64 t; cvta.to.shared.u64 t, %1; cvt.u32.u64 %0, t; }" : "=r"(a) : "l"(p));
    return a;
}
__device__ __forceinline__ void cpa16(uint32_t dst, const void* src) {
    asm volatile("cp.async.cg.shared.global [%0], [%1], 16;" :: "r"(dst), "l"(src));
}
#define CP_COMMIT() asm volatile("cp.async.commit_group;" ::: "memory")
#define CP_WAIT1()  asm volatile("cp.async.wait_group 1;" ::: "memory")

__device__ __forceinline__ void split2(float v, __nv_bfloat16& hi, __nv_bfloat16& lo) {
    hi = __float2bfloat16(v);
    lo = __float2bfloat16(v - __bfloat162float(hi));
}

// ---------------- merged prepass split kernel ----------------
#define N_QKV (LNUM*DMOD*QKVN)
#define N_WO  (LNUM*DMOD*DMOD)
#define N_W1  (LNUM*DMOD*FFD)
#define N_W2  (LNUM*FFD*DMOD)
#define N_EMB (VOC*DMOD)
#define N_SPLIT_TOT (N_QKV + N_WO + N_W1 + N_W2 + N_EMB)

__global__ void split_all_kernel(const float* __restrict__ wq, const float* __restrict__ wk,
                                 const float* __restrict__ wv, const float* __restrict__ wo,
                                 const float* __restrict__ w1, const float* __restrict__ w2,
                                 const float* __restrict__ emb,
                                 __nv_bfloat16* __restrict__ qkv_h, __nv_bfloat16* __restrict__ qkv_l,
                                 __nv_bfloat16* __restrict__ wo_h,  __nv_bfloat16* __restrict__ wo_l,
                                 __nv_bfloat16* __restrict__ w1_h,  __nv_bfloat16* __restrict__ w1_l,
                                 __nv_bfloat16* __restrict__ w2_h,  __nv_bfloat16* __restrict__ w2_l,
                                 __nv_bfloat16* __restrict__ emb_h, __nv_bfloat16* __restrict__ emb_l) {
    int i = blockIdx.x * blockDim.x + threadIdx.x;
    if (i >= N_SPLIT_TOT) return;
    if (i < N_QKV) {
        int l = i / (DMOD * QKVN);
        int rem = i % (DMOD * QKVN);
        int k = rem / QKVN, j = rem % QKVN;
        const float* s = (j < DMOD) ? wq : (j < 2 * DMOD) ? wk : wv;
        float v = s[(size_t)l * DMOD * DMOD + (size_t)k * DMOD + (j % DMOD)];
        split2(v, qkv_h[i], qkv_l[i]);
        return;
    }
    i -= N_QKV;
    if (i < N_WO)  { split2(wo[i],  wo_h[i],  wo_l[i]);  return; }
    i -= N_WO;
    if (i < N_W1)  { split2(w1[i],  w1_h[i],  w1_l[i]);  return; }
    i -= N_W1;
    if (i < N_W2)  { split2(w2[i],  w2_h[i],  w2_l[i]);  return; }
    i -= N_W2;
    split2(emb[i], emb_h[i], emb_l[i]);
}

// ---------------- embedding ----------------
__global__ void embed_kernel(const int* __restrict__ ids, const float* __restrict__ emb,
                             const float* __restrict__ pe, float* __restrict__ X) {
    int i = blockIdx.x * blockDim.x + threadIdx.x;
    if (i >= MTOK * DMOD) return;
    int d = i % DMOD, t = i / DMOD, s = t % SEQ;
    X[i] = emb[(size_t)ids[t] * DMOD + d] + pe[s * DMOD + d];
}

// ---------------- layernorm -> bf16 hi/lo ----------------
__global__ void ln_kernel(const float* __restrict__ X, const float* __restrict__ w,
                          const float* __restrict__ bvec,
                          __nv_bfloat16* __restrict__ Yh, __nv_bfloat16* __restrict__ Yl) {
    __shared__ float red[256];
    int row = blockIdx.x, tid = threadIdx.x;
    const float* x = X + (size_t)row * DMOD;
    float s = 0.f;
    for (int i = tid; i < DMOD; i += 256) s += x[i];
    red[tid] = s; __syncthreads();
    for (int o = 128; o > 0; o >>= 1) { if (tid < o) red[tid] += red[tid + o]; __syncthreads(); }
    float mu = red[0] * (1.0f / DMOD); __syncthreads();
    float v = 0.f;
    for (int i = tid; i < DMOD; i += 256) { float t = x[i] - mu; v += t * t; }
    red[tid] = v; __syncthreads();
    for (int o = 128; o > 0; o >>= 1) { if (tid < o) red[tid] += red[tid + o]; __syncthreads(); }
    float rstd = rsqrtf(red[0] * (1.0f / DMOD) + 1e-5f);
    for (int i = tid; i < DMOD; i += 256) {
        float y = (x[i] - mu) * rstd * w[i] + bvec[i];
        __nv_bfloat16 hi, lo; split2(y, hi, lo);
        Yh[(size_t)row * DMOD + i] = hi;
        Yl[(size_t)row * DMOD + i] = lo;
    }
}

// ---------------- GEMM: pre-split bf16, cp.async 2-stage, WMMA 3-term, 2 CTAs/SM ----------------
#define EP_BIAS 1
#define EP_GELU 2
#define EP_RES  4

__device__ __forceinline__ float gelu_exact(float x) {
    return 0.5f * x * (1.0f + erff(x * 0.70710678118654752f));
}

template<int EP, bool BCOL, bool NG, int TN, bool WH>
__global__ void __launch_bounds__(256, 2)
gemm_tc(const __nv_bfloat16* __restrict__ Ah_g, const __nv_bfloat16* __restrict__ Al_g,
        const __nv_bfloat16* __restrict__ Bh_g, const __nv_bfloat16* __restrict__ Bl_g,
        const float* __restrict__ bias, const float* __restrict__ res,
        float* __restrict__ C, __nv_bfloat16* __restrict__ Chi, __nv_bfloat16* __restrict__ Clo,
        int M, int N, int K, int ldb, int ldc) {
    constexpr int ALD = 40;
    constexpr int BLD = BCOL ? 40 : (TN + 8);
    constexpr int ABYTES = 128 * ALD * 2;
    constexpr int BBYTES = BCOL ? (TN * 40 * 2) : (32 * BLD * 2);
    constexpr int STAGEB = 2 * (ABYTES + BBYTES);
    constexpr int NJ = TN / 32;

    extern __shared__ char smem[];
    uint32_t sbase = smem_u32(smem);

    int tid = threadIdx.x, lane = tid & 31, wid = tid >> 5;
    int warp_m = wid & 3, warp_n = wid >> 2;
    int bm, bn;
    if (BCOL) { bm = blockIdx.x * 128; bn = blockIdx.y * TN; }
    else      { bm = blockIdx.y * 128; bn = blockIdx.x * TN; }
    int nch = K >> 5;

    wmma::fragment<wmma::accumulator, 16, 16, 16, float> acc[2][NJ];
    #pragma unroll
    for (int i = 0; i < 2; i++)
        #pragma unroll
        for (int j = 0; j < NJ; j++) wmma::fill_fragment(acc[i][j], 0.f);

    auto load_stage = [&](int s, int c) {
        int k0 = c * 32;
        uint32_t abase = sbase + s * STAGEB;
        #pragma unroll
        for (int hn = 0; hn < 2; hn++) {
            const __nv_bfloat16* g = hn ? Al_g : Ah_g;
            uint32_t db = abase + hn * ABYTES;
            #pragma unroll
            for (int i = 0; i < 2; i++) {
                int cid = tid + i * 256;
                int r = cid >> 2, seg = cid & 3;
                cpa16(db + (uint32_t)(r * ALD + seg * 8) * 2,
                      g + (size_t)(bm + r) * K + k0 + seg * 8);
            }
        }
        uint32_t bbase = abase + 2 * ABYTES;
        if (BCOL) {
            constexpr int NITB = (TN * 4) / 256;
            #pragma unroll
            for (int hn = 0; hn < 2; hn++) {
                const __nv_bfloat16* g = hn ? Bl_g : Bh_g;
                uint32_t db = bbase + hn * BBYTES;
                #pragma unroll
                for (int i = 0; i < NITB; i++) {
                    int cid = tid + i * 256;
                    int r = cid >> 2, seg = cid & 3;
                    int gn = bn + r;
                    uint32_t d = db + (uint32_t)(r * 40 + seg * 8) * 2;
                    if (!NG || gn < N)
                        cpa16(d, g + (size_t)gn * ldb + k0 + seg * 8);
                    else
                        *reinterpret_cast<uint4*>(smem + (d - sbase)) = make_uint4(0, 0, 0, 0);
                }
            }
        } else {
            constexpr int CH = TN / 8;
            constexpr int NIT = (32 * CH) / 256;
            #pragma unroll
            for (int hn = 0; hn < 2; hn++) {
                const __nv_bfloat16* g = hn ? Bl_g : Bh_g;
                uint32_t db = bbase + hn * BBYTES;
                #pragma unroll
                for (int i = 0; i < NIT; i++) {
                    int cid = tid + i * 256;
                    int kr = cid / CH, seg = cid % CH;
                    cpa16(db + (uint32_t)(kr * BLD + seg * 8) * 2,
                          g + (size_t)(k0 + kr) * ldb + bn + seg * 8);
                }
            }
        }
        CP_COMMIT();
    };

    auto do_mma = [&](int s) {
        char* base = smem + s * STAGEB;
        __nv_bfloat16* Ah = reinterpret_cast<__nv_bfloat16*>(base);
        __nv_bfloat16* Al = reinterpret_cast<__nv_bfloat16*>(base + ABYTES);
        __nv_bfloat16* Bh = reinterpret_cast<__nv_bfloat16*>(base + 2 * ABYTES);
        __nv_bfloat16* Bl = reinterpret_cast<__nv_bfloat16*>(base + 2 * ABYTES + BBYTES);
        #pragma unroll
        for (int kk = 0; kk < 2; kk++) {
            wmma::fragment<wmma::matrix_a, 16, 16, 16, __nv_bfloat16, wmma::row_major> ah[2], al[2];
            #pragma unroll
            for (int i = 0; i < 2; i++) {
                wmma::load_matrix_sync(ah[i], Ah + (warp_m * 32 + i * 16) * ALD + kk * 16, ALD);
                wmma::load_matrix_sync(al[i], Al + (warp_m * 32 + i * 16) * ALD + kk * 16, ALD);
            }
            #pragma unroll
            for (int j = 0; j < NJ; j++) {
                if (BCOL) {
                    wmma::fragment<wmma::matrix_b, 16, 16, 16, __nv_bfloat16, wmma::col_major> bh, bl;
                    wmma::load_matrix_sync(bh, Bh + (warp_n * (TN / 2) + j * 16) * 40 + kk * 16, 40);
                    wmma::load_matrix_sync(bl, Bl + (warp_n * (TN / 2) + j * 16) * 40 + kk * 16, 40);
                    #pragma unroll
                    for (int i = 0; i < 2; i++) {
                        wmma::mma_sync(acc[i][j], ah[i], bh, acc[i][j]);
                        wmma::mma_sync(acc[i][j], ah[i], bl, acc[i][j]);
                        wmma::mma_sync(acc[i][j], al[i], bh, acc[i][j]);
                    }
                } else {
                    wmma::fragment<wmma::matrix_b, 16, 16, 16, __nv_bfloat16, wmma::row_major> bh, bl;
                    wmma::load_matrix_sync(bh, Bh + (kk * 16) * BLD + warp_n * (TN / 2) + j * 16, BLD);
                    wmma::load_matrix_sync(bl, Bl + (kk * 16) * BLD + warp_n * (TN / 2) + j * 16, BLD);
                    #pragma unroll
                    for (int i = 0; i < 2; i++) {
                        wmma::mma_sync(acc[i][j], ah[i], bh, acc[i][j]);
                        wmma::mma_sync(acc[i][j], ah[i], bl, acc[i][j]);
                        wmma::mma_sync(acc[i][j], al[i], bh, acc[i][j]);
                    }
                }
            }
        }
    };

    // 2-stage pipeline (round-6 proven schedule)
    load_stage(0, 0);
    load_stage(1, 1);
    for (int c = 0; c < nch; c++) {
        CP_WAIT1();
        __syncthreads();
        do_mma(c & 1);
        __syncthreads();
        if (c + 2 < nch) load_stage(c & 1, c + 2);
        else CP_COMMIT();
    }

    // epilogue
    float* stg = reinterpret_cast<float*>(smem) + wid * (16 * 20);
    int r = lane >> 1, cb = (lane & 1) * 8;
    #pragma unroll
    for (int i = 0; i < 2; i++) {
        #pragma unroll
        for (int j = 0; j < NJ; j++) {
            wmma::store_matrix_sync(stg, acc[i][j], 20, wmma::mem_row_major);
            __syncwarp();
            int m = bm + warp_m * 32 + i * 16 + r;
            int n0 = bn + warp_n * (TN / 2) + j * 16 + cb;
            #pragma unroll
            for (int q = 0; q < 8; q++) {
                int n = n0 + q;
                float v = stg[r * 20 + cb + q];
                if (EP & EP_BIAS) v += bias[n];
                if (EP & EP_GELU) v = gelu_exact(v);
                if (EP & EP_RES)  v += res[(size_t)m * ldc + n];
                if (!NG || n < N) {
                    if (WH) {
                        __nv_bfloat16 hi, lo; split2(v, hi, lo);
                        Chi[(size_t)m * ldc + n] = hi;
                        Clo[(size_t)m * ldc + n] = lo;
                    } else {
                        C[(size_t)m * ldc + n] = v;
                    }
                }
            }
            __syncwarp();
        }
    }
}

// ---------------- WMMA flash attention (bf16 3-term, fp32 softmax) ----------------
#define KLD 72
#define SLD 68
// smem offsets (bytes)
#define A_QH 0
#define A_QL (A_QH + 64*KLD*2)
#define A_KH (A_QL + 64*KLD*2)
#define A_KL (A_KH + 64*KLD*2)
#define A_VH (A_KL + 64*KLD*2)
#define A_VL (A_VH + 64*KLD*2)
#define A_PH (A_VL + 64*KLD*2)
#define A_PL (A_PH + 64*KLD*2)
#define A_S  (A_PL + 64*KLD*2)
#define A_O  (A_S + 64*SLD*4)
#define A_M  (A_O + 64*SLD*4)
#define A_L  (A_M + 64*4)
#define A_SC (A_L + 64*4)
#define A_MS (A_SC + 64*4)
#define ATT_SMEM (A_MS + 64*4)

__global__ void __launch_bounds__(256)
attn_kernel(const __nv_bfloat16* __restrict__ QKVh, const __nv_bfloat16* __restrict__ QKVl,
            const int* __restrict__ amask,
            __nv_bfloat16* __restrict__ Ohg, __nv_bfloat16* __restrict__ Olg) {
    extern __shared__ char asmem[];
    __nv_bfloat16* Qh = reinterpret_cast<__nv_bfloat16*>(asmem + A_QH);
    __nv_bfloat16* Ql = reinterpret_cast<__nv_bfloat16*>(asmem + A_QL);
    __nv_bfloat16* Kh = reinterpret_cast<__nv_bfloat16*>(asmem + A_KH);
    __nv_bfloat16* Kl = reinterpret_cast<__nv_bfloat16*>(asmem + A_KL);
    __nv_bfloat16* Vh = reinterpret_cast<__nv_bfloat16*>(asmem + A_VH);
    __nv_bfloat16* Vl = reinterpret_cast<__nv_bfloat16*>(asmem + A_VL);
    __nv_bfloat16* Ph = reinterpret_cast<__nv_bfloat16*>(asmem + A_PH);
    __nv_bfloat16* Pl = reinterpret_cast<__nv_bfloat16*>(asmem + A_PL);
    float* S    = reinterpret_cast<float*>(asmem + A_S);   // scores, then PV staging
    float* O    = reinterpret_cast<float*>(asmem + A_O);
    float* sm_m = reinterpret_cast<float*>(asmem + A_M);
    float* sm_l = reinterpret_cast<float*>(asmem + A_L);
    float* sm_sc= reinterpret_cast<float*>(asmem + A_SC);
    int*   msk  = reinterpret_cast<int*>(asmem + A_MS);

    int b = blockIdx.z, hh = blockIdx.y;
    int qt = (SEQ / 64 - 1) - blockIdx.x;     // heavy blocks first
    int q0 = qt * 64;
    int tid = threadIdx.x, wid = tid >> 5;
    int wr = wid & 3, wc = wid >> 2;

    // load Q hi/lo (uint2 = 4 bf16)
    for (int idx = tid; idx < 64 * 16; idx += 256) {
        int i = idx >> 4, d4 = idx & 15;
        size_t ga = (size_t)(b * SEQ + q0 + i) * QKVN + hh * DKH + d4 * 4;
        *reinterpret_cast<uint2*>(&Qh[i * KLD + d4 * 4]) = *reinterpret_cast<const uint2*>(&QKVh[ga]);
        *reinterpret_cast<uint2*>(&Ql[i * KLD + d4 * 4]) = *reinterpret_cast<const uint2*>(&QKVl[ga]);
    }
    for (int idx = tid; idx < 64 * SLD; idx += 256) O[idx] = 0.f;
    if (tid < 64) { sm_m[tid] = -1e30f; sm_l[tid] = 0.f; }

    for (int kt = 0; kt <= qt; kt++) {
        int k0 = kt * 64;
        __syncthreads();
        for (int idx = tid; idx < 64 * 16; idx += 256) {
            int j = idx >> 4, d4 = idx & 15;
            size_t gk = (size_t)(b * SEQ + k0 + j) * QKVN + DMOD + hh * DKH + d4 * 4;
            size_t gv = gk + DMOD;
            *reinterpret_cast<uint2*>(&Kh[j * KLD + d4 * 4]) = *reinterpret_cast<const uint2*>(&QKVh[gk]);
            *reinterpret_cast<uint2*>(&Kl[j * KLD + d4 * 4]) = *reinterpret_cast<const uint2*>(&QKVl[gk]);
            *reinterpret_cast<uint2*>(&Vh[j * KLD + d4 * 4]) = *reinterpret_cast<const uint2*>(&QKVh[gv]);
            *reinterpret_cast<uint2*>(&Vl[j * KLD + d4 * 4]) = *reinterpret_cast<const uint2*>(&QKVl[gv]);
        }
        if (tid < 64) msk[tid] = amask[b * SEQ + k0 + tid];
        __syncthreads();

        // S = Q @ K^T (3-term)
        {
            wmma::fragment<wmma::accumulator, 16, 16, 16, float> sacc[2];
            wmma::fill_fragment(sacc[0], 0.f);
            wmma::fill_fragment(sacc[1], 0.f);
            #pragma unroll
            for (int ks = 0; ks < 4; ks++) {
                wmma::fragment<wmma::matrix_a, 16, 16, 16, __nv_bfloat16, wmma::row_major> a_h, a_l;
                wmma::load_matrix_sync(a_h, Qh + (wr * 16) * KLD + ks * 16, KLD);
                wmma::load_matrix_sync(a_l, Ql + (wr * 16) * KLD + ks * 16, KLD);
                #pragma unroll
                for (int t = 0; t < 2; t++) {
                    wmma::fragment<wmma::matrix_b, 16, 16, 16, __nv_bfloat16, wmma::col_major> b_h, b_l;
                    wmma::load_matrix_sync(b_h, Kh + (wc * 32 + t * 16) * KLD + ks * 16, KLD);
                    wmma::load_matrix_sync(b_l, Kl + (wc * 32 + t * 16) * KLD + ks * 16, KLD);
                    wmma::mma_sync(sacc[t], a_h, b_h, sacc[t]);
                    wmma::mma_sync(sacc[t], a_h, b_l, sacc[t]);
                    wmma::mma_sync(sacc[t], a_l, b_h, sacc[t]);
                }
            }
            #pragma unroll
            for (int t = 0; t < 2; t++)
                wmma::store_matrix_sync(S + (wr * 16) * SLD + wc * 32 + t * 16, sacc[t], SLD, wmma::mem_row_major);
        }
        __syncthreads();

        // online softmax (fp32), produce P hi/lo
        {
            int row = tid >> 2, qq = tid & 3;
            float sv[16];
            float tmax = -1e30f;
            #pragma unroll
            for (int jj = 0; jj < 16; jj++) {
                int j = qq * 16 + jj;
                float s = S[row * SLD + j] * 0.125f;
                if (msk[j] == 0) s = -1e9f;
                if (kt == qt && j > row) s = -1e9f;
                sv[jj] = s;
                tmax = fmaxf(tmax, s);
            }
            tmax = fmaxf(tmax, __shfl_xor_sync(0xffffffff, tmax, 1));
            tmax = fmaxf(tmax, __shfl_xor_sync(0xffffffff, tmax, 2));
            float mold = sm_m[row];
            float newm = fmaxf(mold, tmax);
            float psum = 0.f;
            #pragma unroll
            for (int jj = 0; jj < 16; jj++) {
                float p = __expf(sv[jj] - newm);
                psum += p;
                __nv_bfloat16 hi, lo; split2(p, hi, lo);
                Ph[row * KLD + qq * 16 + jj] = hi;
                Pl[row * KLD + qq * 16 + jj] = lo;
            }
            psum += __shfl_xor_sync(0xffffffff, psum, 1);
            psum += __shfl_xor_sync(0xffffffff, psum, 2);
            if (qq == 0) {
                float sc = __expf(mold - newm);
                sm_sc[row] = sc;
                sm_l[row] = sm_l[row] * sc + psum;
                sm_m[row] = newm;
            }
        }
        __syncthreads();

        // PV = P @ V (3-term), staged into S
        {
            wmma::fragment<wmma::accumulator, 16, 16, 16, float> oacc[2];
            wmma::fill_fragment(oacc[0], 0.f);
            wmma::fill_fragment(oacc[1], 0.f);
            #pragma unroll
            for (int ks = 0; ks < 4; ks++) {
                wmma::fragment<wmma::matrix_a, 16, 16, 16, __nv_bfloat16, wmma::row_major> a_h, a_l;
                wmma::load_matrix_sync(a_h, Ph + (wr * 16) * KLD + ks * 16, KLD);
                wmma::load_matrix_sync(a_l, Pl + (wr * 16) * KLD + ks * 16, KLD);
                #pragma unroll
                for (int t = 0; t < 2; t++) {
                    wmma::fragment<wmma::matrix_b, 16, 16, 16, __nv_bfloat16, wmma::row_major> b_h, b_l;
                    wmma::load_matrix_sync(b_h, Vh + (ks * 16) * KLD + wc * 32 + t * 16, KLD);
                    wmma::load_matrix_sync(b_l, Vl + (ks * 16) * KLD + wc * 32 + t * 16, KLD);
                    wmma::mma_sync(oacc[t], a_h, b_h, oacc[t]);
                    wmma::mma_sync(oacc[t], a_h, b_l, oacc[t]);
                    wmma::mma_sync(oacc[t], a_l, b_h, oacc[t]);
                }
            }
            #pragma unroll
            for (int t = 0; t < 2; t++)
                wmma::store_matrix_sync(S + (wr * 16) * SLD + wc * 32 + t * 16, oacc[t], SLD, wmma::mem_row_major);
        }
        __syncthreads();

        // O = O * sc + PV
        for (int idx = tid; idx < 4096; idx += 256) {
            int i = idx >> 6, d = idx & 63;
            O[i * SLD + d] = O[i * SLD + d] * sm_sc[i] + S[i * SLD + d];
        }
    }
    __syncthreads();
    for (int idx = tid; idx < 4096; idx += 256) {
        int i = idx >> 6, d = idx & 63;
        float v = O[i * SLD + d] / sm_l[i];
        __nv_bfloat16 hi, lo; split2(v, hi, lo);
        size_t off = (size_t)(b * SEQ + q0 + i) * DMOD + hh * DKH + d;
        Ohg[off] = hi; Olg[off] = lo;
    }
}

// ---------------- launch ----------------
extern "C" void kernel_launch(void* const* d_in, const int* in_sizes, int n_in,
                              void* d_out, int out_size) {
    const int*   ids   = (const int*)  d_in[0];
    const int*   amask = (const int*)  d_in[1];
    const float* emb   = (const float*)d_in[2];
    const float* pe    = (const float*)d_in[3];
    const float* wq    = (const float*)d_in[4];
    const float* wk    = (const float*)d_in[5];
    const float* wv    = (const float*)d_in[6];
    const float* wo    = (const float*)d_in[7];
    const float* ln1w  = (const float*)d_in[8];
    const float* ln1b  = (const float*)d_in[9];
    const float* ln2w  = (const float*)d_in[10];
    const float* ln2b  = (const float*)d_in[11];
    const float* w1    = (const float*)d_in[12];
    const float* b1    = (const float*)d_in[13];
    const float* w2    = (const float*)d_in[14];
    const float* b2    = (const float*)d_in[15];
    const float* lnfw  = (const float*)d_in[16];
    const float* lnfb  = (const float*)d_in[17];
    float* out = (float*)d_out;

    float *x;
    __nv_bfloat16 *qkvh, *qkvl, *h_h, *h_l, *att_h, *att_l, *ff_h, *ff_l;
    __nv_bfloat16 *wqkv_h, *wqkv_l, *wo_h, *wo_l, *w1_h, *w1_l, *w2_h, *w2_l, *emb_h, *emb_l;
    cudaGetSymbolAddress((void**)&x,     g_x);
    cudaGetSymbolAddress((void**)&qkvh,  g_qkvh);  cudaGetSymbolAddress((void**)&qkvl,  g_qkvl);
    cudaGetSymbolAddress((void**)&h_h,   g_h_h);   cudaGetSymbolAddress((void**)&h_l,   g_h_l);
    cudaGetSymbolAddress((void**)&att_h, g_att_h); cudaGetSymbolAddress((void**)&att_l, g_att_l);
    cudaGetSymbolAddress((void**)&ff_h,  g_ff_h);  cudaGetSymbolAddress((void**)&ff_l,  g_ff_l);
    cudaGetSymbolAddress((void**)&wqkv_h, g_wqkv_h); cudaGetSymbolAddress((void**)&wqkv_l, g_wqkv_l);
    cudaGetSymbolAddress((void**)&wo_h,  g_wo_h);  cudaGetSymbolAddress((void**)&wo_l,  g_wo_l);
    cudaGetSymbolAddress((void**)&w1_h,  g_w1_h);  cudaGetSymbolAddress((void**)&w1_l,  g_w1_l);
    cudaGetSymbolAddress((void**)&w2_h,  g_w2_h);  cudaGetSymbolAddress((void**)&w2_l,  g_w2_l);
    cudaGetSymbolAddress((void**)&emb_h, g_emb_h); cudaGetSymbolAddress((void**)&emb_l, g_emb_l);

    const int SM_T128 = 2 * (2 * (128 * 40 * 2) + 2 * (32 * 136 * 2));   // 75776
    const int SM_T64  = 2 * (2 * (128 * 40 * 2) + 2 * (32 * 72 * 2));    // 59392
    const int SM_COL  = 2 * (2 * (128 * 40 * 2) + 2 * (128 * 40 * 2));   // 81920

    cudaFuncSetAttribute(gemm_tc<0, false, false, 128, true>,                 cudaFuncAttributeMaxDynamicSharedMemorySize, SM_T128);
    cudaFuncSetAttribute(gemm_tc<EP_RES, false, false, 64, false>,            cudaFuncAttributeMaxDynamicSharedMemorySize, SM_T64);
    cudaFuncSetAttribute(gemm_tc<EP_BIAS | EP_GELU, false, false, 128, true>, cudaFuncAttributeMaxDynamicSharedMemorySize, SM_T128);
    cudaFuncSetAttribute(gemm_tc<EP_BIAS | EP_RES, false, false, 64, false>,  cudaFuncAttributeMaxDynamicSharedMemorySize, SM_T64);
    cudaFuncSetAttribute(gemm_tc<0, true, true, 128, false>,                  cudaFuncAttributeMaxDynamicSharedMemorySize, SM_COL);
    cudaFuncSetAttribute(attn_kernel, cudaFuncAttributeMaxDynamicSharedMemorySize, ATT_SMEM);

    split_all_kernel<<<(N_SPLIT_TOT + 255) / 256, 256>>>(
        wq, wk, wv, wo, w1, w2, emb,
        wqkv_h, wqkv_l, wo_h, wo_l, w1_h, w1_l, w2_h, w2_l, emb_h, emb_l);
    { int n = MTOK * DMOD; embed_kernel<<<(n + 255) / 256, 256>>>(ids, emb, pe, x); }

    dim3 gQKV(QKVN / 128, MTOK / 128);   // 18 x 16
    dim3 gD64(DMOD / 64, MTOK / 128);    // 12 x 16
    dim3 gF(FFD / 128, MTOK / 128);      // 24 x 16

    for (int l = 0; l < LNUM; l++) {
        ln_kernel<<<MTOK, 256>>>(x, ln1w + l * DMOD, ln1b + l * DMOD, h_h, h_l);

        gemm_tc<0, false, false, 128, true><<<gQKV, 256, SM_T128>>>(
            h_h, h_l, wqkv_h + (size_t)l * DMOD * QKVN, wqkv_l + (size_t)l * DMOD * QKVN,
            nullptr, nullptr, nullptr, qkvh, qkvl, MTOK, QKVN, DMOD, QKVN, QKVN);

        attn_kernel<<<dim3(SEQ / 64, HNUM, BAT), 256, ATT_SMEM>>>(qkvh, qkvl, amask, att_h, att_l);

        gemm_tc<EP_RES, false, false, 64, false><<<gD64, 256, SM_T64>>>(
            att_h, att_l, wo_h + (size_t)l * DMOD * DMOD, wo_l + (size_t)l * DMOD * DMOD,
            nullptr, x, x, nullptr, nullptr, MTOK, DMOD, DMOD, DMOD, DMOD);

        ln_kernel<<<MTOK, 256>>>(x, ln2w + l * DMOD, ln2b + l * DMOD, h_h, h_l);

        gemm_tc<EP_BIAS | EP_GELU, false, false, 128, true><<<gF, 256, SM_T128>>>(
            h_h, h_l, w1_h + (size_t)l * DMOD * FFD, w1_l + (size_t)l * DMOD * FFD,
            b1 + (size_t)l * FFD, nullptr, nullptr, ff_h, ff_l, MTOK, FFD, DMOD, FFD, FFD);

        gemm_tc<EP_BIAS | EP_RES, false, false, 64, false><<<gD64, 256, SM_T64>>>(
            ff_h, ff_l, w2_h + (size_t)l * FFD * DMOD, w2_l + (size_t)l * FFD * DMOD,
            b2 + (size_t)l * DMOD, x, x, nullptr, nullptr, MTOK, DMOD, FFD, DMOD, DMOD);
    }

    ln_kernel<<<MTOK, 256>>>(x, lnfw, lnfb, h_h, h_l);

    dim3 gV(MTOK / 128, (VOC + 127) / 128);
    gemm_tc<0, true, true, 128, false><<<gV, 256, SM_COL>>>(
        h_h, h_l, emb_h, emb_l, nullptr, nullptr, out, nullptr, nullptr, MTOK, VOC, DMOD, DMOD, VOC);
}

// round 9
// speedup vs baseline: 1.2904x; 1.1479x over previous
#include <cuda_runtime.h>
#include <cuda_bf16.h>
#include <mma.h>
#include <math.h>
#include <cstdint>
#include <cstddef>
using namespace nvcuda;

#define LNUM 6
#define DMOD 768
#define HNUM 12
#define DKH  64
#define FFD  3072
#define VOC  50257
#define SEQ  1024
#define BAT  2
#define MTOK (BAT*SEQ)   // 2048
#define QKVN (3*DMOD)    // 2304

// ---------------- device scratch ----------------
__device__ float g_x  [MTOK*DMOD];
__device__ __nv_bfloat16 g_qkvh[MTOK*QKVN], g_qkvl[MTOK*QKVN];
__device__ __nv_bfloat16 g_h_h [MTOK*DMOD],  g_h_l [MTOK*DMOD];
__device__ __nv_bfloat16 g_att_h[MTOK*DMOD], g_att_l[MTOK*DMOD];
__device__ __nv_bfloat16 g_ff_h[MTOK*FFD],   g_ff_l[MTOK*FFD];
__device__ __nv_bfloat16 g_wqkv_h[LNUM*DMOD*QKVN], g_wqkv_l[LNUM*DMOD*QKVN];
__device__ __nv_bfloat16 g_wo_h [LNUM*DMOD*DMOD],  g_wo_l [LNUM*DMOD*DMOD];
__device__ __nv_bfloat16 g_w1_h [LNUM*DMOD*FFD],   g_w1_l [LNUM*DMOD*FFD];
__device__ __nv_bfloat16 g_w2_h [LNUM*FFD*DMOD],   g_w2_l [LNUM*FFD*DMOD];
__device__ __nv_bfloat16 g_emb_h[VOC*DMOD],        g_emb_l[VOC*DMOD];

// ---------------- helpers ----------------
__device__ __forceinline__ uint32_t smem_u32(const void* p) {
    uint32_t a;
    asm("{ .reg .u64 t; cvta.to.shared.u64 t, %1; cvt.u32.u64 %0, t; }" : "=r"(a) : "l"(p));
    return a;
}
__device__ __forceinline__ void cpa16(uint32_t dst, const void* src) {
    asm volatile("cp.async.cg.shared.global [%0], [%1], 16;" :: "r"(dst), "l"(src));
}
#define CP_COMMIT() asm volatile("cp.async.commit_group;" ::: "memory")
#define CP_WAIT1()  asm volatile("cp.async.wait_group 1;" ::: "memory")

__device__ __forceinline__ void split2(float v, __nv_bfloat16& hi, __nv_bfloat16& lo) {
    hi = __float2bfloat16(v);
    lo = __float2bfloat16(v - __bfloat162float(hi));
}

// ---------------- merged prepass split kernel ----------------
#define N_QKV (LNUM*DMOD*QKVN)
#define N_WO  (LNUM*DMOD*DMOD)
#define N_W1  (LNUM*DMOD*FFD)
#define N_W2  (LNUM*FFD*DMOD)
#define N_EMB (VOC*DMOD)
#define N_SPLIT_TOT (N_QKV + N_WO + N_W1 + N_W2 + N_EMB)

__global__ void split_all_kernel(const float* __restrict__ wq, const float* __restrict__ wk,
                                 const float* __restrict__ wv, const float* __restrict__ wo,
                                 const float* __restrict__ w1, const float* __restrict__ w2,
                                 const float* __restrict__ emb,
                                 __nv_bfloat16* __restrict__ qkv_h, __nv_bfloat16* __restrict__ qkv_l,
                                 __nv_bfloat16* __restrict__ wo_h,  __nv_bfloat16* __restrict__ wo_l,
                                 __nv_bfloat16* __restrict__ w1_h,  __nv_bfloat16* __restrict__ w1_l,
                                 __nv_bfloat16* __restrict__ w2_h,  __nv_bfloat16* __restrict__ w2_l,
                                 __nv_bfloat16* __restrict__ emb_h, __nv_bfloat16* __restrict__ emb_l) {
    int i = blockIdx.x * blockDim.x + threadIdx.x;
    if (i >= N_SPLIT_TOT) return;
    if (i < N_QKV) {
        int l = i / (DMOD * QKVN);
        int rem = i % (DMOD * QKVN);
        int k = rem / QKVN, j = rem % QKVN;
        const float* s = (j < DMOD) ? wq : (j < 2 * DMOD) ? wk : wv;
        float v = s[(size_t)l * DMOD * DMOD + (size_t)k * DMOD + (j % DMOD)];
        split2(v, qkv_h[i], qkv_l[i]);
        return;
    }
    i -= N_QKV;
    if (i < N_WO)  { split2(wo[i],  wo_h[i],  wo_l[i]);  return; }
    i -= N_WO;
    if (i < N_W1)  { split2(w1[i],  w1_h[i],  w1_l[i]);  return; }
    i -= N_W1;
    if (i < N_W2)  { split2(w2[i],  w2_h[i],  w2_l[i]);  return; }
    i -= N_W2;
    split2(emb[i], emb_h[i], emb_l[i]);
}

// ---------------- embedding ----------------
__global__ void embed_kernel(const int* __restrict__ ids, const float* __restrict__ emb,
                             const float* __restrict__ pe, float* __restrict__ X) {
    int i = blockIdx.x * blockDim.x + threadIdx.x;
    if (i >= MTOK * DMOD) return;
    int d = i % DMOD, t = i / DMOD, s = t % SEQ;
    X[i] = emb[(size_t)ids[t] * DMOD + d] + pe[s * DMOD + d];
}

// ---------------- layernorm -> bf16 hi/lo ----------------
__global__ void ln_kernel(const float* __restrict__ X, const float* __restrict__ w,
                          const float* __restrict__ bvec,
                          __nv_bfloat16* __restrict__ Yh, __nv_bfloat16* __restrict__ Yl) {
    __shared__ float red[256];
    int row = blockIdx.x, tid = threadIdx.x;
    const float* x = X + (size_t)row * DMOD;
    float s = 0.f;
    for (int i = tid; i < DMOD; i += 256) s += x[i];
    red[tid] = s; __syncthreads();
    for (int o = 128; o > 0; o >>= 1) { if (tid < o) red[tid] += red[tid + o]; __syncthreads(); }
    float mu = red[0] * (1.0f / DMOD); __syncthreads();
    float v = 0.f;
    for (int i = tid; i < DMOD; i += 256) { float t = x[i] - mu; v += t * t; }
    red[tid] = v; __syncthreads();
    for (int o = 128; o > 0; o >>= 1) { if (tid < o) red[tid] += red[tid + o]; __syncthreads(); }
    float rstd = rsqrtf(red[0] * (1.0f / DMOD) + 1e-5f);
    for (int i = tid; i < DMOD; i += 256) {
        float y = (x[i] - mu) * rstd * w[i] + bvec[i];
        __nv_bfloat16 hi, lo; split2(y, hi, lo);
        Yh[(size_t)row * DMOD + i] = hi;
        Yl[(size_t)row * DMOD + i] = lo;
    }
}

// ---------------- GEMM: pre-split bf16, cp.async 2-stage, WMMA 3-term, 2 CTAs/SM ----------------
#define EP_BIAS 1
#define EP_GELU 2
#define EP_RES  4

__device__ __forceinline__ float gelu_exact(float x) {
    return 0.5f * x * (1.0f + erff(x * 0.70710678118654752f));
}

template<int EP, bool BCOL, bool NG, int TN, bool WH>
__global__ void __launch_bounds__(256, 2)
gemm_tc(const __nv_bfloat16* __restrict__ Ah_g, const __nv_bfloat16* __restrict__ Al_g,
        const __nv_bfloat16* __restrict__ Bh_g, const __nv_bfloat16* __restrict__ Bl_g,
        const float* __restrict__ bias, const float* __restrict__ res,
        float* __restrict__ C, __nv_bfloat16* __restrict__ Chi, __nv_bfloat16* __restrict__ Clo,
        int M, int N, int K, int ldb, int ldc) {
    constexpr int ALD = 40;
    constexpr int BLD = BCOL ? 40 : (TN + 8);
    constexpr int ABYTES = 128 * ALD * 2;
    constexpr int BBYTES = BCOL ? (TN * 40 * 2) : (32 * BLD * 2);
    constexpr int STAGEB = 2 * (ABYTES + BBYTES);
    constexpr int NJ = TN / 32;

    extern __shared__ char smem[];
    uint32_t sbase = smem_u32(smem);

    int tid = threadIdx.x, lane = tid & 31, wid = tid >> 5;
    int warp_m = wid & 3, warp_n = wid >> 2;
    int bm, bn;
    if (BCOL) { bm = blockIdx.x * 128; bn = blockIdx.y * TN; }
    else      { bm = blockIdx.y * 128; bn = blockIdx.x * TN; }
    int nch = K >> 5;

    wmma::fragment<wmma::accumulator, 16, 16, 16, float> acc[2][NJ];
    #pragma unroll
    for (int i = 0; i < 2; i++)
        #pragma unroll
        for (int j = 0; j < NJ; j++) wmma::fill_fragment(acc[i][j], 0.f);

    auto load_stage = [&](int s, int c) {
        int k0 = c * 32;
        uint32_t abase = sbase + s * STAGEB;
        #pragma unroll
        for (int hn = 0; hn < 2; hn++) {
            const __nv_bfloat16* g = hn ? Al_g : Ah_g;
            uint32_t db = abase + hn * ABYTES;
            #pragma unroll
            for (int i = 0; i < 2; i++) {
                int cid = tid + i * 256;
                int r = cid >> 2, seg = cid & 3;
                cpa16(db + (uint32_t)(r * ALD + seg * 8) * 2,
                      g + (size_t)(bm + r) * K + k0 + seg * 8);
            }
        }
        uint32_t bbase = abase + 2 * ABYTES;
        if (BCOL) {
            constexpr int NITB = (TN * 4) / 256;
            #pragma unroll
            for (int hn = 0; hn < 2; hn++) {
                const __nv_bfloat16* g = hn ? Bl_g : Bh_g;
                uint32_t db = bbase + hn * BBYTES;
                #pragma unroll
                for (int i = 0; i < NITB; i++) {
                    int cid = tid + i * 256;
                    int r = cid >> 2, seg = cid & 3;
                    int gn = bn + r;
                    uint32_t d = db + (uint32_t)(r * 40 + seg * 8) * 2;
                    if (!NG || gn < N)
                        cpa16(d, g + (size_t)gn * ldb + k0 + seg * 8);
                    else
                        *reinterpret_cast<uint4*>(smem + (d - sbase)) = make_uint4(0, 0, 0, 0);
                }
            }
        } else {
            constexpr int CH = TN / 8;
            constexpr int NIT = (32 * CH) / 256;
            #pragma unroll
            for (int hn = 0; hn < 2; hn++) {
                const __nv_bfloat16* g = hn ? Bl_g : Bh_g;
                uint32_t db = bbase + hn * BBYTES;
                #pragma unroll
                for (int i = 0; i < NIT; i++) {
                    int cid = tid + i * 256;
                    int kr = cid / CH, seg = cid % CH;
                    cpa16(db + (uint32_t)(kr * BLD + seg * 8) * 2,
                          g + (size_t)(k0 + kr) * ldb + bn + seg * 8);
                }
            }
        }
        CP_COMMIT();
    };

    auto do_mma = [&](int s) {
        char* base = smem + s * STAGEB;
        __nv_bfloat16* Ah = reinterpret_cast<__nv_bfloat16*>(base);
        __nv_bfloat16* Al = reinterpret_cast<__nv_bfloat16*>(base + ABYTES);
        __nv_bfloat16* Bh = reinterpret_cast<__nv_bfloat16*>(base + 2 * ABYTES);
        __nv_bfloat16* Bl = reinterpret_cast<__nv_bfloat16*>(base + 2 * ABYTES + BBYTES);
        #pragma unroll
        for (int kk = 0; kk < 2; kk++) {
            wmma::fragment<wmma::matrix_a, 16, 16, 16, __nv_bfloat16, wmma::row_major> ah[2], al[2];
            #pragma unroll
            for (int i = 0; i < 2; i++) {
                wmma::load_matrix_sync(ah[i], Ah + (warp_m * 32 + i * 16) * ALD + kk * 16, ALD);
                wmma::load_matrix_sync(al[i], Al + (warp_m * 32 + i * 16) * ALD + kk * 16, ALD);
            }
            #pragma unroll
            for (int j = 0; j < NJ; j++) {
                if (BCOL) {
                    wmma::fragment<wmma::matrix_b, 16, 16, 16, __nv_bfloat16, wmma::col_major> bh, bl;
                    wmma::load_matrix_sync(bh, Bh + (warp_n * (TN / 2) + j * 16) * 40 + kk * 16, 40);
                    wmma::load_matrix_sync(bl, Bl + (warp_n * (TN / 2) + j * 16) * 40 + kk * 16, 40);
                    #pragma unroll
                    for (int i = 0; i < 2; i++) {
                        wmma::mma_sync(acc[i][j], ah[i], bh, acc[i][j]);
                        wmma::mma_sync(acc[i][j], ah[i], bl, acc[i][j]);
                        wmma::mma_sync(acc[i][j], al[i], bh, acc[i][j]);
                    }
                } else {
                    wmma::fragment<wmma::matrix_b, 16, 16, 16, __nv_bfloat16, wmma::row_major> bh, bl;
                    wmma::load_matrix_sync(bh, Bh + (kk * 16) * BLD + warp_n * (TN / 2) + j * 16, BLD);
                    wmma::load_matrix_sync(bl, Bl + (kk * 16) * BLD + warp_n * (TN / 2) + j * 16, BLD);
                    #pragma unroll
                    for (int i = 0; i < 2; i++) {
                        wmma::mma_sync(acc[i][j], ah[i], bh, acc[i][j]);
                        wmma::mma_sync(acc[i][j], ah[i], bl, acc[i][j]);
                        wmma::mma_sync(acc[i][j], al[i], bh, acc[i][j]);
                    }
                }
            }
        }
    };

    // 2-stage pipeline (round-6 proven schedule)
    load_stage(0, 0);
    load_stage(1, 1);
    for (int c = 0; c < nch; c++) {
        CP_WAIT1();
        __syncthreads();
        do_mma(c & 1);
        __syncthreads();
        if (c + 2 < nch) load_stage(c & 1, c + 2);
        else CP_COMMIT();
    }

    // vectorized epilogue
    float* stg = reinterpret_cast<float*>(smem) + wid * (16 * 20);
    int r = lane >> 1, cb = (lane & 1) * 8;
    #pragma unroll
    for (int i = 0; i < 2; i++) {
        #pragma unroll
        for (int j = 0; j < NJ; j++) {
            wmma::store_matrix_sync(stg, acc[i][j], 20, wmma::mem_row_major);
            __syncwarp();
            int m = bm + warp_m * 32 + i * 16 + r;
            int n0 = bn + warp_n * (TN / 2) + j * 16 + cb;
            float v[8];
            #pragma unroll
            for (int q = 0; q < 8; q++) v[q] = stg[r * 20 + cb + q];
            if (EP & EP_BIAS) {
                float4 b0 = *reinterpret_cast<const float4*>(bias + n0);
                float4 b1 = *reinterpret_cast<const float4*>(bias + n0 + 4);
                v[0]+=b0.x; v[1]+=b0.y; v[2]+=b0.z; v[3]+=b0.w;
                v[4]+=b1.x; v[5]+=b1.y; v[6]+=b1.z; v[7]+=b1.w;
            }
            if (EP & EP_GELU) {
                #pragma unroll
                for (int q = 0; q < 8; q++) v[q] = gelu_exact(v[q]);
            }
            if (EP & EP_RES) {
                const float* rp = res + (size_t)m * ldc + n0;
                float4 r0 = *reinterpret_cast<const float4*>(rp);
                float4 r1 = *reinterpret_cast<const float4*>(rp + 4);
                v[0]+=r0.x; v[1]+=r0.y; v[2]+=r0.z; v[3]+=r0.w;
                v[4]+=r1.x; v[5]+=r1.y; v[6]+=r1.z; v[7]+=r1.w;
            }
            if (WH) {
                __nv_bfloat16 hb[8], lb[8];
                #pragma unroll
                for (int q = 0; q < 8; q++) split2(v[q], hb[q], lb[q]);
                *reinterpret_cast<uint4*>(Chi + (size_t)m * ldc + n0) = *reinterpret_cast<uint4*>(hb);
                *reinterpret_cast<uint4*>(Clo + (size_t)m * ldc + n0) = *reinterpret_cast<uint4*>(lb);
            } else if (NG) {
                #pragma unroll
                for (int q = 0; q < 8; q++)
                    if (n0 + q < N) C[(size_t)m * ldc + n0 + q] = v[q];
            } else {
                float* cp = C + (size_t)m * ldc + n0;
                *reinterpret_cast<float4*>(cp)     = make_float4(v[0], v[1], v[2], v[3]);
                *reinterpret_cast<float4*>(cp + 4) = make_float4(v[4], v[5], v[6], v[7]);
            }
            __syncwarp();
        }
    }
}

// ---------------- WMMA flash attention (bf16 3-term, fp32 softmax) ----------------
#define KLD 72
#define SLD 68
#define A_QH 0
#define A_QL (A_QH + 64*KLD*2)
#define A_KH (A_QL + 64*KLD*2)
#define A_KL (A_KH + 64*KLD*2)
#define A_VH (A_KL + 64*KLD*2)
#define A_VL (A_VH + 64*KLD*2)
#define A_PH (A_VL + 64*KLD*2)
#define A_PL (A_PH + 64*KLD*2)
#define A_S  (A_PL + 64*KLD*2)
#define A_O  (A_S + 64*SLD*4)
#define A_M  (A_O + 64*SLD*4)
#define A_L  (A_M + 64*4)
#define A_SC (A_L + 64*4)
#define A_MS (A_SC + 64*4)
#define ATT_SMEM (A_MS + 64*4)

__global__ void __launch_bounds__(256)
attn_kernel(const __nv_bfloat16* __restrict__ QKVh, const __nv_bfloat16* __restrict__ QKVl,
            const int* __restrict__ amask,
            __nv_bfloat16* __restrict__ Ohg, __nv_bfloat16* __restrict__ Olg) {
    extern __shared__ char asmem[];
    __nv_bfloat16* Qh = reinterpret_cast<__nv_bfloat16*>(asmem + A_QH);
    __nv_bfloat16* Ql = reinterpret_cast<__nv_bfloat16*>(asmem + A_QL);
    __nv_bfloat16* Kh = reinterpret_cast<__nv_bfloat16*>(asmem + A_KH);
    __nv_bfloat16* Kl = reinterpret_cast<__nv_bfloat16*>(asmem + A_KL);
    __nv_bfloat16* Vh = reinterpret_cast<__nv_bfloat16*>(asmem + A_VH);
    __nv_bfloat16* Vl = reinterpret_cast<__nv_bfloat16*>(asmem + A_VL);
    __nv_bfloat16* Ph = reinterpret_cast<__nv_bfloat16*>(asmem + A_PH);
    __nv_bfloat16* Pl = reinterpret_cast<__nv_bfloat16*>(asmem + A_PL);
    float* S    = reinterpret_cast<float*>(asmem + A_S);
    float* O    = reinterpret_cast<float*>(asmem + A_O);
    float* sm_m = reinterpret_cast<float*>(asmem + A_M);
    float* sm_l = reinterpret_cast<float*>(asmem + A_L);
    float* sm_sc= reinterpret_cast<float*>(asmem + A_SC);
    int*   msk  = reinterpret_cast<int*>(asmem + A_MS);

    int b = blockIdx.z, hh = blockIdx.y;
    int qt = (SEQ / 64 - 1) - blockIdx.x;
    int q0 = qt * 64;
    int tid = threadIdx.x, wid = tid >> 5;
    int wr = wid & 3, wc = wid >> 2;

    for (int idx = tid; idx < 64 * 16; idx += 256) {
        int i = idx >> 4, d4 = idx & 15;
        size_t ga = (size_t)(b * SEQ + q0 + i) * QKVN + hh * DKH + d4 * 4;
        *reinterpret_cast<uint2*>(&Qh[i * KLD + d4 * 4]) = *reinterpret_cast<const uint2*>(&QKVh[ga]);
        *reinterpret_cast<uint2*>(&Ql[i * KLD + d4 * 4]) = *reinterpret_cast<const uint2*>(&QKVl[ga]);
    }
    for (int idx = tid; idx < 64 * SLD; idx += 256) O[idx] = 0.f;
    if (tid < 64) { sm_m[tid] = -1e30f; sm_l[tid] = 0.f; }

    for (int kt = 0; kt <= qt; kt++) {
        int k0 = kt * 64;
        __syncthreads();
        for (int idx = tid; idx < 64 * 16; idx += 256) {
            int j = idx >> 4, d4 = idx & 15;
            size_t gk = (size_t)(b * SEQ + k0 + j) * QKVN + DMOD + hh * DKH + d4 * 4;
            size_t gv = gk + DMOD;
            *reinterpret_cast<uint2*>(&Kh[j * KLD + d4 * 4]) = *reinterpret_cast<const uint2*>(&QKVh[gk]);
            *reinterpret_cast<uint2*>(&Kl[j * KLD + d4 * 4]) = *reinterpret_cast<const uint2*>(&QKVl[gk]);
            *reinterpret_cast<uint2*>(&Vh[j * KLD + d4 * 4]) = *reinterpret_cast<const uint2*>(&QKVh[gv]);
            *reinterpret_cast<uint2*>(&Vl[j * KLD + d4 * 4]) = *reinterpret_cast<const uint2*>(&QKVl[gv]);
        }
        if (tid < 64) msk[tid] = amask[b * SEQ + k0 + tid];
        __syncthreads();

        {
            wmma::fragment<wmma::accumulator, 16, 16, 16, float> sacc[2];
            wmma::fill_fragment(sacc[0], 0.f);
            wmma::fill_fragment(sacc[1], 0.f);
            #pragma unroll
            for (int ks = 0; ks < 4; ks++) {
                wmma::fragment<wmma::matrix_a, 16, 16, 16, __nv_bfloat16, wmma::row_major> a_h, a_l;
                wmma::load_matrix_sync(a_h, Qh + (wr * 16) * KLD + ks * 16, KLD);
                wmma::load_matrix_sync(a_l, Ql + (wr * 16) * KLD + ks * 16, KLD);
                #pragma unroll
                for (int t = 0; t < 2; t++) {
                    wmma::fragment<wmma::matrix_b, 16, 16, 16, __nv_bfloat16, wmma::col_major> b_h, b_l;
                    wmma::load_matrix_sync(b_h, Kh + (wc * 32 + t * 16) * KLD + ks * 16, KLD);
                    wmma::load_matrix_sync(b_l, Kl + (wc * 32 + t * 16) * KLD + ks * 16, KLD);
                    wmma::mma_sync(sacc[t], a_h, b_h, sacc[t]);
                    wmma::mma_sync(sacc[t], a_h, b_l, sacc[t]);
                    wmma::mma_sync(sacc[t], a_l, b_h, sacc[t]);
                }
            }
            #pragma unroll
            for (int t = 0; t < 2; t++)
                wmma::store_matrix_sync(S + (wr * 16) * SLD + wc * 32 + t * 16, sacc[t], SLD, wmma::mem_row_major);
        }
        __syncthreads();

        {
            int row = tid >> 2, qq = tid & 3;
            float sv[16];
            float tmax = -1e30f;
            #pragma unroll
            for (int jj = 0; jj < 16; jj++) {
                int j = qq * 16 + jj;
                float s = S[row * SLD + j] * 0.125f;
                if (msk[j] == 0) s = -1e9f;
                if (kt == qt && j > row) s = -1e9f;
                sv[jj] = s;
                tmax = fmaxf(tmax, s);
            }
            tmax = fmaxf(tmax, __shfl_xor_sync(0xffffffff, tmax, 1));
            tmax = fmaxf(tmax, __shfl_xor_sync(0xffffffff, tmax, 2));
            float mold = sm_m[row];
            float newm = fmaxf(mold, tmax);
            float psum = 0.f;
            __nv_bfloat16 hb[16], lb[16];
            #pragma unroll
            for (int jj = 0; jj < 16; jj++) {
                float p = __expf(sv[jj] - newm);
                psum += p;
                split2(p, hb[jj], lb[jj]);
            }
            *reinterpret_cast<uint4*>(&Ph[row * KLD + qq * 16])     = *reinterpret_cast<uint4*>(hb);
            *reinterpret_cast<uint4*>(&Ph[row * KLD + qq * 16 + 8]) = *reinterpret_cast<uint4*>(hb + 8);
            *reinterpret_cast<uint4*>(&Pl[row * KLD + qq * 16])     = *reinterpret_cast<uint4*>(lb);
            *reinterpret_cast<uint4*>(&Pl[row * KLD + qq * 16 + 8]) = *reinterpret_cast<uint4*>(lb + 8);
            psum += __shfl_xor_sync(0xffffffff, psum, 1);
            psum += __shfl_xor_sync(0xffffffff, psum, 2);
            if (qq == 0) {
                float sc = __expf(mold - newm);
                sm_sc[row] = sc;
                sm_l[row] = sm_l[row] * sc + psum;
                sm_m[row] = newm;
            }
        }
        __syncthreads();

        {
            wmma::fragment<wmma::accumulator, 16, 16, 16, float> oacc[2];
            wmma::fill_fragment(oacc[0], 0.f);
            wmma::fill_fragment(oacc[1], 0.f);
            #pragma unroll
            for (int ks = 0; ks < 4; ks++) {
                wmma::fragment<wmma::matrix_a, 16, 16, 16, __nv_bfloat16, wmma::row_major> a_h, a_l;
                wmma::load_matrix_sync(a_h, Ph + (wr * 16) * KLD + ks * 16, KLD);
                wmma::load_matrix_sync(a_l, Pl + (wr * 16) * KLD + ks * 16, KLD);
                #pragma unroll
                for (int t = 0; t < 2; t++) {
                    wmma::fragment<wmma::matrix_b, 16, 16, 16, __nv_bfloat16, wmma::row_major> b_h, b_l;
                    wmma::load_matrix_sync(b_h, Vh + (ks * 16) * KLD + wc * 32 + t * 16, KLD);
                    wmma::load_matrix_sync(b_l, Vl + (ks * 16) * KLD + wc * 32 + t * 16, KLD);
                    wmma::mma_sync(oacc[t], a_h, b_h, oacc[t]);
                    wmma::mma_sync(oacc[t], a_h, b_l, oacc[t]);
                    wmma::mma_sync(oacc[t], a_l, b_h, oacc[t]);
                }
            }
            #pragma unroll
            for (int t = 0; t < 2; t++)
                wmma::store_matrix_sync(S + (wr * 16) * SLD + wc * 32 + t * 16, oacc[t], SLD, wmma::mem_row_major);
        }
        __syncthreads();

        for (int idx = tid; idx < 4096; idx += 256) {
            int i = idx >> 6, d = idx & 63;
            O[i * SLD + d] = O[i * SLD + d] * sm_sc[i] + S[i * SLD + d];
        }
    }
    __syncthreads();
    for (int idx = tid; idx < 1024; idx += 256) {
        int i = idx >> 4, d4 = (idx & 15) * 4;
        float inv = 1.0f / sm_l[i];
        __nv_bfloat16 hb[4], lb[4];
        #pragma unroll
        for (int q = 0; q < 4; q++)
            split2(O[i * SLD + d4 + q] * inv, hb[q], lb[q]);
        size_t off = (size_t)(b * SEQ + q0 + i) * DMOD + hh * DKH + d4;
        *reinterpret_cast<uint2*>(Ohg + off) = *reinterpret_cast<uint2*>(hb);
        *reinterpret_cast<uint2*>(Olg + off) = *reinterpret_cast<uint2*>(lb);
    }
}

// ---------------- launch ----------------
extern "C" void kernel_launch(void* const* d_in, const int* in_sizes, int n_in,
                              void* d_out, int out_size) {
    const int*   ids   = (const int*)  d_in[0];
    const int*   amask = (const int*)  d_in[1];
    const float* emb   = (const float*)d_in[2];
    const float* pe    = (const float*)d_in[3];
    const float* wq    = (const float*)d_in[4];
    const float* wk    = (const float*)d_in[5];
    const float* wv    = (const float*)d_in[6];
    const float* wo    = (const float*)d_in[7];
    const float* ln1w  = (const float*)d_in[8];
    const float* ln1b  = (const float*)d_in[9];
    const float* ln2w  = (const float*)d_in[10];
    const float* ln2b  = (const float*)d_in[11];
    const float* w1    = (const float*)d_in[12];
    const float* b1    = (const float*)d_in[13];
    const float* w2    = (const float*)d_in[14];
    const float* b2    = (const float*)d_in[15];
    const float* lnfw  = (const float*)d_in[16];
    const float* lnfb  = (const float*)d_in[17];
    float* out = (float*)d_out;

    float *x;
    __nv_bfloat16 *qkvh, *qkvl, *h_h, *h_l, *att_h, *att_l, *ff_h, *ff_l;
    __nv_bfloat16 *wqkv_h, *wqkv_l, *wo_h, *wo_l, *w1_h, *w1_l, *w2_h, *w2_l, *emb_h, *emb_l;
    cudaGetSymbolAddress((void**)&x,     g_x);
    cudaGetSymbolAddress((void**)&qkvh,  g_qkvh);  cudaGetSymbolAddress((void**)&qkvl,  g_qkvl);
    cudaGetSymbolAddress((void**)&h_h,   g_h_h);   cudaGetSymbolAddress((void**)&h_l,   g_h_l);
    cudaGetSymbolAddress((void**)&att_h, g_att_h); cudaGetSymbolAddress((void**)&att_l, g_att_l);
    cudaGetSymbolAddress((void**)&ff_h,  g_ff_h);  cudaGetSymbolAddress((void**)&ff_l,  g_ff_l);
    cudaGetSymbolAddress((void**)&wqkv_h, g_wqkv_h); cudaGetSymbolAddress((void**)&wqkv_l, g_wqkv_l);
    cudaGetSymbolAddress((void**)&wo_h,  g_wo_h);  cudaGetSymbolAddress((void**)&wo_l,  g_wo_l);
    cudaGetSymbolAddress((void**)&w1_h,  g_w1_h);  cudaGetSymbolAddress((void**)&w1_l,  g_w1_l);
    cudaGetSymbolAddress((void**)&w2_h,  g_w2_h);  cudaGetSymbolAddress((void**)&w2_l,  g_w2_l);
    cudaGetSymbolAddress((void**)&emb_h, g_emb_h); cudaGetSymbolAddress((void**)&emb_l, g_emb_l);

    const int SM_T128 = 2 * (2 * (128 * 40 * 2) + 2 * (32 * 136 * 2));   // 75776
    const int SM_T64  = 2 * (2 * (128 * 40 * 2) + 2 * (32 * 72 * 2));    // 59392
    const int SM_COL  = 2 * (2 * (128 * 40 * 2) + 2 * (128 * 40 * 2));   // 81920

    cudaFuncSetAttribute(gemm_tc<0, false, false, 128, true>,                 cudaFuncAttributeMaxDynamicSharedMemorySize, SM_T128);
    cudaFuncSetAttribute(gemm_tc<EP_RES, false, false, 64, false>,            cudaFuncAttributeMaxDynamicSharedMemorySize, SM_T64);
    cudaFuncSetAttribute(gemm_tc<EP_BIAS | EP_GELU, false, false, 128, true>, cudaFuncAttributeMaxDynamicSharedMemorySize, SM_T128);
    cudaFuncSetAttribute(gemm_tc<EP_BIAS | EP_RES, false, false, 64, false>,  cudaFuncAttributeMaxDynamicSharedMemorySize, SM_T64);
    cudaFuncSetAttribute(gemm_tc<0, true, true, 128, false>,                  cudaFuncAttributeMaxDynamicSharedMemorySize, SM_COL);
    cudaFuncSetAttribute(attn_kernel, cudaFuncAttributeMaxDynamicSharedMemorySize, ATT_SMEM);

    split_all_kernel<<<(N_SPLIT_TOT + 255) / 256, 256>>>(
        wq, wk, wv, wo, w1, w2, emb,
        wqkv_h, wqkv_l, wo_h, wo_l, w1_h, w1_l, w2_h, w2_l, emb_h, emb_l);
    { int n = MTOK * DMOD; embed_kernel<<<(n + 255) / 256, 256>>>(ids, emb, pe, x); }

    dim3 gQKV(QKVN / 128, MTOK / 128);
    dim3 gD64(DMOD / 64, MTOK / 128);
    dim3 gF(FFD / 128, MTOK / 128);

    for (int l = 0; l < LNUM; l++) {
        ln_kernel<<<MTOK, 256>>>(x, ln1w + l * DMOD, ln1b + l * DMOD, h_h, h_l);

        gemm_tc<0, false, false, 128, true><<<gQKV, 256, SM_T128>>>(
            h_h, h_l, wqkv_h + (size_t)l * DMOD * QKVN, wqkv_l + (size_t)l * DMOD * QKVN,
            nullptr, nullptr, nullptr, qkvh, qkvl, MTOK, QKVN, DMOD, QKVN, QKVN);

        attn_kernel<<<dim3(SEQ / 64, HNUM, BAT), 256, ATT_SMEM>>>(qkvh, qkvl, amask, att_h, att_l);

        gemm_tc<EP_RES, false, false, 64, false><<<gD64, 256, SM_T64>>>(
            att_h, att_l, wo_h + (size_t)l * DMOD * DMOD, wo_l + (size_t)l * DMOD * DMOD,
            nullptr, x, x, nullptr, nullptr, MTOK, DMOD, DMOD, DMOD, DMOD);

        ln_kernel<<<MTOK, 256>>>(x, ln2w + l * DMOD, ln2b + l * DMOD, h_h, h_l);

        gemm_tc<EP_BIAS | EP_GELU, false, false, 128, true><<<gF, 256, SM_T128>>>(
            h_h, h_l, w1_h + (size_t)l * DMOD * FFD, w1_l + (size_t)l * DMOD * FFD,
            b1 + (size_t)l * FFD, nullptr, nullptr, ff_h, ff_l, MTOK, FFD, DMOD, FFD, FFD);

        gemm_tc<EP_BIAS | EP_RES, false, false, 64, false><<<gD64, 256, SM_T64>>>(
            ff_h, ff_l, w2_h + (size_t)l * FFD * DMOD, w2_l + (size_t)l * FFD * DMOD,
            b2 + (size_t)l * DMOD, x, x, nullptr, nullptr, MTOK, DMOD, FFD, DMOD, DMOD);
    }

    ln_kernel<<<MTOK, 256>>>(x, lnfw, lnfb, h_h, h_l);

    dim3 gV(MTOK / 128, (VOC + 127) / 128);
    gemm_tc<0, true, true, 128, false><<<gV, 256, SM_COL>>>(
        h_h, h_l, emb_h, emb_l, nullptr, nullptr, out, nullptr, nullptr, MTOK, VOC, DMOD, DMOD, VOC);
}

// round 12
// speedup vs baseline: 1.3708x; 1.0623x over previous
#include <cuda_runtime.h>
#include <cuda_bf16.h>
#include <mma.h>
#include <math.h>
#include <cstdint>
#include <cstddef>
using namespace nvcuda;

#define LNUM 6
#define DMOD 768
#define HNUM 12
#define DKH  64
#define FFD  3072
#define VOC  50257
#define SEQ  1024
#define BAT  2
#define MTOK (BAT*SEQ)   // 2048
#define QKVN (3*DMOD)    // 2304

// ---------------- device scratch ----------------
__device__ float g_x  [MTOK*DMOD];
__device__ float g_part[2*MTOK*DMOD];     // split-K partials
__device__ __nv_bfloat16 g_qkvh[MTOK*QKVN], g_qkvl[MTOK*QKVN];
__device__ __nv_bfloat16 g_h_h [MTOK*DMOD],  g_h_l [MTOK*DMOD];
__device__ __nv_bfloat16 g_att_h[MTOK*DMOD], g_att_l[MTOK*DMOD];
__device__ __nv_bfloat16 g_ff_h[MTOK*FFD],   g_ff_l[MTOK*FFD];
__device__ __nv_bfloat16 g_wqkv_h[LNUM*DMOD*QKVN], g_wqkv_l[LNUM*DMOD*QKVN];
__device__ __nv_bfloat16 g_wo_h [LNUM*DMOD*DMOD],  g_wo_l [LNUM*DMOD*DMOD];
__device__ __nv_bfloat16 g_w1_h [LNUM*DMOD*FFD],   g_w1_l [LNUM*DMOD*FFD];
__device__ __nv_bfloat16 g_w2_h [LNUM*FFD*DMOD],   g_w2_l [LNUM*FFD*DMOD];
__device__ __nv_bfloat16 g_emb_h[VOC*DMOD],        g_emb_l[VOC*DMOD];

// ---------------- helpers ----------------
__device__ __forceinline__ uint32_t smem_u32(const void* p) {
    uint32_t a;
    asm("{ .reg .u64 t; cvta.to.shared.u64 t, %1; cvt.u32.u64 %0, t; }" : "=r"(a) : "l"(p));
    return a;
}
__device__ __forceinline__ void cpa16(uint32_t dst, const void* src) {
    asm volatile("cp.async.cg.shared.global [%0], [%1], 16;" :: "r"(dst), "l"(src));
}
#define CP_COMMIT() asm volatile("cp.async.commit_group;" ::: "memory")
#define CP_WAIT1()  asm volatile("cp.async.wait_group 1;" ::: "memory")

__device__ __forceinline__ void split2(float v, __nv_bfloat16& hi, __nv_bfloat16& lo) {
    hi = __float2bfloat16(v);
    lo = __float2bfloat16(v - __bfloat162float(hi));
}

// ---------------- merged prepass split kernel ----------------
#define N_QKV (LNUM*DMOD*QKVN)
#define N_WO  (LNUM*DMOD*DMOD)
#define N_W1  (LNUM*DMOD*FFD)
#define N_W2  (LNUM*FFD*DMOD)
#define N_EMB (VOC*DMOD)
#define N_SPLIT_TOT (N_QKV + N_WO + N_W1 + N_W2 + N_EMB)

__global__ void split_all_kernel(const float* __restrict__ wq, const float* __restrict__ wk,
                                 const float* __restrict__ wv, const float* __restrict__ wo,
                                 const float* __restrict__ w1, const float* __restrict__ w2,
                                 const float* __restrict__ emb,
                                 __nv_bfloat16* __restrict__ qkv_h, __nv_bfloat16* __restrict__ qkv_l,
                                 __nv_bfloat16* __restrict__ wo_h,  __nv_bfloat16* __restrict__ wo_l,
                                 __nv_bfloat16* __restrict__ w1_h,  __nv_bfloat16* __restrict__ w1_l,
                                 __nv_bfloat16* __restrict__ w2_h,  __nv_bfloat16* __restrict__ w2_l,
                                 __nv_bfloat16* __restrict__ emb_h, __nv_bfloat16* __restrict__ emb_l) {
    int i = blockIdx.x * blockDim.x + threadIdx.x;
    if (i >= N_SPLIT_TOT) return;
    if (i < N_QKV) {
        int l = i / (DMOD * QKVN);
        int rem = i % (DMOD * QKVN);
        int k = rem / QKVN, j = rem % QKVN;
        const float* s = (j < DMOD) ? wq : (j < 2 * DMOD) ? wk : wv;
        float v = s[(size_t)l * DMOD * DMOD + (size_t)k * DMOD + (j % DMOD)];
        split2(v, qkv_h[i], qkv_l[i]);
        return;
    }
    i -= N_QKV;
    if (i < N_WO)  { split2(wo[i],  wo_h[i],  wo_l[i]);  return; }
    i -= N_WO;
    if (i < N_W1)  { split2(w1[i],  w1_h[i],  w1_l[i]);  return; }
    i -= N_W1;
    if (i < N_W2)  { split2(w2[i],  w2_h[i],  w2_l[i]);  return; }
    i -= N_W2;
    split2(emb[i], emb_h[i], emb_l[i]);
}

// ---------------- embedding ----------------
__global__ void embed_kernel(const int* __restrict__ ids, const float* __restrict__ emb,
                             const float* __restrict__ pe, float* __restrict__ X) {
    int i = blockIdx.x * blockDim.x + threadIdx.x;
    if (i >= MTOK * DMOD) return;
    int d = i % DMOD, t = i / DMOD, s = t % SEQ;
    X[i] = emb[(size_t)ids[t] * DMOD + d] + pe[s * DMOD + d];
}

// ---------------- split-K reduce: x += p0 + p1 (+ bias) ----------------
__global__ void reduce_add_kernel(float* __restrict__ X, const float* __restrict__ p0,
                                  const float* __restrict__ p1, const float* __restrict__ bias) {
    int i = blockIdx.x * blockDim.x + threadIdx.x;   // over MTOK*DMOD/4
    if (i >= MTOK * DMOD / 4) return;
    float4 a = reinterpret_cast<float4*>(X)[i];
    float4 q0 = reinterpret_cast<const float4*>(p0)[i];
    float4 q1 = reinterpret_cast<const float4*>(p1)[i];
    a.x += q0.x + q1.x; a.y += q0.y + q1.y;
    a.z += q0.z + q1.z; a.w += q0.w + q1.w;
    if (bias) {
        float4 b = reinterpret_cast<const float4*>(bias)[i % (DMOD / 4)];
        a.x += b.x; a.y += b.y; a.z += b.z; a.w += b.w;
    }
    reinterpret_cast<float4*>(X)[i] = a;
}

// ---------------- layernorm -> bf16 hi/lo (vectorized) ----------------
__global__ void ln_kernel(const float* __restrict__ X, const float* __restrict__ w,
                          const float* __restrict__ bvec,
                          __nv_bfloat16* __restrict__ Yh, __nv_bfloat16* __restrict__ Yl) {
    __shared__ float red[256];
    int row = blockIdx.x, tid = threadIdx.x;
    const float4* x4 = reinterpret_cast<const float4*>(X + (size_t)row * DMOD);
    float4 xv = make_float4(0.f, 0.f, 0.f, 0.f);
    if (tid < 192) xv = x4[tid];
    float s = xv.x + xv.y + xv.z + xv.w;
    red[tid] = s; __syncthreads();
    for (int o = 128; o > 0; o >>= 1) { if (tid < o) red[tid] += red[tid + o]; __syncthreads(); }
    float mu = red[0] * (1.0f / DMOD); __syncthreads();
    float v = 0.f;
    if (tid < 192) {
        float a = xv.x - mu, b = xv.y - mu, c = xv.z - mu, d = xv.w - mu;
        v = a * a + b * b + c * c + d * d;
    }
    red[tid] = v; __syncthreads();
    for (int o = 128; o > 0; o >>= 1) { if (tid < o) red[tid] += red[tid + o]; __syncthreads(); }
    float rstd = rsqrtf(red[0] * (1.0f / DMOD) + 1e-5f);
    if (tid < 192) {
        float4 wv = reinterpret_cast<const float4*>(w)[tid];
        float4 bv = reinterpret_cast<const float4*>(bvec)[tid];
        float y[4];
        y[0] = (xv.x - mu) * rstd * wv.x + bv.x;
        y[1] = (xv.y - mu) * rstd * wv.y + bv.y;
        y[2] = (xv.z - mu) * rstd * wv.z + bv.z;
        y[3] = (xv.w - mu) * rstd * wv.w + bv.w;
        __nv_bfloat16 hb[4], lb[4];
        #pragma unroll
        for (int q = 0; q < 4; q++) split2(y[q], hb[q], lb[q]);
        size_t off = (size_t)row * DMOD + tid * 4;
        *reinterpret_cast<uint2*>(Yh + off) = *reinterpret_cast<uint2*>(hb);
        *reinterpret_cast<uint2*>(Yl + off) = *reinterpret_cast<uint2*>(lb);
    }
}

// ---------------- GEMM: pre-split bf16, cp.async 2-stage, WMMA 3-term, 2 CTAs/SM ----------------
// Generic split-K: gridDim.z partitions the K range; C offset by z*M*ldc (partials).
#define EP_BIAS 1
#define EP_GELU 2
#define EP_RES  4

__device__ __forceinline__ float gelu_exact(float x) {
    return 0.5f * x * (1.0f + erff(x * 0.70710678118654752f));
}

template<int EP, bool BCOL, bool NG, int TN, bool WH>
__global__ void __launch_bounds__(256, 2)
gemm_tc(const __nv_bfloat16* __restrict__ Ah_g, const __nv_bfloat16* __restrict__ Al_g,
        const __nv_bfloat16* __restrict__ Bh_g, const __nv_bfloat16* __restrict__ Bl_g,
        const float* __restrict__ bias, const float* __restrict__ res,
        float* __restrict__ C, __nv_bfloat16* __restrict__ Chi, __nv_bfloat16* __restrict__ Clo,
        int M, int N, int K, int lda, int ldb, int ldc) {
    constexpr int ALD = 40;
    constexpr int BLD = BCOL ? 40 : (TN + 8);
    constexpr int ABYTES = 128 * ALD * 2;
    constexpr int BBYTES = BCOL ? (TN * 40 * 2) : (32 * BLD * 2);
    constexpr int STAGEB = 2 * (ABYTES + BBYTES);
    constexpr int NJ = TN / 32;

    extern __shared__ char smem[];
    uint32_t sbase = smem_u32(smem);

    int tid = threadIdx.x, lane = tid & 31, wid = tid >> 5;
    int warp_m = wid & 3, warp_n = wid >> 2;
    int bm, bn;
    if (BCOL) { bm = blockIdx.x * 128; bn = blockIdx.y * TN; }
    else      { bm = blockIdx.y * 128; bn = blockIdx.x * TN; }
    int kbase = blockIdx.z * K;
    int nch = K >> 5;

    wmma::fragment<wmma::accumulator, 16, 16, 16, float> acc[2][NJ];
    #pragma unroll
    for (int i = 0; i < 2; i++)
        #pragma unroll
        for (int j = 0; j < NJ; j++) wmma::fill_fragment(acc[i][j], 0.f);

    auto load_stage = [&](int s, int c) {
        int k0 = kbase + c * 32;
        uint32_t abase = sbase + s * STAGEB;
        #pragma unroll
        for (int hn = 0; hn < 2; hn++) {
            const __nv_bfloat16* g = hn ? Al_g : Ah_g;
            uint32_t db = abase + hn * ABYTES;
            #pragma unroll
            for (int i = 0; i < 2; i++) {
                int cid = tid + i * 256;
                int r = cid >> 2, seg = cid & 3;
                cpa16(db + (uint32_t)(r * ALD + seg * 8) * 2,
                      g + (size_t)(bm + r) * lda + k0 + seg * 8);
            }
        }
        uint32_t bbase = abase + 2 * ABYTES;
        if (BCOL) {
            constexpr int NITB = (TN * 4) / 256;
            #pragma unroll
            for (int hn = 0; hn < 2; hn++) {
                const __nv_bfloat16* g = hn ? Bl_g : Bh_g;
                uint32_t db = bbase + hn * BBYTES;
                #pragma unroll
                for (int i = 0; i < NITB; i++) {
                    int cid = tid + i * 256;
                    int r = cid >> 2, seg = cid & 3;
                    int gn = bn + r;
                    uint32_t d = db + (uint32_t)(r * 40 + seg * 8) * 2;
                    if (!NG || gn < N)
                        cpa16(d, g + (size_t)gn * ldb + k0 + seg * 8);
                    else
                        *reinterpret_cast<uint4*>(smem + (d - sbase)) = make_uint4(0, 0, 0, 0);
                }
            }
        } else {
            constexpr int CH = TN / 8;
            constexpr int NIT = (32 * CH) / 256;
            #pragma unroll
            for (int hn = 0; hn < 2; hn++) {
                const __nv_bfloat16* g = hn ? Bl_g : Bh_g;
                uint32_t db = bbase + hn * BBYTES;
                #pragma unroll
                for (int i = 0; i < NIT; i++) {
                    int cid = tid + i * 256;
                    int kr = cid / CH, seg = cid % CH;
                    cpa16(db + (uint32_t)(kr * BLD + seg * 8) * 2,
                          g + (size_t)(k0 + kr) * ldb + bn + seg * 8);
                }
            }
        }
        CP_COMMIT();
    };

    auto do_mma = [&](int s) {
        char* base = smem + s * STAGEB;
        __nv_bfloat16* Ah = reinterpret_cast<__nv_bfloat16*>(base);
        __nv_bfloat16* Al = reinterpret_cast<__nv_bfloat16*>(base + ABYTES);
        __nv_bfloat16* Bh = reinterpret_cast<__nv_bfloat16*>(base + 2 * ABYTES);
        __nv_bfloat16* Bl = reinterpret_cast<__nv_bfloat16*>(base + 2 * ABYTES + BBYTES);
        #pragma unroll
        for (int kk = 0; kk < 2; kk++) {
            wmma::fragment<wmma::matrix_a, 16, 16, 16, __nv_bfloat16, wmma::row_major> ah[2], al[2];
            #pragma unroll
            for (int i = 0; i < 2; i++) {
                wmma::load_matrix_sync(ah[i], Ah + (warp_m * 32 + i * 16) * ALD + kk * 16, ALD);
                wmma::load_matrix_sync(al[i], Al + (warp_m * 32 + i * 16) * ALD + kk * 16, ALD);
            }
            #pragma unroll
            for (int j = 0; j < NJ; j++) {
                if (BCOL) {
                    wmma::fragment<wmma::matrix_b, 16, 16, 16, __nv_bfloat16, wmma::col_major> bh, bl;
                    wmma::load_matrix_sync(bh, Bh + (warp_n * (TN / 2) + j * 16) * 40 + kk * 16, 40);
                    wmma::load_matrix_sync(bl, Bl + (warp_n * (TN / 2) + j * 16) * 40 + kk * 16, 40);
                    #pragma unroll
                    for (int i = 0; i < 2; i++) {
                        wmma::mma_sync(acc[i][j], ah[i], bh, acc[i][j]);
                        wmma::mma_sync(acc[i][j], ah[i], bl, acc[i][j]);
                        wmma::mma_sync(acc[i][j], al[i], bh, acc[i][j]);
                    }
                } else {
                    wmma::fragment<wmma::matrix_b, 16, 16, 16, __nv_bfloat16, wmma::row_major> bh, bl;
                    wmma::load_matrix_sync(bh, Bh + (kk * 16) * BLD + warp_n * (TN / 2) + j * 16, BLD);
                    wmma::load_matrix_sync(bl, Bl + (kk * 16) * BLD + warp_n * (TN / 2) + j * 16, BLD);
                    #pragma unroll
                    for (int i = 0; i < 2; i++) {
                        wmma::mma_sync(acc[i][j], ah[i], bh, acc[i][j]);
                        wmma::mma_sync(acc[i][j], ah[i], bl, acc[i][j]);
                        wmma::mma_sync(acc[i][j], al[i], bh, acc[i][j]);
                    }
                }
            }
        }
    };

    load_stage(0, 0);
    load_stage(1, 1);
    for (int c = 0; c < nch; c++) {
        CP_WAIT1();
        __syncthreads();
        do_mma(c & 1);
        __syncthreads();
        if (c + 2 < nch) load_stage(c & 1, c + 2);
        else CP_COMMIT();
    }

    // vectorized epilogue (NG path stays scalar: ldc may be odd -> no float4)
    size_t coff = (size_t)blockIdx.z * M * ldc;
    float* stg = reinterpret_cast<float*>(smem) + wid * (16 * 20);
    int r = lane >> 1, cb = (lane & 1) * 8;
    #pragma unroll
    for (int i = 0; i < 2; i++) {
        #pragma unroll
        for (int j = 0; j < NJ; j++) {
            wmma::store_matrix_sync(stg, acc[i][j], 20, wmma::mem_row_major);
            __syncwarp();
            int m = bm + warp_m * 32 + i * 16 + r;
            int n0 = bn + warp_n * (TN / 2) + j * 16 + cb;
            float v[8];
            #pragma unroll
            for (int q = 0; q < 8; q++) v[q] = stg[r * 20 + cb + q];
            if (EP & EP_BIAS) {
                float4 b0 = *reinterpret_cast<const float4*>(bias + n0);
                float4 b1 = *reinterpret_cast<const float4*>(bias + n0 + 4);
                v[0]+=b0.x; v[1]+=b0.y; v[2]+=b0.z; v[3]+=b0.w;
                v[4]+=b1.x; v[5]+=b1.y; v[6]+=b1.z; v[7]+=b1.w;
            }
            if (EP & EP_GELU) {
                #pragma unroll
                for (int q = 0; q < 8; q++) v[q] = gelu_exact(v[q]);
            }
            if (EP & EP_RES) {
                const float* rp = res + (size_t)m * ldc + n0;
                float4 r0 = *reinterpret_cast<const float4*>(rp);
                float4 r1 = *reinterpret_cast<const float4*>(rp + 4);
                v[0]+=r0.x; v[1]+=r0.y; v[2]+=r0.z; v[3]+=r0.w;
                v[4]+=r1.x; v[5]+=r1.y; v[6]+=r1.z; v[7]+=r1.w;
            }
            if (WH) {
                __nv_bfloat16 hb[8], lb[8];
                #pragma unroll
                for (int q = 0; q < 8; q++) split2(v[q], hb[q], lb[q]);
                *reinterpret_cast<uint4*>(Chi + (size_t)m * ldc + n0) = *reinterpret_cast<uint4*>(hb);
                *reinterpret_cast<uint4*>(Clo + (size_t)m * ldc + n0) = *reinterpret_cast<uint4*>(lb);
            } else if (NG) {
                #pragma unroll
                for (int q = 0; q < 8; q++)
                    if (n0 + q < N) C[coff + (size_t)m * ldc + n0 + q] = v[q];
            } else {
                float* cp = C + coff + (size_t)m * ldc + n0;
                *reinterpret_cast<float4*>(cp)     = make_float4(v[0], v[1], v[2], v[3]);
                *reinterpret_cast<float4*>(cp + 4) = make_float4(v[4], v[5], v[6], v[7]);
            }
            __syncwarp();
        }
    }
}

// ---------------- WMMA flash attention (bf16 3-term, fp32 softmax) ----------------
#define KLD 72
#define SLD 68
#define A_QH 0
#define A_QL (A_QH + 64*KLD*2)
#define A_KH (A_QL + 64*KLD*2)
#define A_KL (A_KH + 64*KLD*2)
#define A_VH (A_KL + 64*KLD*2)
#define A_VL (A_VH + 64*KLD*2)
#define A_PH (A_VL + 64*KLD*2)
#define A_PL (A_PH + 64*KLD*2)
#define A_S  (A_PL + 64*KLD*2)
#define A_O  (A_S + 64*SLD*4)
#define A_M  (A_O + 64*SLD*4)
#define A_L  (A_M + 64*4)
#define A_SC (A_L + 64*4)
#define A_MS (A_SC + 64*4)
#define ATT_SMEM (A_MS + 64*4)

__global__ void __launch_bounds__(256)
attn_kernel(const __nv_bfloat16* __restrict__ QKVh, const __nv_bfloat16* __restrict__ QKVl,
            const int* __restrict__ amask,
            __nv_bfloat16* __restrict__ Ohg, __nv_bfloat16* __restrict__ Olg) {
    extern __shared__ char asmem[];
    __nv_bfloat16* Qh = reinterpret_cast<__nv_bfloat16*>(asmem + A_QH);
    __nv_bfloat16* Ql = reinterpret_cast<__nv_bfloat16*>(asmem + A_QL);
    __nv_bfloat16* Kh = reinterpret_cast<__nv_bfloat16*>(asmem + A_KH);
    __nv_bfloat16* Kl = reinterpret_cast<__nv_bfloat16*>(asmem + A_KL);
    __nv_bfloat16* Vh = reinterpret_cast<__nv_bfloat16*>(asmem + A_VH);
    __nv_bfloat16* Vl = reinterpret_cast<__nv_bfloat16*>(asmem + A_VL);
    __nv_bfloat16* Ph = reinterpret_cast<__nv_bfloat16*>(asmem + A_PH);
    __nv_bfloat16* Pl = reinterpret_cast<__nv_bfloat16*>(asmem + A_PL);
    float* S    = reinterpret_cast<float*>(asmem + A_S);
    float* O    = reinterpret_cast<float*>(asmem + A_O);
    float* sm_m = reinterpret_cast<float*>(asmem + A_M);
    float* sm_l = reinterpret_cast<float*>(asmem + A_L);
    float* sm_sc= reinterpret_cast<float*>(asmem + A_SC);
    int*   msk  = reinterpret_cast<int*>(asmem + A_MS);

    int b = blockIdx.z, hh = blockIdx.y;
    int qt = (SEQ / 64 - 1) - blockIdx.x;
    int q0 = qt * 64;
    int tid = threadIdx.x, wid = tid >> 5;
    int wr = wid & 3, wc = wid >> 2;

    for (int idx = tid; idx < 64 * 16; idx += 256) {
        int i = idx >> 4, d4 = idx & 15;
        size_t ga = (size_t)(b * SEQ + q0 + i) * QKVN + hh * DKH + d4 * 4;
        *reinterpret_cast<uint2*>(&Qh[i * KLD + d4 * 4]) = *reinterpret_cast<const uint2*>(&QKVh[ga]);
        *reinterpret_cast<uint2*>(&Ql[i * KLD + d4 * 4]) = *reinterpret_cast<const uint2*>(&QKVl[ga]);
    }
    for (int idx = tid; idx < 64 * SLD; idx += 256) O[idx] = 0.f;
    if (tid < 64) { sm_m[tid] = -1e30f; sm_l[tid] = 0.f; }

    for (int kt = 0; kt <= qt; kt++) {
        int k0 = kt * 64;
        __syncthreads();
        for (int idx = tid; idx < 64 * 16; idx += 256) {
            int j = idx >> 4, d4 = idx & 15;
            size_t gk = (size_t)(b * SEQ + k0 + j) * QKVN + DMOD + hh * DKH + d4 * 4;
            size_t gv = gk + DMOD;
            *reinterpret_cast<uint2*>(&Kh[j * KLD + d4 * 4]) = *reinterpret_cast<const uint2*>(&QKVh[gk]);
            *reinterpret_cast<uint2*>(&Kl[j * KLD + d4 * 4]) = *reinterpret_cast<const uint2*>(&QKVl[gk]);
            *reinterpret_cast<uint2*>(&Vh[j * KLD + d4 * 4]) = *reinterpret_cast<const uint2*>(&QKVh[gv]);
            *reinterpret_cast<uint2*>(&Vl[j * KLD + d4 * 4]) = *reinterpret_cast<const uint2*>(&QKVl[gv]);
        }
        if (tid < 64) msk[tid] = amask[b * SEQ + k0 + tid];
        __syncthreads();

        {
            wmma::fragment<wmma::accumulator, 16, 16, 16, float> sacc[2];
            wmma::fill_fragment(sacc[0], 0.f);
            wmma::fill_fragment(sacc[1], 0.f);
            #pragma unroll
            for (int ks = 0; ks < 4; ks++) {
                wmma::fragment<wmma::matrix_a, 16, 16, 16, __nv_bfloat16, wmma::row_major> a_h, a_l;
                wmma::load_matrix_sync(a_h, Qh + (wr * 16) * KLD + ks * 16, KLD);
                wmma::load_matrix_sync(a_l, Ql + (wr * 16) * KLD + ks * 16, KLD);
                #pragma unroll
                for (int t = 0; t < 2; t++) {
                    wmma::fragment<wmma::matrix_b, 16, 16, 16, __nv_bfloat16, wmma::col_major> b_h, b_l;
                    wmma::load_matrix_sync(b_h, Kh + (wc * 32 + t * 16) * KLD + ks * 16, KLD);
                    wmma::load_matrix_sync(b_l, Kl + (wc * 32 + t * 16) * KLD + ks * 16, KLD);
                    wmma::mma_sync(sacc[t], a_h, b_h, sacc[t]);
                    wmma::mma_sync(sacc[t], a_h, b_l, sacc[t]);
                    wmma::mma_sync(sacc[t], a_l, b_h, sacc[t]);
                }
            }
            #pragma unroll
            for (int t = 0; t < 2; t++)
                wmma::store_matrix_sync(S + (wr * 16) * SLD + wc * 32 + t * 16, sacc[t], SLD, wmma::mem_row_major);
        }
        __syncthreads();

        {
            int row = tid >> 2, qq = tid & 3;
            float sv[16];
            float tmax = -1e30f;
            #pragma unroll
            for (int jj = 0; jj < 16; jj++) {
                int j = qq * 16 + jj;
                float s = S[row * SLD + j] * 0.125f;
                if (msk[j] == 0) s = -1e9f;
                if (kt == qt && j > row) s = -1e9f;
                sv[jj] = s;
                tmax = fmaxf(tmax, s);
            }
            tmax = fmaxf(tmax, __shfl_xor_sync(0xffffffff, tmax, 1));
            tmax = fmaxf(tmax, __shfl_xor_sync(0xffffffff, tmax, 2));
            float mold = sm_m[row];
            float newm = fmaxf(mold, tmax);
            float psum = 0.f;
            __nv_bfloat16 hb[16], lb[16];
            #pragma unroll
            for (int jj = 0; jj < 16; jj++) {
                float p = __expf(sv[jj] - newm);
                psum += p;
                split2(p, hb[jj], lb[jj]);
            }
            *reinterpret_cast<uint4*>(&Ph[row * KLD + qq * 16])     = *reinterpret_cast<uint4*>(hb);
            *reinterpret_cast<uint4*>(&Ph[row * KLD + qq * 16 + 8]) = *reinterpret_cast<uint4*>(hb + 8);
            *reinterpret_cast<uint4*>(&Pl[row * KLD + qq * 16])     = *reinterpret_cast<uint4*>(lb);
            *reinterpret_cast<uint4*>(&Pl[row * KLD + qq * 16 + 8]) = *reinterpret_cast<uint4*>(lb + 8);
            psum += __shfl_xor_sync(0xffffffff, psum, 1);
            psum += __shfl_xor_sync(0xffffffff, psum, 2);
            if (qq == 0) {
                float sc = __expf(mold - newm);
                sm_sc[row] = sc;
                sm_l[row] = sm_l[row] * sc + psum;
                sm_m[row] = newm;
            }
        }
        __syncthreads();

        {
            wmma::fragment<wmma::accumulator, 16, 16, 16, float> oacc[2];
            wmma::fill_fragment(oacc[0], 0.f);
            wmma::fill_fragment(oacc[1], 0.f);
            #pragma unroll
            for (int ks = 0; ks < 4; ks++) {
                wmma::fragment<wmma::matrix_a, 16, 16, 16, __nv_bfloat16, wmma::row_major> a_h, a_l;
                wmma::load_matrix_sync(a_h, Ph + (wr * 16) * KLD + ks * 16, KLD);
                wmma::load_matrix_sync(a_l, Pl + (wr * 16) * KLD + ks * 16, KLD);
                #pragma unroll
                for (int t = 0; t < 2; t++) {
                    wmma::fragment<wmma::matrix_b, 16, 16, 16, __nv_bfloat16, wmma::row_major> b_h, b_l;
                    wmma::load_matrix_sync(b_h, Vh + (ks * 16) * KLD + wc * 32 + t * 16, KLD);
                    wmma::load_matrix_sync(b_l, Vl + (ks * 16) * KLD + wc * 32 + t * 16, KLD);
                    wmma::mma_sync(oacc[t], a_h, b_h, oacc[t]);
                    wmma::mma_sync(oacc[t], a_h, b_l, oacc[t]);
                    wmma::mma_sync(oacc[t], a_l, b_h, oacc[t]);
                }
            }
            #pragma unroll
            for (int t = 0; t < 2; t++)
                wmma::store_matrix_sync(S + (wr * 16) * SLD + wc * 32 + t * 16, oacc[t], SLD, wmma::mem_row_major);
        }
        __syncthreads();

        for (int idx = tid; idx < 4096; idx += 256) {
            int i = idx >> 6, d = idx & 63;
            O[i * SLD + d] = O[i * SLD + d] * sm_sc[i] + S[i * SLD + d];
        }
    }
    __syncthreads();
    for (int idx = tid; idx < 1024; idx += 256) {
        int i = idx >> 4, d4 = (idx & 15) * 4;
        float inv = 1.0f / sm_l[i];
        __nv_bfloat16 hb[4], lb[4];
        #pragma unroll
        for (int q = 0; q < 4; q++)
            split2(O[i * SLD + d4 + q] * inv, hb[q], lb[q]);
        size_t off = (size_t)(b * SEQ + q0 + i) * DMOD + hh * DKH + d4;
        *reinterpret_cast<uint2*>(Ohg + off) = *reinterpret_cast<uint2*>(hb);
        *reinterpret_cast<uint2*>(Olg + off) = *reinterpret_cast<uint2*>(lb);
    }
}

// ---------------- launch ----------------
extern "C" void kernel_launch(void* const* d_in, const int* in_sizes, int n_in,
                              void* d_out, int out_size) {
    const int*   ids   = (const int*)  d_in[0];
    const int*   amask = (const int*)  d_in[1];
    const float* emb   = (const float*)d_in[2];
    const float* pe    = (const float*)d_in[3];
    const float* wq    = (const float*)d_in[4];
    const float* wk    = (const float*)d_in[5];
    const float* wv    = (const float*)d_in[6];
    const float* wo    = (const float*)d_in[7];
    const float* ln1w  = (const float*)d_in[8];
    const float* ln1b  = (const float*)d_in[9];
    const float* ln2w  = (const float*)d_in[10];
    const float* ln2b  = (const float*)d_in[11];
    const float* w1    = (const float*)d_in[12];
    const float* b1    = (const float*)d_in[13];
    const float* w2    = (const float*)d_in[14];
    const float* b2    = (const float*)d_in[15];
    const float* lnfw  = (const float*)d_in[16];
    const float* lnfb  = (const float*)d_in[17];
    float* out = (float*)d_out;

    float *x, *part;
    __nv_bfloat16 *qkvh, *qkvl, *h_h, *h_l, *att_h, *att_l, *ff_h, *ff_l;
    __nv_bfloat16 *wqkv_h, *wqkv_l, *wo_h, *wo_l, *w1_h, *w1_l, *w2_h, *w2_l, *emb_h, *emb_l;
    cudaGetSymbolAddress((void**)&x,     g_x);
    cudaGetSymbolAddress((void**)&part,  g_part);
    cudaGetSymbolAddress((void**)&qkvh,  g_qkvh);  cudaGetSymbolAddress((void**)&qkvl,  g_qkvl);
    cudaGetSymbolAddress((void**)&h_h,   g_h_h);   cudaGetSymbolAddress((void**)&h_l,   g_h_l);
    cudaGetSymbolAddress((void**)&att_h, g_att_h); cudaGetSymbolAddress((void**)&att_l, g_att_l);
    cudaGetSymbolAddress((void**)&ff_h,  g_ff_h);  cudaGetSymbolAddress((void**)&ff_l,  g_ff_l);
    cudaGetSymbolAddress((void**)&wqkv_h, g_wqkv_h); cudaGetSymbolAddress((void**)&wqkv_l, g_wqkv_l);
    cudaGetSymbolAddress((void**)&wo_h,  g_wo_h);  cudaGetSymbolAddress((void**)&wo_l,  g_wo_l);
    cudaGetSymbolAddress((void**)&w1_h,  g_w1_h);  cudaGetSymbolAddress((void**)&w1_l,  g_w1_l);
    cudaGetSymbolAddress((void**)&w2_h,  g_w2_h);  cudaGetSymbolAddress((void**)&w2_l,  g_w2_l);
    cudaGetSymbolAddress((void**)&emb_h, g_emb_h); cudaGetSymbolAddress((void**)&emb_l, g_emb_l);

    const int SM_T128 = 2 * (2 * (128 * 40 * 2) + 2 * (32 * 136 * 2));   // 75776
    const int SM_T64  = 2 * (2 * (128 * 40 * 2) + 2 * (32 * 72 * 2));    // 59392
    const int SM_COL  = 2 * (2 * (128 * 40 * 2) + 2 * (128 * 40 * 2));   // 81920

    cudaFuncSetAttribute(gemm_tc<0, false, false, 128, true>,                 cudaFuncAttributeMaxDynamicSharedMemorySize, SM_T128);
    cudaFuncSetAttribute(gemm_tc<0, false, false, 64, false>,                 cudaFuncAttributeMaxDynamicSharedMemorySize, SM_T64);
    cudaFuncSetAttribute(gemm_tc<EP_BIAS | EP_GELU, false, false, 128, true>, cudaFuncAttributeMaxDynamicSharedMemorySize, SM_T128);
    cudaFuncSetAttribute(gemm_tc<0, true, true, 128, false>,                  cudaFuncAttributeMaxDynamicSharedMemorySize, SM_COL);
    cudaFuncSetAttribute(attn_kernel, cudaFuncAttributeMaxDynamicSharedMemorySize, ATT_SMEM);

    split_all_kernel<<<(N_SPLIT_TOT + 255) / 256, 256>>>(
        wq, wk, wv, wo, w1, w2, emb,
        wqkv_h, wqkv_l, wo_h, wo_l, w1_h, w1_l, w2_h, w2_l, emb_h, emb_l);
    { int n = MTOK * DMOD; embed_kernel<<<(n + 255) / 256, 256>>>(ids, emb, pe, x); }

    dim3 gQKV(QKVN / 128, MTOK / 128);
    dim3 gD64S(DMOD / 64, MTOK / 128, 2);   // split-K=2 grids
    dim3 gF(FFD / 128, MTOK / 128);
    int nred = (MTOK * DMOD / 4 + 255) / 256;

    for (int l = 0; l < LNUM; l++) {
        ln_kernel<<<MTOK, 256>>>(x, ln1w + l * DMOD, ln1b + l * DMOD, h_h, h_l);

        gemm_tc<0, false, false, 128, true><<<gQKV, 256, SM_T128>>>(
            h_h, h_l, wqkv_h + (size_t)l * DMOD * QKVN, wqkv_l + (size_t)l * DMOD * QKVN,
            nullptr, nullptr, nullptr, qkvh, qkvl, MTOK, QKVN, DMOD, DMOD, QKVN, QKVN);

        attn_kernel<<<dim3(SEQ / 64, HNUM, BAT), 256, ATT_SMEM>>>(qkvh, qkvl, amask, att_h, att_l);

        // WO split-K=2: partials then x += p0+p1
        gemm_tc<0, false, false, 64, false><<<gD64S, 256, SM_T64>>>(
            att_h, att_l, wo_h + (size_t)l * DMOD * DMOD, wo_l + (size_t)l * DMOD * DMOD,
            nullptr, nullptr, part, nullptr, nullptr, MTOK, DMOD, DMOD / 2, DMOD, DMOD, DMOD);
        reduce_add_kernel<<<nred, 256>>>(x, part, part + MTOK * DMOD, nullptr);

        ln_kernel<<<MTOK, 256>>>(x, ln2w + l * DMOD, ln2b + l * DMOD, h_h, h_l);

        gemm_tc<EP_BIAS | EP_GELU, false, false, 128, true><<<gF, 256, SM_T128>>>(
            h_h, h_l, w1_h + (size_t)l * DMOD * FFD, w1_l + (size_t)l * DMOD * FFD,
            b1 + (size_t)l * FFD, nullptr, nullptr, ff_h, ff_l, MTOK, FFD, DMOD, DMOD, FFD, FFD);

        // FF2 split-K=2: partials then x += p0+p1+b2
        gemm_tc<0, false, false, 64, false><<<gD64S, 256, SM_T64>>>(
            ff_h, ff_l, w2_h + (size_t)l * FFD * DMOD, w2_l + (size_t)l * FFD * DMOD,
            nullptr, nullptr, part, nullptr, nullptr, MTOK, DMOD, FFD / 2, FFD, DMOD, DMOD);
        reduce_add_kernel<<<nred, 256>>>(x, part, part + MTOK * DMOD, b2 + (size_t)l * DMOD);
    }

    ln_kernel<<<MTOK, 256>>>(x, lnfw, lnfb, h_h, h_l);

    dim3 gV(MTOK / 128, (VOC + 127) / 128);
    gemm_tc<0, true, true, 128, false><<<gV, 256, SM_COL>>>(
        h_h, h_l, emb_h, emb_l, nullptr, nullptr, out, nullptr, nullptr, MTOK, VOC, DMOD, DMOD, DMOD, VOC);
}

// round 15
// speedup vs baseline: 1.3916x; 1.0152x over previous
#include <cuda_runtime.h>
#include <cuda_bf16.h>
#include <mma.h>
#include <math.h>
#include <cstdint>
#include <cstddef>
using namespace nvcuda;

#define LNUM 6
#define DMOD 768
#define HNUM 12
#define DKH  64
#define FFD  3072
#define VOC  50257
#define SEQ  1024
#define BAT  2
#define MTOK (BAT*SEQ)   // 2048
#define QKVN (3*DMOD)    // 2304

// ---------------- device scratch ----------------
__device__ float g_x  [MTOK*DMOD];
__device__ float g_part[2*MTOK*DMOD];     // split-K partials
__device__ __nv_bfloat16 g_qkvh[MTOK*QKVN], g_qkvl[MTOK*QKVN];
__device__ __nv_bfloat16 g_h_h [MTOK*DMOD],  g_h_l [MTOK*DMOD];
__device__ __nv_bfloat16 g_att_h[MTOK*DMOD], g_att_l[MTOK*DMOD];
__device__ __nv_bfloat16 g_ff_h[MTOK*FFD],   g_ff_l[MTOK*FFD];
__device__ __nv_bfloat16 g_wqkv_h[LNUM*DMOD*QKVN], g_wqkv_l[LNUM*DMOD*QKVN];
__device__ __nv_bfloat16 g_wo_h [LNUM*DMOD*DMOD],  g_wo_l [LNUM*DMOD*DMOD];
__device__ __nv_bfloat16 g_w1_h [LNUM*DMOD*FFD],   g_w1_l [LNUM*DMOD*FFD];
__device__ __nv_bfloat16 g_w2_h [LNUM*FFD*DMOD],   g_w2_l [LNUM*FFD*DMOD];
__device__ __nv_bfloat16 g_emb_h[VOC*DMOD],        g_emb_l[VOC*DMOD];

// ---------------- helpers ----------------
__device__ __forceinline__ uint32_t smem_u32(const void* p) {
    uint32_t a;
    asm("{ .reg .u64 t; cvta.to.shared.u64 t, %1; cvt.u32.u64 %0, t; }" : "=r"(a) : "l"(p));
    return a;
}
__device__ __forceinline__ void cpa16(uint32_t dst, const void* src) {
    asm volatile("cp.async.cg.shared.global [%0], [%1], 16;" :: "r"(dst), "l"(src));
}
#define CP_COMMIT() asm volatile("cp.async.commit_group;" ::: "memory")
#define CP_WAIT1()  asm volatile("cp.async.wait_group 1;" ::: "memory")

__device__ __forceinline__ void split2(float v, __nv_bfloat16& hi, __nv_bfloat16& lo) {
    hi = __float2bfloat16(v);
    lo = __float2bfloat16(v - __bfloat162float(hi));
}

// ---------------- merged prepass split kernel ----------------
#define N_QKV (LNUM*DMOD*QKVN)
#define N_WO  (LNUM*DMOD*DMOD)
#define N_W1  (LNUM*DMOD*FFD)
#define N_W2  (LNUM*FFD*DMOD)
#define N_EMB (VOC*DMOD)
#define N_SPLIT_TOT (N_QKV + N_WO + N_W1 + N_W2 + N_EMB)

__global__ void split_all_kernel(const float* __restrict__ wq, const float* __restrict__ wk,
                                 const float* __restrict__ wv, const float* __restrict__ wo,
                                 const float* __restrict__ w1, const float* __restrict__ w2,
                                 const float* __restrict__ emb,
                                 __nv_bfloat16* __restrict__ qkv_h, __nv_bfloat16* __restrict__ qkv_l,
                                 __nv_bfloat16* __restrict__ wo_h,  __nv_bfloat16* __restrict__ wo_l,
                                 __nv_bfloat16* __restrict__ w1_h,  __nv_bfloat16* __restrict__ w1_l,
                                 __nv_bfloat16* __restrict__ w2_h,  __nv_bfloat16* __restrict__ w2_l,
                                 __nv_bfloat16* __restrict__ emb_h, __nv_bfloat16* __restrict__ emb_l) {
    int i = blockIdx.x * blockDim.x + threadIdx.x;
    if (i >= N_SPLIT_TOT) return;
    if (i < N_QKV) {
        int l = i / (DMOD * QKVN);
        int rem = i % (DMOD * QKVN);
        int k = rem / QKVN, j = rem % QKVN;
        const float* s = (j < DMOD) ? wq : (j < 2 * DMOD) ? wk : wv;
        float v = s[(size_t)l * DMOD * DMOD + (size_t)k * DMOD + (j % DMOD)];
        split2(v, qkv_h[i], qkv_l[i]);
        return;
    }
    i -= N_QKV;
    if (i < N_WO)  { split2(wo[i],  wo_h[i],  wo_l[i]);  return; }
    i -= N_WO;
    if (i < N_W1)  { split2(w1[i],  w1_h[i],  w1_l[i]);  return; }
    i -= N_W1;
    if (i < N_W2)  { split2(w2[i],  w2_h[i],  w2_l[i]);  return; }
    i -= N_W2;
    split2(emb[i], emb_h[i], emb_l[i]);
}

// ---------------- embedding ----------------
__global__ void embed_kernel(const int* __restrict__ ids, const float* __restrict__ emb,
                             const float* __restrict__ pe, float* __restrict__ X) {
    int i = blockIdx.x * blockDim.x + threadIdx.x;
    if (i >= MTOK * DMOD) return;
    int d = i % DMOD, t = i / DMOD, s = t % SEQ;
    X[i] = emb[(size_t)ids[t] * DMOD + d] + pe[s * DMOD + d];
}

// ---------------- fused (split-K reduce) + layernorm -> bf16 hi/lo ----------------
// If p0 != null: x_row += p0_row + p1_row (+pbias), written back to X, then LN.
__global__ void ln_kernel(float* __restrict__ X,
                          const float* __restrict__ p0, const float* __restrict__ p1,
                          const float* __restrict__ pbias,
                          const float* __restrict__ w, const float* __restrict__ bvec,
                          __nv_bfloat16* __restrict__ Yh, __nv_bfloat16* __restrict__ Yl) {
    __shared__ float red[256];
    int row = blockIdx.x, tid = threadIdx.x;
    float4 xv = make_float4(0.f, 0.f, 0.f, 0.f);
    if (tid < 192) {
        xv = reinterpret_cast<const float4*>(X + (size_t)row * DMOD)[tid];
        if (p0) {
            float4 a = reinterpret_cast<const float4*>(p0 + (size_t)row * DMOD)[tid];
            float4 b = reinterpret_cast<const float4*>(p1 + (size_t)row * DMOD)[tid];
            xv.x += a.x + b.x; xv.y += a.y + b.y; xv.z += a.z + b.z; xv.w += a.w + b.w;
            if (pbias) {
                float4 c = reinterpret_cast<const float4*>(pbias)[tid];
                xv.x += c.x; xv.y += c.y; xv.z += c.z; xv.w += c.w;
            }
            reinterpret_cast<float4*>(X + (size_t)row * DMOD)[tid] = xv;
        }
    }
    float s = xv.x + xv.y + xv.z + xv.w;
    red[tid] = s; __syncthreads();
    for (int o = 128; o > 0; o >>= 1) { if (tid < o) red[tid] += red[tid + o]; __syncthreads(); }
    float mu = red[0] * (1.0f / DMOD); __syncthreads();
    float v = 0.f;
    if (tid < 192) {
        float a = xv.x - mu, b = xv.y - mu, c = xv.z - mu, d = xv.w - mu;
        v = a * a + b * b + c * c + d * d;
    }
    red[tid] = v; __syncthreads();
    for (int o = 128; o > 0; o >>= 1) { if (tid < o) red[tid] += red[tid + o]; __syncthreads(); }
    float rstd = rsqrtf(red[0] * (1.0f / DMOD) + 1e-5f);
    if (tid < 192) {
        float4 wv = reinterpret_cast<const float4*>(w)[tid];
        float4 bv = reinterpret_cast<const float4*>(bvec)[tid];
        float y[4];
        y[0] = (xv.x - mu) * rstd * wv.x + bv.x;
        y[1] = (xv.y - mu) * rstd * wv.y + bv.y;
        y[2] = (xv.z - mu) * rstd * wv.z + bv.z;
        y[3] = (xv.w - mu) * rstd * wv.w + bv.w;
        __nv_bfloat16 hb[4], lb[4];
        #pragma unroll
        for (int q = 0; q < 4; q++) split2(y[q], hb[q], lb[q]);
        size_t off = (size_t)row * DMOD + tid * 4;
        *reinterpret_cast<uint2*>(Yh + off) = *reinterpret_cast<uint2*>(hb);
        *reinterpret_cast<uint2*>(Yl + off) = *reinterpret_cast<uint2*>(lb);
    }
}

// ---------------- GEMM: pre-split bf16, cp.async 2-stage, WMMA 3-term ----------------
// MINB = min blocks per SM (occupancy/reg cap). Split-K via gridDim.z; C offset z*M*ldc.
#define EP_BIAS 1
#define EP_GELU 2
#define EP_RES  4

__device__ __forceinline__ float gelu_exact(float x) {
    return 0.5f * x * (1.0f + erff(x * 0.70710678118654752f));
}

template<int EP, bool BCOL, bool NG, int TN, bool WH, int MINB>
__global__ void __launch_bounds__(256, MINB)
gemm_tc(const __nv_bfloat16* __restrict__ Ah_g, const __nv_bfloat16* __restrict__ Al_g,
        const __nv_bfloat16* __restrict__ Bh_g, const __nv_bfloat16* __restrict__ Bl_g,
        const float* __restrict__ bias, const float* __restrict__ res,
        float* __restrict__ C, __nv_bfloat16* __restrict__ Chi, __nv_bfloat16* __restrict__ Clo,
        int M, int N, int K, int lda, int ldb, int ldc) {
    constexpr int ALD = 40;
    constexpr int BLD = BCOL ? 40 : (TN + 8);
    constexpr int ABYTES = 128 * ALD * 2;
    constexpr int BBYTES = BCOL ? (TN * 40 * 2) : (32 * BLD * 2);
    constexpr int STAGEB = 2 * (ABYTES + BBYTES);
    constexpr int NJ = TN / 32;

    extern __shared__ char smem[];
    uint32_t sbase = smem_u32(smem);

    int tid = threadIdx.x, lane = tid & 31, wid = tid >> 5;
    int warp_m = wid & 3, warp_n = wid >> 2;
    int bm, bn;
    if (BCOL) { bm = blockIdx.x * 128; bn = blockIdx.y * TN; }
    else      { bm = blockIdx.y * 128; bn = blockIdx.x * TN; }
    int kbase = blockIdx.z * K;
    int nch = K >> 5;

    wmma::fragment<wmma::accumulator, 16, 16, 16, float> acc[2][NJ];
    #pragma unroll
    for (int i = 0; i < 2; i++)
        #pragma unroll
        for (int j = 0; j < NJ; j++) wmma::fill_fragment(acc[i][j], 0.f);

    auto load_stage = [&](int s, int c) {
        int k0 = kbase + c * 32;
        uint32_t abase = sbase + s * STAGEB;
        #pragma unroll
        for (int hn = 0; hn < 2; hn++) {
            const __nv_bfloat16* g = hn ? Al_g : Ah_g;
            uint32_t db = abase + hn * ABYTES;
            #pragma unroll
            for (int i = 0; i < 2; i++) {
                int cid = tid + i * 256;
                int r = cid >> 2, seg = cid & 3;
                cpa16(db + (uint32_t)(r * ALD + seg * 8) * 2,
                      g + (size_t)(bm + r) * lda + k0 + seg * 8);
            }
        }
        uint32_t bbase = abase + 2 * ABYTES;
        if (BCOL) {
            constexpr int NITB = (TN * 4) / 256;
            #pragma unroll
            for (int hn = 0; hn < 2; hn++) {
                const __nv_bfloat16* g = hn ? Bl_g : Bh_g;
                uint32_t db = bbase + hn * BBYTES;
                #pragma unroll
                for (int i = 0; i < NITB; i++) {
                    int cid = tid + i * 256;
                    int r = cid >> 2, seg = cid & 3;
                    int gn = bn + r;
                    uint32_t d = db + (uint32_t)(r * 40 + seg * 8) * 2;
                    if (!NG || gn < N)
                        cpa16(d, g + (size_t)gn * ldb + k0 + seg * 8);
                    else
                        *reinterpret_cast<uint4*>(smem + (d - sbase)) = make_uint4(0, 0, 0, 0);
                }
            }
        } else {
            constexpr int CH = TN / 8;
            constexpr int NIT = (32 * CH) / 256;
            #pragma unroll
            for (int hn = 0; hn < 2; hn++) {
                const __nv_bfloat16* g = hn ? Bl_g : Bh_g;
                uint32_t db = bbase + hn * BBYTES;
                #pragma unroll
                for (int i = 0; i < NIT; i++) {
                    int cid = tid + i * 256;
                    int kr = cid / CH, seg = cid % CH;
                    cpa16(db + (uint32_t)(kr * BLD + seg * 8) * 2,
                          g + (size_t)(k0 + kr) * ldb + bn + seg * 8);
                }
            }
        }
        CP_COMMIT();
    };

    auto do_mma = [&](int s) {
        char* base = smem + s * STAGEB;
        __nv_bfloat16* Ah = reinterpret_cast<__nv_bfloat16*>(base);
        __nv_bfloat16* Al = reinterpret_cast<__nv_bfloat16*>(base + ABYTES);
        __nv_bfloat16* Bh = reinterpret_cast<__nv_bfloat16*>(base + 2 * ABYTES);
        __nv_bfloat16* Bl = reinterpret_cast<__nv_bfloat16*>(base + 2 * ABYTES + BBYTES);
        #pragma unroll
        for (int kk = 0; kk < 2; kk++) {
            wmma::fragment<wmma::matrix_a, 16, 16, 16, __nv_bfloat16, wmma::row_major> ah[2], al[2];
            #pragma unroll
            for (int i = 0; i < 2; i++) {
                wmma::load_matrix_sync(ah[i], Ah + (warp_m * 32 + i * 16) * ALD + kk * 16, ALD);
                wmma::load_matrix_sync(al[i], Al + (warp_m * 32 + i * 16) * ALD + kk * 16, ALD);
            }
            #pragma unroll
            for (int j = 0; j < NJ; j++) {
                if (BCOL) {
                    wmma::fragment<wmma::matrix_b, 16, 16, 16, __nv_bfloat16, wmma::col_major> bh, bl;
                    wmma::load_matrix_sync(bh, Bh + (warp_n * (TN / 2) + j * 16) * 40 + kk * 16, 40);
                    wmma::load_matrix_sync(bl, Bl + (warp_n * (TN / 2) + j * 16) * 40 + kk * 16, 40);
                    #pragma unroll
                    for (int i = 0; i < 2; i++) {
                        wmma::mma_sync(acc[i][j], ah[i], bh, acc[i][j]);
                        wmma::mma_sync(acc[i][j], ah[i], bl, acc[i][j]);
                        wmma::mma_sync(acc[i][j], al[i], bh, acc[i][j]);
                    }
                } else {
                    wmma::fragment<wmma::matrix_b, 16, 16, 16, __nv_bfloat16, wmma::row_major> bh, bl;
                    wmma::load_matrix_sync(bh, Bh + (kk * 16) * BLD + warp_n * (TN / 2) + j * 16, BLD);
                    wmma::load_matrix_sync(bl, Bl + (kk * 16) * BLD + warp_n * (TN / 2) + j * 16, BLD);
                    #pragma unroll
                    for (int i = 0; i < 2; i++) {
                        wmma::mma_sync(acc[i][j], ah[i], bh, acc[i][j]);
                        wmma::mma_sync(acc[i][j], ah[i], bl, acc[i][j]);
                        wmma::mma_sync(acc[i][j], al[i], bh, acc[i][j]);
                    }
                }
            }
        }
    };

    load_stage(0, 0);
    load_stage(1, 1);
    for (int c = 0; c < nch; c++) {
        CP_WAIT1();
        __syncthreads();
        do_mma(c & 1);
        __syncthreads();
        if (c + 2 < nch) load_stage(c & 1, c + 2);
        else CP_COMMIT();
    }

    // vectorized epilogue (NG path stays scalar: ldc may be odd -> no float4)
    size_t coff = (size_t)blockIdx.z * M * ldc;
    float* stg = reinterpret_cast<float*>(smem) + wid * (16 * 20);
    int r = lane >> 1, cb = (lane & 1) * 8;
    #pragma unroll
    for (int i = 0; i < 2; i++) {
        #pragma unroll
        for (int j = 0; j < NJ; j++) {
            wmma::store_matrix_sync(stg, acc[i][j], 20, wmma::mem_row_major);
            __syncwarp();
            int m = bm + warp_m * 32 + i * 16 + r;
            int n0 = bn + warp_n * (TN / 2) + j * 16 + cb;
            float v[8];
            #pragma unroll
            for (int q = 0; q < 8; q++) v[q] = stg[r * 20 + cb + q];
            if (EP & EP_BIAS) {
                float4 b0 = *reinterpret_cast<const float4*>(bias + n0);
                float4 b1 = *reinterpret_cast<const float4*>(bias + n0 + 4);
                v[0]+=b0.x; v[1]+=b0.y; v[2]+=b0.z; v[3]+=b0.w;
                v[4]+=b1.x; v[5]+=b1.y; v[6]+=b1.z; v[7]+=b1.w;
            }
            if (EP & EP_GELU) {
                #pragma unroll
                for (int q = 0; q < 8; q++) v[q] = gelu_exact(v[q]);
            }
            if (EP & EP_RES) {
                const float* rp = res + (size_t)m * ldc + n0;
                float4 r0 = *reinterpret_cast<const float4*>(rp);
                float4 r1 = *reinterpret_cast<const float4*>(rp + 4);
                v[0]+=r0.x; v[1]+=r0.y; v[2]+=r0.z; v[3]+=r0.w;
                v[4]+=r1.x; v[5]+=r1.y; v[6]+=r1.z; v[7]+=r1.w;
            }
            if (WH) {
                __nv_bfloat16 hb[8], lb[8];
                #pragma unroll
                for (int q = 0; q < 8; q++) split2(v[q], hb[q], lb[q]);
                *reinterpret_cast<uint4*>(Chi + (size_t)m * ldc + n0) = *reinterpret_cast<uint4*>(hb);
                *reinterpret_cast<uint4*>(Clo + (size_t)m * ldc + n0) = *reinterpret_cast<uint4*>(lb);
            } else if (NG) {
                #pragma unroll
                for (int q = 0; q < 8; q++)
                    if (n0 + q < N) C[coff + (size_t)m * ldc + n0 + q] = v[q];
            } else {
                float* cp = C + coff + (size_t)m * ldc + n0;
                *reinterpret_cast<float4*>(cp)     = make_float4(v[0], v[1], v[2], v[3]);
                *reinterpret_cast<float4*>(cp + 4) = make_float4(v[4], v[5], v[6], v[7]);
            }
            __syncwarp();
        }
    }
}

// ---------------- WMMA flash attention (bf16 3-term, fp32 softmax) ----------------
#define KLD 72
#define SLD 68
#define A_QH 0
#define A_QL (A_QH + 64*KLD*2)
#define A_KH (A_QL + 64*KLD*2)
#define A_KL (A_KH + 64*KLD*2)
#define A_VH (A_KL + 64*KLD*2)
#define A_VL (A_VH + 64*KLD*2)
#define A_PH (A_VL + 64*KLD*2)
#define A_PL (A_PH + 64*KLD*2)
#define A_S  (A_PL + 64*KLD*2)
#define A_O  (A_S + 64*SLD*4)
#define A_M  (A_O + 64*SLD*4)
#define A_L  (A_M + 64*4)
#define A_SC (A_L + 64*4)
#define A_MS (A_SC + 64*4)
#define ATT_SMEM (A_MS + 64*4)

__global__ void __launch_bounds__(256)
attn_kernel(const __nv_bfloat16* __restrict__ QKVh, const __nv_bfloat16* __restrict__ QKVl,
            const int* __restrict__ amask,
            __nv_bfloat16* __restrict__ Ohg, __nv_bfloat16* __restrict__ Olg) {
    extern __shared__ char asmem[];
    __nv_bfloat16* Qh = reinterpret_cast<__nv_bfloat16*>(asmem + A_QH);
    __nv_bfloat16* Ql = reinterpret_cast<__nv_bfloat16*>(asmem + A_QL);
    __nv_bfloat16* Kh = reinterpret_cast<__nv_bfloat16*>(asmem + A_KH);
    __nv_bfloat16* Kl = reinterpret_cast<__nv_bfloat16*>(asmem + A_KL);
    __nv_bfloat16* Vh = reinterpret_cast<__nv_bfloat16*>(asmem + A_VH);
    __nv_bfloat16* Vl = reinterpret_cast<__nv_bfloat16*>(asmem + A_VL);
    __nv_bfloat16* Ph = reinterpret_cast<__nv_bfloat16*>(asmem + A_PH);
    __nv_bfloat16* Pl = reinterpret_cast<__nv_bfloat16*>(asmem + A_PL);
    float* S    = reinterpret_cast<float*>(asmem + A_S);
    float* O    = reinterpret_cast<float*>(asmem + A_O);
    float* sm_m = reinterpret_cast<float*>(asmem + A_M);
    float* sm_l = reinterpret_cast<float*>(asmem + A_L);
    float* sm_sc= reinterpret_cast<float*>(asmem + A_SC);
    int*   msk  = reinterpret_cast<int*>(asmem + A_MS);

    int b = blockIdx.z, hh = blockIdx.y;
    int qt = (SEQ / 64 - 1) - blockIdx.x;
    int q0 = qt * 64;
    int tid = threadIdx.x, wid = tid >> 5;
    int wr = wid & 3, wc = wid >> 2;

    for (int idx = tid; idx < 64 * 16; idx += 256) {
        int i = idx >> 4, d4 = idx & 15;
        size_t ga = (size_t)(b * SEQ + q0 + i) * QKVN + hh * DKH + d4 * 4;
        *reinterpret_cast<uint2*>(&Qh[i * KLD + d4 * 4]) = *reinterpret_cast<const uint2*>(&QKVh[ga]);
        *reinterpret_cast<uint2*>(&Ql[i * KLD + d4 * 4]) = *reinterpret_cast<const uint2*>(&QKVl[ga]);
    }
    for (int idx = tid; idx < 64 * SLD; idx += 256) O[idx] = 0.f;
    if (tid < 64) { sm_m[tid] = -1e30f; sm_l[tid] = 0.f; }

    for (int kt = 0; kt <= qt; kt++) {
        int k0 = kt * 64;
        __syncthreads();
        for (int idx = tid; idx < 64 * 16; idx += 256) {
            int j = idx >> 4, d4 = idx & 15;
            size_t gk = (size_t)(b * SEQ + k0 + j) * QKVN + DMOD + hh * DKH + d4 * 4;
            size_t gv = gk + DMOD;
            *reinterpret_cast<uint2*>(&Kh[j * KLD + d4 * 4]) = *reinterpret_cast<const uint2*>(&QKVh[gk]);
            *reinterpret_cast<uint2*>(&Kl[j * KLD + d4 * 4]) = *reinterpret_cast<const uint2*>(&QKVl[gk]);
            *reinterpret_cast<uint2*>(&Vh[j * KLD + d4 * 4]) = *reinterpret_cast<const uint2*>(&QKVh[gv]);
            *reinterpret_cast<uint2*>(&Vl[j * KLD + d4 * 4]) = *reinterpret_cast<const uint2*>(&QKVl[gv]);
        }
        if (tid < 64) msk[tid] = amask[b * SEQ + k0 + tid];
        __syncthreads();

        {
            wmma::fragment<wmma::accumulator, 16, 16, 16, float> sacc[2];
            wmma::fill_fragment(sacc[0], 0.f);
            wmma::fill_fragment(sacc[1], 0.f);
            #pragma unroll
            for (int ks = 0; ks < 4; ks++) {
                wmma::fragment<wmma::matrix_a, 16, 16, 16, __nv_bfloat16, wmma::row_major> a_h, a_l;
                wmma::load_matrix_sync(a_h, Qh + (wr * 16) * KLD + ks * 16, KLD);
                wmma::load_matrix_sync(a_l, Ql + (wr * 16) * KLD + ks * 16, KLD);
                #pragma unroll
                for (int t = 0; t < 2; t++) {
                    wmma::fragment<wmma::matrix_b, 16, 16, 16, __nv_bfloat16, wmma::col_major> b_h, b_l;
                    wmma::load_matrix_sync(b_h, Kh + (wc * 32 + t * 16) * KLD + ks * 16, KLD);
                    wmma::load_matrix_sync(b_l, Kl + (wc * 32 + t * 16) * KLD + ks * 16, KLD);
                    wmma::mma_sync(sacc[t], a_h, b_h, sacc[t]);
                    wmma::mma_sync(sacc[t], a_h, b_l, sacc[t]);
                    wmma::mma_sync(sacc[t], a_l, b_h, sacc[t]);
                }
            }
            #pragma unroll
            for (int t = 0; t < 2; t++)
                wmma::store_matrix_sync(S + (wr * 16) * SLD + wc * 32 + t * 16, sacc[t], SLD, wmma::mem_row_major);
        }
        __syncthreads();

        {
            int row = tid >> 2, qq = tid & 3;
            float sv[16];
            float tmax = -1e30f;
            #pragma unroll
            for (int jj = 0; jj < 16; jj++) {
                int j = qq * 16 + jj;
                float s = S[row * SLD + j] * 0.125f;
                if (msk[j] == 0) s = -1e9f;
                if (kt == qt && j > row) s = -1e9f;
                sv[jj] = s;
                tmax = fmaxf(tmax, s);
            }
            tmax = fmaxf(tmax, __shfl_xor_sync(0xffffffff, tmax, 1));
            tmax = fmaxf(tmax, __shfl_xor_sync(0xffffffff, tmax, 2));
            float mold = sm_m[row];
            float newm = fmaxf(mold, tmax);
            float psum = 0.f;
            __nv_bfloat16 hb[16], lb[16];
            #pragma unroll
            for (int jj = 0; jj < 16; jj++) {
                float p = __expf(sv[jj] - newm);
                psum += p;
                split2(p, hb[jj], lb[jj]);
            }
            *reinterpret_cast<uint4*>(&Ph[row * KLD + qq * 16])     = *reinterpret_cast<uint4*>(hb);
            *reinterpret_cast<uint4*>(&Ph[row * KLD + qq * 16 + 8]) = *reinterpret_cast<uint4*>(hb + 8);
            *reinterpret_cast<uint4*>(&Pl[row * KLD + qq * 16])     = *reinterpret_cast<uint4*>(lb);
            *reinterpret_cast<uint4*>(&Pl[row * KLD + qq * 16 + 8]) = *reinterpret_cast<uint4*>(lb + 8);
            psum += __shfl_xor_sync(0xffffffff, psum, 1);
            psum += __shfl_xor_sync(0xffffffff, psum, 2);
            if (qq == 0) {
                float sc = __expf(mold - newm);
                sm_sc[row] = sc;
                sm_l[row] = sm_l[row] * sc + psum;
                sm_m[row] = newm;
            }
        }
        __syncthreads();

        {
            wmma::fragment<wmma::accumulator, 16, 16, 16, float> oacc[2];
            wmma::fill_fragment(oacc[0], 0.f);
            wmma::fill_fragment(oacc[1], 0.f);
            #pragma unroll
            for (int ks = 0; ks < 4; ks++) {
                wmma::fragment<wmma::matrix_a, 16, 16, 16, __nv_bfloat16, wmma::row_major> a_h, a_l;
                wmma::load_matrix_sync(a_h, Ph + (wr * 16) * KLD + ks * 16, KLD);
                wmma::load_matrix_sync(a_l, Pl + (wr * 16) * KLD + ks * 16, KLD);
                #pragma unroll
                for (int t = 0; t < 2; t++) {
                    wmma::fragment<wmma::matrix_b, 16, 16, 16, __nv_bfloat16, wmma::row_major> b_h, b_l;
                    wmma::load_matrix_sync(b_h, Vh + (ks * 16) * KLD + wc * 32 + t * 16, KLD);
                    wmma::load_matrix_sync(b_l, Vl + (ks * 16) * KLD + wc * 32 + t * 16, KLD);
                    wmma::mma_sync(oacc[t], a_h, b_h, oacc[t]);
                    wmma::mma_sync(oacc[t], a_h, b_l, oacc[t]);
                    wmma::mma_sync(oacc[t], a_l, b_h, oacc[t]);
                }
            }
            #pragma unroll
            for (int t = 0; t < 2; t++)
                wmma::store_matrix_sync(S + (wr * 16) * SLD + wc * 32 + t * 16, oacc[t], SLD, wmma::mem_row_major);
        }
        __syncthreads();

        for (int idx = tid; idx < 4096; idx += 256) {
            int i = idx >> 6, d = idx & 63;
            O[i * SLD + d] = O[i * SLD + d] * sm_sc[i] + S[i * SLD + d];
        }
    }
    __syncthreads();
    for (int idx = tid; idx < 1024; idx += 256) {
        int i = idx >> 4, d4 = (idx & 15) * 4;
        float inv = 1.0f / sm_l[i];
        __nv_bfloat16 hb[4], lb[4];
        #pragma unroll
        for (int q = 0; q < 4; q++)
            split2(O[i * SLD + d4 + q] * inv, hb[q], lb[q]);
        size_t off = (size_t)(b * SEQ + q0 + i) * DMOD + hh * DKH + d4;
        *reinterpret_cast<uint2*>(Ohg + off) = *reinterpret_cast<uint2*>(hb);
        *reinterpret_cast<uint2*>(Olg + off) = *reinterpret_cast<uint2*>(lb);
    }
}

// ---------------- launch ----------------
extern "C" void kernel_launch(void* const* d_in, const int* in_sizes, int n_in,
                              void* d_out, int out_size) {
    const int*   ids   = (const int*)  d_in[0];
    const int*   amask = (const int*)  d_in[1];
    const float* emb   = (const float*)d_in[2];
    const float* pe    = (const float*)d_in[3];
    const float* wq    = (const float*)d_in[4];
    const float* wk    = (const float*)d_in[5];
    const float* wv    = (const float*)d_in[6];
    const float* wo    = (const float*)d_in[7];
    const float* ln1w  = (const float*)d_in[8];
    const float* ln1b  = (const float*)d_in[9];
    const float* ln2w  = (const float*)d_in[10];
    const float* ln2b  = (const float*)d_in[11];
    const float* w1    = (const float*)d_in[12];
    const float* b1    = (const float*)d_in[13];
    const float* w2    = (const float*)d_in[14];
    const float* b2    = (const float*)d_in[15];
    const float* lnfw  = (const float*)d_in[16];
    const float* lnfb  = (const float*)d_in[17];
    float* out = (float*)d_out;

    float *x, *part;
    __nv_bfloat16 *qkvh, *qkvl, *h_h, *h_l, *att_h, *att_l, *ff_h, *ff_l;
    __nv_bfloat16 *wqkv_h, *wqkv_l, *wo_h, *wo_l, *w1_h, *w1_l, *w2_h, *w2_l, *emb_h, *emb_l;
    cudaGetSymbolAddress((void**)&x,     g_x);
    cudaGetSymbolAddress((void**)&part,  g_part);
    cudaGetSymbolAddress((void**)&qkvh,  g_qkvh);  cudaGetSymbolAddress((void**)&qkvl,  g_qkvl);
    cudaGetSymbolAddress((void**)&h_h,   g_h_h);   cudaGetSymbolAddress((void**)&h_l,   g_h_l);
    cudaGetSymbolAddress((void**)&att_h, g_att_h); cudaGetSymbolAddress((void**)&att_l, g_att_l);
    cudaGetSymbolAddress((void**)&ff_h,  g_ff_h);  cudaGetSymbolAddress((void**)&ff_l,  g_ff_l);
    cudaGetSymbolAddress((void**)&wqkv_h, g_wqkv_h); cudaGetSymbolAddress((void**)&wqkv_l, g_wqkv_l);
    cudaGetSymbolAddress((void**)&wo_h,  g_wo_h);  cudaGetSymbolAddress((void**)&wo_l,  g_wo_l);
    cudaGetSymbolAddress((void**)&w1_h,  g_w1_h);  cudaGetSymbolAddress((void**)&w1_l,  g_w1_l);
    cudaGetSymbolAddress((void**)&w2_h,  g_w2_h);  cudaGetSymbolAddress((void**)&w2_l,  g_w2_l);
    cudaGetSymbolAddress((void**)&emb_h, g_emb_h); cudaGetSymbolAddress((void**)&emb_l, g_emb_l);

    const int SM_T128 = 2 * (2 * (128 * 40 * 2) + 2 * (32 * 136 * 2));   // 75776
    const int SM_T64  = 2 * (2 * (128 * 40 * 2) + 2 * (32 * 72 * 2));    // 59392
    const int SM_COL  = 2 * (2 * (128 * 40 * 2) + 2 * (128 * 40 * 2));   // 81920

    cudaFuncSetAttribute(gemm_tc<0, false, false, 128, true, 2>,                 cudaFuncAttributeMaxDynamicSharedMemorySize, SM_T128);
    cudaFuncSetAttribute(gemm_tc<0, false, false, 64, false, 3>,                 cudaFuncAttributeMaxDynamicSharedMemorySize, SM_T64);
    cudaFuncSetAttribute(gemm_tc<EP_BIAS | EP_GELU, false, false, 128, true, 2>, cudaFuncAttributeMaxDynamicSharedMemorySize, SM_T128);
    cudaFuncSetAttribute(gemm_tc<0, true, true, 128, false, 2>,                  cudaFuncAttributeMaxDynamicSharedMemorySize, SM_COL);
    cudaFuncSetAttribute(attn_kernel, cudaFuncAttributeMaxDynamicSharedMemorySize, ATT_SMEM);

    split_all_kernel<<<(N_SPLIT_TOT + 255) / 256, 256>>>(
        wq, wk, wv, wo, w1, w2, emb,
        wqkv_h, wqkv_l, wo_h, wo_l, w1_h, w1_l, w2_h, w2_l, emb_h, emb_l);
    { int n = MTOK * DMOD; embed_kernel<<<(n + 255) / 256, 256>>>(ids, emb, pe, x); }

    dim3 gQKV(QKVN / 128, MTOK / 128);
    dim3 gD64S(DMOD / 64, MTOK / 128, 2);   // split-K=2 grids
    dim3 gF(FFD / 128, MTOK / 128);
    float* p1 = part + MTOK * DMOD;

    for (int l = 0; l < LNUM; l++) {
        // LN1: plain for layer 0; fused with previous layer's FF2 partials (+b2) otherwise
        if (l == 0)
            ln_kernel<<<MTOK, 256>>>(x, nullptr, nullptr, nullptr,
                                     ln1w, ln1b, h_h, h_l);
        else
            ln_kernel<<<MTOK, 256>>>(x, part, p1, b2 + (size_t)(l - 1) * DMOD,
                                     ln1w + l * DMOD, ln1b + l * DMOD, h_h, h_l);

        gemm_tc<0, false, false, 128, true, 2><<<gQKV, 256, SM_T128>>>(
            h_h, h_l, wqkv_h + (size_t)l * DMOD * QKVN, wqkv_l + (size_t)l * DMOD * QKVN,
            nullptr, nullptr, nullptr, qkvh, qkvl, MTOK, QKVN, DMOD, DMOD, QKVN, QKVN);

        attn_kernel<<<dim3(SEQ / 64, HNUM, BAT), 256, ATT_SMEM>>>(qkvh, qkvl, amask, att_h, att_l);

        // WO split-K=2 -> partials
        gemm_tc<0, false, false, 64, false, 3><<<gD64S, 256, SM_T64>>>(
            att_h, att_l, wo_h + (size_t)l * DMOD * DMOD, wo_l + (size_t)l * DMOD * DMOD,
            nullptr, nullptr, part, nullptr, nullptr, MTOK, DMOD, DMOD / 2, DMOD, DMOD, DMOD);

        // LN2 fused with WO partials
        ln_kernel<<<MTOK, 256>>>(x, part, p1, nullptr,
                                 ln2w + l * DMOD, ln2b + l * DMOD, h_h, h_l);

        gemm_tc<EP_BIAS | EP_GELU, false, false, 128, true, 2><<<gF, 256, SM_T128>>>(
            h_h, h_l, w1_h + (size_t)l * DMOD * FFD, w1_l + (size_t)l * DMOD * FFD,
            b1 + (size_t)l * FFD, nullptr, nullptr, ff_h, ff_l, MTOK, FFD, DMOD, DMOD, FFD, FFD);

        // FF2 split-K=2 -> partials (consumed by next LN1 or final LN)
        gemm_tc<0, false, false, 64, false, 3><<<gD64S, 256, SM_T64>>>(
            ff_h, ff_l, w2_h + (size_t)l * FFD * DMOD, w2_l + (size_t)l * FFD * DMOD,
            nullptr, nullptr, part, nullptr, nullptr, MTOK, DMOD, FFD / 2, FFD, DMOD, DMOD);
    }

    // final LN fused with last FF2 partials (+b2 of layer 5)
    ln_kernel<<<MTOK, 256>>>(x, part, p1, b2 + (size_t)(LNUM - 1) * DMOD,
                             lnfw, lnfb, h_h, h_l);

    dim3 gV(MTOK / 128, (VOC + 127) / 128);
    gemm_tc<0, true, true, 128, false, 2><<<gV, 256, SM_COL>>>(
        h_h, h_l, emb_h, emb_l, nullptr, nullptr, out, nullptr, nullptr, MTOK, VOC, DMOD, DMOD, DMOD, VOC);
}

// round 16
// speedup vs baseline: 1.6891x; 1.2138x over previous
#include <cuda_runtime.h>
#include <cuda_bf16.h>
#include <cuda_fp16.h>
#include <mma.h>
#include <math.h>
#include <cstdint>
#include <cstddef>
using namespace nvcuda;

#define LNUM 6
#define DMOD 768
#define HNUM 12
#define DKH  64
#define FFD  3072
#define VOC  50257
#define SEQ  1024
#define BAT  2
#define MTOK (BAT*SEQ)   // 2048
#define QKVN (3*DMOD)    // 2304

// ---------------- device scratch ----------------
__device__ float g_x  [MTOK*DMOD];
__device__ float g_part[2*MTOK*DMOD];     // split-K partials
__device__ __half g_hf [MTOK*DMOD];       // fp16 h for lm_head
__device__ __half g_embf[VOC*DMOD];       // fp16 emb for lm_head
__device__ __nv_bfloat16 g_qkvh[MTOK*QKVN], g_qkvl[MTOK*QKVN];
__device__ __nv_bfloat16 g_h_h [MTOK*DMOD],  g_h_l [MTOK*DMOD];
__device__ __nv_bfloat16 g_att_h[MTOK*DMOD], g_att_l[MTOK*DMOD];
__device__ __nv_bfloat16 g_ff_h[MTOK*FFD],   g_ff_l[MTOK*FFD];
__device__ __nv_bfloat16 g_wqkv_h[LNUM*DMOD*QKVN], g_wqkv_l[LNUM*DMOD*QKVN];
__device__ __nv_bfloat16 g_wo_h [LNUM*DMOD*DMOD],  g_wo_l [LNUM*DMOD*DMOD];
__device__ __nv_bfloat16 g_w1_h [LNUM*DMOD*FFD],   g_w1_l [LNUM*DMOD*FFD];
__device__ __nv_bfloat16 g_w2_h [LNUM*FFD*DMOD],   g_w2_l [LNUM*FFD*DMOD];

// ---------------- helpers ----------------
__device__ __forceinline__ uint32_t smem_u32(const void* p) {
    uint32_t a;
    asm("{ .reg .u64 t; cvta.to.shared.u64 t, %1; cvt.u32.u64 %0, t; }" : "=r"(a) : "l"(p));
    return a;
}
__device__ __forceinline__ void cpa16(uint32_t dst, const void* src) {
    asm volatile("cp.async.cg.shared.global [%0], [%1], 16;" :: "r"(dst), "l"(src));
}
#define CP_COMMIT() asm volatile("cp.async.commit_group;" ::: "memory")
#define CP_WAIT1()  asm volatile("cp.async.wait_group 1;" ::: "memory")

__device__ __forceinline__ void split2(float v, __nv_bfloat16& hi, __nv_bfloat16& lo) {
    hi = __float2bfloat16(v);
    lo = __float2bfloat16(v - __bfloat162float(hi));
}

// ---------------- merged prepass split kernel ----------------
#define N_QKV (LNUM*DMOD*QKVN)
#define N_WO  (LNUM*DMOD*DMOD)
#define N_W1  (LNUM*DMOD*FFD)
#define N_W2  (LNUM*FFD*DMOD)
#define N_EMB (VOC*DMOD)
#define N_SPLIT_TOT (N_QKV + N_WO + N_W1 + N_W2 + N_EMB)

__global__ void split_all_kernel(const float* __restrict__ wq, const float* __restrict__ wk,
                                 const float* __restrict__ wv, const float* __restrict__ wo,
                                 const float* __restrict__ w1, const float* __restrict__ w2,
                                 const float* __restrict__ emb,
                                 __nv_bfloat16* __restrict__ qkv_h, __nv_bfloat16* __restrict__ qkv_l,
                                 __nv_bfloat16* __restrict__ wo_h,  __nv_bfloat16* __restrict__ wo_l,
                                 __nv_bfloat16* __restrict__ w1_h,  __nv_bfloat16* __restrict__ w1_l,
                                 __nv_bfloat16* __restrict__ w2_h,  __nv_bfloat16* __restrict__ w2_l,
                                 __half* __restrict__ emb_f) {
    int i = blockIdx.x * blockDim.x + threadIdx.x;
    if (i >= N_SPLIT_TOT) return;
    if (i < N_QKV) {
        int l = i / (DMOD * QKVN);
        int rem = i % (DMOD * QKVN);
        int k = rem / QKVN, j = rem % QKVN;
        const float* s = (j < DMOD) ? wq : (j < 2 * DMOD) ? wk : wv;
        float v = s[(size_t)l * DMOD * DMOD + (size_t)k * DMOD + (j % DMOD)];
        split2(v, qkv_h[i], qkv_l[i]);
        return;
    }
    i -= N_QKV;
    if (i < N_WO)  { split2(wo[i],  wo_h[i],  wo_l[i]);  return; }
    i -= N_WO;
    if (i < N_W1)  { split2(w1[i],  w1_h[i],  w1_l[i]);  return; }
    i -= N_W1;
    if (i < N_W2)  { split2(w2[i],  w2_h[i],  w2_l[i]);  return; }
    i -= N_W2;
    emb_f[i] = __float2half(emb[i]);
}

// ---------------- embedding ----------------
__global__ void embed_kernel(const int* __restrict__ ids, const float* __restrict__ emb,
                             const float* __restrict__ pe, float* __restrict__ X) {
    int i = blockIdx.x * blockDim.x + threadIdx.x;
    if (i >= MTOK * DMOD) return;
    int d = i % DMOD, t = i / DMOD, s = t % SEQ;
    X[i] = emb[(size_t)ids[t] * DMOD + d] + pe[s * DMOD + d];
}

// ---------------- fused (split-K reduce) + layernorm ----------------
// If p0: x_row += p0+p1(+pbias) first. Writes bf16 hi/lo if Yh, fp16 if Yf.
__global__ void ln_kernel(float* __restrict__ X,
                          const float* __restrict__ p0, const float* __restrict__ p1,
                          const float* __restrict__ pbias,
                          const float* __restrict__ w, const float* __restrict__ bvec,
                          __nv_bfloat16* __restrict__ Yh, __nv_bfloat16* __restrict__ Yl,
                          __half* __restrict__ Yf) {
    __shared__ float red[256];
    int row = blockIdx.x, tid = threadIdx.x;
    float4 xv = make_float4(0.f, 0.f, 0.f, 0.f);
    if (tid < 192) {
        xv = reinterpret_cast<const float4*>(X + (size_t)row * DMOD)[tid];
        if (p0) {
            float4 a = reinterpret_cast<const float4*>(p0 + (size_t)row * DMOD)[tid];
            float4 b = reinterpret_cast<const float4*>(p1 + (size_t)row * DMOD)[tid];
            xv.x += a.x + b.x; xv.y += a.y + b.y; xv.z += a.z + b.z; xv.w += a.w + b.w;
            if (pbias) {
                float4 c = reinterpret_cast<const float4*>(pbias)[tid];
                xv.x += c.x; xv.y += c.y; xv.z += c.z; xv.w += c.w;
            }
            reinterpret_cast<float4*>(X + (size_t)row * DMOD)[tid] = xv;
        }
    }
    float s = xv.x + xv.y + xv.z + xv.w;
    red[tid] = s; __syncthreads();
    for (int o = 128; o > 0; o >>= 1) { if (tid < o) red[tid] += red[tid + o]; __syncthreads(); }
    float mu = red[0] * (1.0f / DMOD); __syncthreads();
    float v = 0.f;
    if (tid < 192) {
        float a = xv.x - mu, b = xv.y - mu, c = xv.z - mu, d = xv.w - mu;
        v = a * a + b * b + c * c + d * d;
    }
    red[tid] = v; __syncthreads();
    for (int o = 128; o > 0; o >>= 1) { if (tid < o) red[tid] += red[tid + o]; __syncthreads(); }
    float rstd = rsqrtf(red[0] * (1.0f / DMOD) + 1e-5f);
    if (tid < 192) {
        float4 wv = reinterpret_cast<const float4*>(w)[tid];
        float4 bv = reinterpret_cast<const float4*>(bvec)[tid];
        float y[4];
        y[0] = (xv.x - mu) * rstd * wv.x + bv.x;
        y[1] = (xv.y - mu) * rstd * wv.y + bv.y;
        y[2] = (xv.z - mu) * rstd * wv.z + bv.z;
        y[3] = (xv.w - mu) * rstd * wv.w + bv.w;
        size_t off = (size_t)row * DMOD + tid * 4;
        if (Yh) {
            __nv_bfloat16 hb[4], lb[4];
            #pragma unroll
            for (int q = 0; q < 4; q++) split2(y[q], hb[q], lb[q]);
            *reinterpret_cast<uint2*>(Yh + off) = *reinterpret_cast<uint2*>(hb);
            *reinterpret_cast<uint2*>(Yl + off) = *reinterpret_cast<uint2*>(lb);
        }
        if (Yf) {
            __half hf[4];
            #pragma unroll
            for (int q = 0; q < 4; q++) hf[q] = __float2half(y[q]);
            *reinterpret_cast<uint2*>(Yf + off) = *reinterpret_cast<uint2*>(hf);
        }
    }
}

// ---------------- GEMM: pre-split bf16, cp.async 2-stage, WMMA 3-term ----------------
#define EP_BIAS 1
#define EP_GELU 2
#define EP_RES  4

__device__ __forceinline__ float gelu_exact(float x) {
    return 0.5f * x * (1.0f + erff(x * 0.70710678118654752f));
}

template<int EP, bool NG, int TN, bool WH, int MINB>
__global__ void __launch_bounds__(256, MINB)
gemm_tc(const __nv_bfloat16* __restrict__ Ah_g, const __nv_bfloat16* __restrict__ Al_g,
        const __nv_bfloat16* __restrict__ Bh_g, const __nv_bfloat16* __restrict__ Bl_g,
        const float* __restrict__ bias, const float* __restrict__ res,
        float* __restrict__ C, __nv_bfloat16* __restrict__ Chi, __nv_bfloat16* __restrict__ Clo,
        int M, int N, int K, int lda, int ldb, int ldc) {
    constexpr int ALD = 40;
    constexpr int BLD = TN + 8;
    constexpr int ABYTES = 128 * ALD * 2;
    constexpr int BBYTES = 32 * BLD * 2;
    constexpr int STAGEB = 2 * (ABYTES + BBYTES);
    constexpr int NJ = TN / 32;

    extern __shared__ char smem[];
    uint32_t sbase = smem_u32(smem);

    int tid = threadIdx.x, lane = tid & 31, wid = tid >> 5;
    int warp_m = wid & 3, warp_n = wid >> 2;
    int bm = blockIdx.y * 128, bn = blockIdx.x * TN;
    int kbase = blockIdx.z * K;
    int nch = K >> 5;

    wmma::fragment<wmma::accumulator, 16, 16, 16, float> acc[2][NJ];
    #pragma unroll
    for (int i = 0; i < 2; i++)
        #pragma unroll
        for (int j = 0; j < NJ; j++) wmma::fill_fragment(acc[i][j], 0.f);

    auto load_stage = [&](int s, int c) {
        int k0 = kbase + c * 32;
        uint32_t abase = sbase + s * STAGEB;
        #pragma unroll
        for (int hn = 0; hn < 2; hn++) {
            const __nv_bfloat16* g = hn ? Al_g : Ah_g;
            uint32_t db = abase + hn * ABYTES;
            #pragma unroll
            for (int i = 0; i < 2; i++) {
                int cid = tid + i * 256;
                int r = cid >> 2, seg = cid & 3;
                cpa16(db + (uint32_t)(r * ALD + seg * 8) * 2,
                      g + (size_t)(bm + r) * lda + k0 + seg * 8);
            }
        }
        uint32_t bbase = abase + 2 * ABYTES;
        constexpr int CH = TN / 8;
        constexpr int NIT = (32 * CH) / 256;
        #pragma unroll
        for (int hn = 0; hn < 2; hn++) {
            const __nv_bfloat16* g = hn ? Bl_g : Bh_g;
            uint32_t db = bbase + hn * BBYTES;
            #pragma unroll
            for (int i = 0; i < NIT; i++) {
                int cid = tid + i * 256;
                int kr = cid / CH, seg = cid % CH;
                cpa16(db + (uint32_t)(kr * BLD + seg * 8) * 2,
                      g + (size_t)(k0 + kr) * ldb + bn + seg * 8);
            }
        }
        CP_COMMIT();
    };

    auto do_mma = [&](int s) {
        char* base = smem + s * STAGEB;
        __nv_bfloat16* Ah = reinterpret_cast<__nv_bfloat16*>(base);
        __nv_bfloat16* Al = reinterpret_cast<__nv_bfloat16*>(base + ABYTES);
        __nv_bfloat16* Bh = reinterpret_cast<__nv_bfloat16*>(base + 2 * ABYTES);
        __nv_bfloat16* Bl = reinterpret_cast<__nv_bfloat16*>(base + 2 * ABYTES + BBYTES);
        #pragma unroll
        for (int kk = 0; kk < 2; kk++) {
            wmma::fragment<wmma::matrix_a, 16, 16, 16, __nv_bfloat16, wmma::row_major> ah[2], al[2];
            #pragma unroll
            for (int i = 0; i < 2; i++) {
                wmma::load_matrix_sync(ah[i], Ah + (warp_m * 32 + i * 16) * ALD + kk * 16, ALD);
                wmma::load_matrix_sync(al[i], Al + (warp_m * 32 + i * 16) * ALD + kk * 16, ALD);
            }
            #pragma unroll
            for (int j = 0; j < NJ; j++) {
                wmma::fragment<wmma::matrix_b, 16, 16, 16, __nv_bfloat16, wmma::row_major> bh, bl;
                wmma::load_matrix_sync(bh, Bh + (kk * 16) * BLD + warp_n * (TN / 2) + j * 16, BLD);
                wmma::load_matrix_sync(bl, Bl + (kk * 16) * BLD + warp_n * (TN / 2) + j * 16, BLD);
                #pragma unroll
                for (int i = 0; i < 2; i++) {
                    wmma::mma_sync(acc[i][j], ah[i], bh, acc[i][j]);
                    wmma::mma_sync(acc[i][j], ah[i], bl, acc[i][j]);
                    wmma::mma_sync(acc[i][j], al[i], bh, acc[i][j]);
                }
            }
        }
    };

    load_stage(0, 0);
    load_stage(1, 1);
    for (int c = 0; c < nch; c++) {
        CP_WAIT1();
        __syncthreads();
        do_mma(c & 1);
        __syncthreads();
        if (c + 2 < nch) load_stage(c & 1, c + 2);
        else CP_COMMIT();
    }

    size_t coff = (size_t)blockIdx.z * M * ldc;
    float* stg = reinterpret_cast<float*>(smem) + wid * (16 * 20);
    int r = lane >> 1, cb = (lane & 1) * 8;
    #pragma unroll
    for (int i = 0; i < 2; i++) {
        #pragma unroll
        for (int j = 0; j < NJ; j++) {
            wmma::store_matrix_sync(stg, acc[i][j], 20, wmma::mem_row_major);
            __syncwarp();
            int m = bm + warp_m * 32 + i * 16 + r;
            int n0 = bn + warp_n * (TN / 2) + j * 16 + cb;
            float v[8];
            #pragma unroll
            for (int q = 0; q < 8; q++) v[q] = stg[r * 20 + cb + q];
            if (EP & EP_BIAS) {
                float4 b0 = *reinterpret_cast<const float4*>(bias + n0);
                float4 b1 = *reinterpret_cast<const float4*>(bias + n0 + 4);
                v[0]+=b0.x; v[1]+=b0.y; v[2]+=b0.z; v[3]+=b0.w;
                v[4]+=b1.x; v[5]+=b1.y; v[6]+=b1.z; v[7]+=b1.w;
            }
            if (EP & EP_GELU) {
                #pragma unroll
                for (int q = 0; q < 8; q++) v[q] = gelu_exact(v[q]);
            }
            if (EP & EP_RES) {
                const float* rp = res + (size_t)m * ldc + n0;
                float4 r0 = *reinterpret_cast<const float4*>(rp);
                float4 r1 = *reinterpret_cast<const float4*>(rp + 4);
                v[0]+=r0.x; v[1]+=r0.y; v[2]+=r0.z; v[3]+=r0.w;
                v[4]+=r1.x; v[5]+=r1.y; v[6]+=r1.z; v[7]+=r1.w;
            }
            if (WH) {
                __nv_bfloat16 hb[8], lb[8];
                #pragma unroll
                for (int q = 0; q < 8; q++) split2(v[q], hb[q], lb[q]);
                *reinterpret_cast<uint4*>(Chi + (size_t)m * ldc + n0) = *reinterpret_cast<uint4*>(hb);
                *reinterpret_cast<uint4*>(Clo + (size_t)m * ldc + n0) = *reinterpret_cast<uint4*>(lb);
            } else if (NG) {
                #pragma unroll
                for (int q = 0; q < 8; q++)
                    if (n0 + q < N) C[coff + (size_t)m * ldc + n0 + q] = v[q];
            } else {
                float* cp = C + coff + (size_t)m * ldc + n0;
                *reinterpret_cast<float4*>(cp)     = make_float4(v[0], v[1], v[2], v[3]);
                *reinterpret_cast<float4*>(cp + 4) = make_float4(v[4], v[5], v[6], v[7]);
            }
            __syncwarp();
        }
    }
}

// ---------------- lm_head: plain fp16 single-MMA GEMM, C = A @ B^T ----------------
// A [M,K] fp16 row-major; B [N,K] fp16 (emb); scalar stores (ldc odd).
#define FALD 40
#define FABYTES (128*FALD*2)
#define FSTAGEB (2*FABYTES)
#define SM_F16 (2*FSTAGEB)

__global__ void __launch_bounds__(256, 2)
gemm_f16_lmhead(const __half* __restrict__ A, const __half* __restrict__ B,
                float* __restrict__ C, int M, int N, int K, int ldb, int ldc) {
    extern __shared__ char smem[];
    uint32_t sbase = smem_u32(smem);

    int tid = threadIdx.x, lane = tid & 31, wid = tid >> 5;
    int warp_m = wid & 3, warp_n = wid >> 2;
    int bm = blockIdx.x * 128, bn = blockIdx.y * 128;   // m fastest -> L2 reuse of B
    int nch = K >> 5;

    wmma::fragment<wmma::accumulator, 16, 16, 16, float> acc[2][4];
    #pragma unroll
    for (int i = 0; i < 2; i++)
        #pragma unroll
        for (int j = 0; j < 4; j++) wmma::fill_fragment(acc[i][j], 0.f);

    auto load_stage = [&](int s, int c) {
        int k0 = c * 32;
        uint32_t abase = sbase + s * FSTAGEB;
        #pragma unroll
        for (int i = 0; i < 2; i++) {
            int cid = tid + i * 256;
            int r = cid >> 2, seg = cid & 3;
            cpa16(abase + (uint32_t)(r * FALD + seg * 8) * 2,
                  A + (size_t)(bm + r) * K + k0 + seg * 8);
        }
        uint32_t bbase = abase + FABYTES;
        #pragma unroll
        for (int i = 0; i < 2; i++) {
            int cid = tid + i * 256;
            int r = cid >> 2, seg = cid & 3;
            int gn = bn + r;
            uint32_t d = bbase + (uint32_t)(r * FALD + seg * 8) * 2;
            if (gn < N)
                cpa16(d, B + (size_t)gn * ldb + k0 + seg * 8);
            else
                *reinterpret_cast<uint4*>(smem + (d - sbase)) = make_uint4(0, 0, 0, 0);
        }
        CP_COMMIT();
    };

    auto do_mma = [&](int s) {
        char* base = smem + s * FSTAGEB;
        __half* As = reinterpret_cast<__half*>(base);
        __half* Bs = reinterpret_cast<__half*>(base + FABYTES);
        #pragma unroll
        for (int kk = 0; kk < 2; kk++) {
            wmma::fragment<wmma::matrix_a, 16, 16, 16, __half, wmma::row_major> af[2];
            #pragma unroll
            for (int i = 0; i < 2; i++)
                wmma::load_matrix_sync(af[i], As + (warp_m * 32 + i * 16) * FALD + kk * 16, FALD);
            #pragma unroll
            for (int j = 0; j < 4; j++) {
                wmma::fragment<wmma::matrix_b, 16, 16, 16, __half, wmma::col_major> bf;
                wmma::load_matrix_sync(bf, Bs + (warp_n * 64 + j * 16) * FALD + kk * 16, FALD);
                #pragma unroll
                for (int i = 0; i < 2; i++)
                    wmma::mma_sync(acc[i][j], af[i], bf, acc[i][j]);
            }
        }
    };

    load_stage(0, 0);
    load_stage(1, 1);
    for (int c = 0; c < nch; c++) {
        CP_WAIT1();
        __syncthreads();
        do_mma(c & 1);
        __syncthreads();
        if (c + 2 < nch) load_stage(c & 1, c + 2);
        else CP_COMMIT();
    }

    float* stg = reinterpret_cast<float*>(smem) + wid * (16 * 20);
    int r = lane >> 1, cb = (lane & 1) * 8;
    #pragma unroll
    for (int i = 0; i < 2; i++) {
        #pragma unroll
        for (int j = 0; j < 4; j++) {
            wmma::store_matrix_sync(stg, acc[i][j], 20, wmma::mem_row_major);
            __syncwarp();
            int m = bm + warp_m * 32 + i * 16 + r;
            int n0 = bn + warp_n * 64 + j * 16 + cb;
            #pragma unroll
            for (int q = 0; q < 8; q++)
                if (n0 + q < N) C[(size_t)m * ldc + n0 + q] = stg[r * 20 + cb + q];
            __syncwarp();
        }
    }
}

// ---------------- WMMA flash attention (bf16 3-term, fp32 softmax) ----------------
#define KLD 72
#define SLD 68
#define A_QH 0
#define A_QL (A_QH + 64*KLD*2)
#define A_KH (A_QL + 64*KLD*2)
#define A_KL (A_KH + 64*KLD*2)
#define A_VH (A_KL + 64*KLD*2)
#define A_VL (A_VH + 64*KLD*2)
#define A_PH (A_VL + 64*KLD*2)
#define A_PL (A_PH + 64*KLD*2)
#define A_S  (A_PL + 64*KLD*2)
#define A_O  (A_S + 64*SLD*4)
#define A_M  (A_O + 64*SLD*4)
#define A_L  (A_M + 64*4)
#define A_SC (A_L + 64*4)
#define A_MS (A_SC + 64*4)
#define ATT_SMEM (A_MS + 64*4)

__global__ void __launch_bounds__(256)
attn_kernel(const __nv_bfloat16* __restrict__ QKVh, const __nv_bfloat16* __restrict__ QKVl,
            const int* __restrict__ amask,
            __nv_bfloat16* __restrict__ Ohg, __nv_bfloat16* __restrict__ Olg) {
    extern __shared__ char asmem[];
    __nv_bfloat16* Qh = reinterpret_cast<__nv_bfloat16*>(asmem + A_QH);
    __nv_bfloat16* Ql = reinterpret_cast<__nv_bfloat16*>(asmem + A_QL);
    __nv_bfloat16* Kh = reinterpret_cast<__nv_bfloat16*>(asmem + A_KH);
    __nv_bfloat16* Kl = reinterpret_cast<__nv_bfloat16*>(asmem + A_KL);
    __nv_bfloat16* Vh = reinterpret_cast<__nv_bfloat16*>(asmem + A_VH);
    __nv_bfloat16* Vl = reinterpret_cast<__nv_bfloat16*>(asmem + A_VL);
    __nv_bfloat16* Ph = reinterpret_cast<__nv_bfloat16*>(asmem + A_PH);
    __nv_bfloat16* Pl = reinterpret_cast<__nv_bfloat16*>(asmem + A_PL);
    float* S    = reinterpret_cast<float*>(asmem + A_S);
    float* O    = reinterpret_cast<float*>(asmem + A_O);
    float* sm_m = reinterpret_cast<float*>(asmem + A_M);
    float* sm_l = reinterpret_cast<float*>(asmem + A_L);
    float* sm_sc= reinterpret_cast<float*>(asmem + A_SC);
    int*   msk  = reinterpret_cast<int*>(asmem + A_MS);

    int b = blockIdx.z, hh = blockIdx.y;
    int qt = (SEQ / 64 - 1) - blockIdx.x;
    int q0 = qt * 64;
    int tid = threadIdx.x, wid = tid >> 5;
    int wr = wid & 3, wc = wid >> 2;

    for (int idx = tid; idx < 64 * 16; idx += 256) {
        int i = idx >> 4, d4 = idx & 15;
        size_t ga = (size_t)(b * SEQ + q0 + i) * QKVN + hh * DKH + d4 * 4;
        *reinterpret_cast<uint2*>(&Qh[i * KLD + d4 * 4]) = *reinterpret_cast<const uint2*>(&QKVh[ga]);
        *reinterpret_cast<uint2*>(&Ql[i * KLD + d4 * 4]) = *reinterpret_cast<const uint2*>(&QKVl[ga]);
    }
    for (int idx = tid; idx < 64 * SLD; idx += 256) O[idx] = 0.f;
    if (tid < 64) { sm_m[tid] = -1e30f; sm_l[tid] = 0.f; }

    for (int kt = 0; kt <= qt; kt++) {
        int k0 = kt * 64;
        __syncthreads();
        for (int idx = tid; idx < 64 * 16; idx += 256) {
            int j = idx >> 4, d4 = idx & 15;
            size_t gk = (size_t)(b * SEQ + k0 + j) * QKVN + DMOD + hh * DKH + d4 * 4;
            size_t gv = gk + DMOD;
            *reinterpret_cast<uint2*>(&Kh[j * KLD + d4 * 4]) = *reinterpret_cast<const uint2*>(&QKVh[gk]);
            *reinterpret_cast<uint2*>(&Kl[j * KLD + d4 * 4]) = *reinterpret_cast<const uint2*>(&QKVl[gk]);
            *reinterpret_cast<uint2*>(&Vh[j * KLD + d4 * 4]) = *reinterpret_cast<const uint2*>(&QKVh[gv]);
            *reinterpret_cast<uint2*>(&Vl[j * KLD + d4 * 4]) = *reinterpret_cast<const uint2*>(&QKVl[gv]);
        }
        if (tid < 64) msk[tid] = amask[b * SEQ + k0 + tid];
        __syncthreads();

        {
            wmma::fragment<wmma::accumulator, 16, 16, 16, float> sacc[2];
            wmma::fill_fragment(sacc[0], 0.f);
            wmma::fill_fragment(sacc[1], 0.f);
            #pragma unroll
            for (int ks = 0; ks < 4; ks++) {
                wmma::fragment<wmma::matrix_a, 16, 16, 16, __nv_bfloat16, wmma::row_major> a_h, a_l;
                wmma::load_matrix_sync(a_h, Qh + (wr * 16) * KLD + ks * 16, KLD);
                wmma::load_matrix_sync(a_l, Ql + (wr * 16) * KLD + ks * 16, KLD);
                #pragma unroll
                for (int t = 0; t < 2; t++) {
                    wmma::fragment<wmma::matrix_b, 16, 16, 16, __nv_bfloat16, wmma::col_major> b_h, b_l;
                    wmma::load_matrix_sync(b_h, Kh + (wc * 32 + t * 16) * KLD + ks * 16, KLD);
                    wmma::load_matrix_sync(b_l, Kl + (wc * 32 + t * 16) * KLD + ks * 16, KLD);
                    wmma::mma_sync(sacc[t], a_h, b_h, sacc[t]);
                    wmma::mma_sync(sacc[t], a_h, b_l, sacc[t]);
                    wmma::mma_sync(sacc[t], a_l, b_h, sacc[t]);
                }
            }
            #pragma unroll
            for (int t = 0; t < 2; t++)
                wmma::store_matrix_sync(S + (wr * 16) * SLD + wc * 32 + t * 16, sacc[t], SLD, wmma::mem_row_major);
        }
        __syncthreads();

        {
            int row = tid >> 2, qq = tid & 3;
            float sv[16];
            float tmax = -1e30f;
            #pragma unroll
            for (int jj = 0; jj < 16; jj++) {
                int j = qq * 16 + jj;
                float s = S[row * SLD + j] * 0.125f;
                if (msk[j] == 0) s = -1e9f;
                if (kt == qt && j > row) s = -1e9f;
                sv[jj] = s;
                tmax = fmaxf(tmax, s);
            }
            tmax = fmaxf(tmax, __shfl_xor_sync(0xffffffff, tmax, 1));
            tmax = fmaxf(tmax, __shfl_xor_sync(0xffffffff, tmax, 2));
            float mold = sm_m[row];
            float newm = fmaxf(mold, tmax);
            float psum = 0.f;
            __nv_bfloat16 hb[16], lb[16];
            #pragma unroll
            for (int jj = 0; jj < 16; jj++) {
                float p = __expf(sv[jj] - newm);
                psum += p;
                split2(p, hb[jj], lb[jj]);
            }
            *reinterpret_cast<uint4*>(&Ph[row * KLD + qq * 16])     = *reinterpret_cast<uint4*>(hb);
            *reinterpret_cast<uint4*>(&Ph[row * KLD + qq * 16 + 8]) = *reinterpret_cast<uint4*>(hb + 8);
            *reinterpret_cast<uint4*>(&Pl[row * KLD + qq * 16])     = *reinterpret_cast<uint4*>(lb);
            *reinterpret_cast<uint4*>(&Pl[row * KLD + qq * 16 + 8]) = *reinterpret_cast<uint4*>(lb + 8);
            psum += __shfl_xor_sync(0xffffffff, psum, 1);
            psum += __shfl_xor_sync(0xffffffff, psum, 2);
            if (qq == 0) {
                float sc = __expf(mold - newm);
                sm_sc[row] = sc;
                sm_l[row] = sm_l[row] * sc + psum;
                sm_m[row] = newm;
            }
        }
        __syncthreads();

        {
            wmma::fragment<wmma::accumulator, 16, 16, 16, float> oacc[2];
            wmma::fill_fragment(oacc[0], 0.f);
            wmma::fill_fragment(oacc[1], 0.f);
            #pragma unroll
            for (int ks = 0; ks < 4; ks++) {
                wmma::fragment<wmma::matrix_a, 16, 16, 16, __nv_bfloat16, wmma::row_major> a_h, a_l;
                wmma::load_matrix_sync(a_h, Ph + (wr * 16) * KLD + ks * 16, KLD);
                wmma::load_matrix_sync(a_l, Pl + (wr * 16) * KLD + ks * 16, KLD);
                #pragma unroll
                for (int t = 0; t < 2; t++) {
                    wmma::fragment<wmma::matrix_b, 16, 16, 16, __nv_bfloat16, wmma::row_major> b_h, b_l;
                    wmma::load_matrix_sync(b_h, Vh + (ks * 16) * KLD + wc * 32 + t * 16, KLD);
                    wmma::load_matrix_sync(b_l, Vl + (ks * 16) * KLD + wc * 32 + t * 16, KLD);
                    wmma::mma_sync(oacc[t], a_h, b_h, oacc[t]);
                    wmma::mma_sync(oacc[t], a_h, b_l, oacc[t]);
                    wmma::mma_sync(oacc[t], a_l, b_h, oacc[t]);
                }
            }
            #pragma unroll
            for (int t = 0; t < 2; t++)
                wmma::store_matrix_sync(S + (wr * 16) * SLD + wc * 32 + t * 16, oacc[t], SLD, wmma::mem_row_major);
        }
        __syncthreads();

        for (int idx = tid; idx < 4096; idx += 256) {
            int i = idx >> 6, d = idx & 63;
            O[i * SLD + d] = O[i * SLD + d] * sm_sc[i] + S[i * SLD + d];
        }
    }
    __syncthreads();
    for (int idx = tid; idx < 1024; idx += 256) {
        int i = idx >> 4, d4 = (idx & 15) * 4;
        float inv = 1.0f / sm_l[i];
        __nv_bfloat16 hb[4], lb[4];
        #pragma unroll
        for (int q = 0; q < 4; q++)
            split2(O[i * SLD + d4 + q] * inv, hb[q], lb[q]);
        size_t off = (size_t)(b * SEQ + q0 + i) * DMOD + hh * DKH + d4;
        *reinterpret_cast<uint2*>(Ohg + off) = *reinterpret_cast<uint2*>(hb);
        *reinterpret_cast<uint2*>(Olg + off) = *reinterpret_cast<uint2*>(lb);
    }
}

// ---------------- launch ----------------
extern "C" void kernel_launch(void* const* d_in, const int* in_sizes, int n_in,
                              void* d_out, int out_size) {
    const int*   ids   = (const int*)  d_in[0];
    const int*   amask = (const int*)  d_in[1];
    const float* emb   = (const float*)d_in[2];
    const float* pe    = (const float*)d_in[3];
    const float* wq    = (const float*)d_in[4];
    const float* wk    = (const float*)d_in[5];
    const float* wv    = (const float*)d_in[6];
    const float* wo    = (const float*)d_in[7];
    const float* ln1w  = (const float*)d_in[8];
    const float* ln1b  = (const float*)d_in[9];
    const float* ln2w  = (const float*)d_in[10];
    const float* ln2b  = (const float*)d_in[11];
    const float* w1    = (const float*)d_in[12];
    const float* b1    = (const float*)d_in[13];
    const float* w2    = (const float*)d_in[14];
    const float* b2    = (const float*)d_in[15];
    const float* lnfw  = (const float*)d_in[16];
    const float* lnfb  = (const float*)d_in[17];
    float* out = (float*)d_out;

    float *x, *part;
    __half *hf, *embf;
    __nv_bfloat16 *qkvh, *qkvl, *h_h, *h_l, *att_h, *att_l, *ff_h, *ff_l;
    __nv_bfloat16 *wqkv_h, *wqkv_l, *wo_h, *wo_l, *w1_h, *w1_l, *w2_h, *w2_l;
    cudaGetSymbolAddress((void**)&x,     g_x);
    cudaGetSymbolAddress((void**)&part,  g_part);
    cudaGetSymbolAddress((void**)&hf,    g_hf);
    cudaGetSymbolAddress((void**)&embf,  g_embf);
    cudaGetSymbolAddress((void**)&qkvh,  g_qkvh);  cudaGetSymbolAddress((void**)&qkvl,  g_qkvl);
    cudaGetSymbolAddress((void**)&h_h,   g_h_h);   cudaGetSymbolAddress((void**)&h_l,   g_h_l);
    cudaGetSymbolAddress((void**)&att_h, g_att_h); cudaGetSymbolAddress((void**)&att_l, g_att_l);
    cudaGetSymbolAddress((void**)&ff_h,  g_ff_h);  cudaGetSymbolAddress((void**)&ff_l,  g_ff_l);
    cudaGetSymbolAddress((void**)&wqkv_h, g_wqkv_h); cudaGetSymbolAddress((void**)&wqkv_l, g_wqkv_l);
    cudaGetSymbolAddress((void**)&wo_h,  g_wo_h);  cudaGetSymbolAddress((void**)&wo_l,  g_wo_l);
    cudaGetSymbolAddress((void**)&w1_h,  g_w1_h);  cudaGetSymbolAddress((void**)&w1_l,  g_w1_l);
    cudaGetSymbolAddress((void**)&w2_h,  g_w2_h);  cudaGetSymbolAddress((void**)&w2_l,  g_w2_l);

    const int SM_T128 = 2 * (2 * (128 * 40 * 2) + 2 * (32 * 136 * 2));   // 75776
    const int SM_T64  = 2 * (2 * (128 * 40 * 2) + 2 * (32 * 72 * 2));    // 59392

    cudaFuncSetAttribute(gemm_tc<0, false, 128, true, 2>,                 cudaFuncAttributeMaxDynamicSharedMemorySize, SM_T128);
    cudaFuncSetAttribute(gemm_tc<0, false, 64, false, 3>,                 cudaFuncAttributeMaxDynamicSharedMemorySize, SM_T64);
    cudaFuncSetAttribute(gemm_tc<EP_BIAS | EP_GELU, false, 128, true, 2>, cudaFuncAttributeMaxDynamicSharedMemorySize, SM_T128);
    cudaFuncSetAttribute(gemm_f16_lmhead, cudaFuncAttributeMaxDynamicSharedMemorySize, SM_F16);
    cudaFuncSetAttribute(attn_kernel, cudaFuncAttributeMaxDynamicSharedMemorySize, ATT_SMEM);

    split_all_kernel<<<(N_SPLIT_TOT + 255) / 256, 256>>>(
        wq, wk, wv, wo, w1, w2, emb,
        wqkv_h, wqkv_l, wo_h, wo_l, w1_h, w1_l, w2_h, w2_l, embf);
    { int n = MTOK * DMOD; embed_kernel<<<(n + 255) / 256, 256>>>(ids, emb, pe, x); }

    dim3 gQKV(QKVN / 128, MTOK / 128);
    dim3 gD64S(DMOD / 64, MTOK / 128, 2);
    dim3 gF(FFD / 128, MTOK / 128);
    float* p1 = part + MTOK * DMOD;

    for (int l = 0; l < LNUM; l++) {
        if (l == 0)
            ln_kernel<<<MTOK, 256>>>(x, nullptr, nullptr, nullptr,
                                     ln1w, ln1b, h_h, h_l, nullptr);
        else
            ln_kernel<<<MTOK, 256>>>(x, part, p1, b2 + (size_t)(l - 1) * DMOD,
                                     ln1w + l * DMOD, ln1b + l * DMOD, h_h, h_l, nullptr);

        gemm_tc<0, false, 128, true, 2><<<gQKV, 256, SM_T128>>>(
            h_h, h_l, wqkv_h + (size_t)l * DMOD * QKVN, wqkv_l + (size_t)l * DMOD * QKVN,
            nullptr, nullptr, nullptr, qkvh, qkvl, MTOK, QKVN, DMOD, DMOD, QKVN, QKVN);

        attn_kernel<<<dim3(SEQ / 64, HNUM, BAT), 256, ATT_SMEM>>>(qkvh, qkvl, amask, att_h, att_l);

        gemm_tc<0, false, 64, false, 3><<<gD64S, 256, SM_T64>>>(
            att_h, att_l, wo_h + (size_t)l * DMOD * DMOD, wo_l + (size_t)l * DMOD * DMOD,
            nullptr, nullptr, part, nullptr, nullptr, MTOK, DMOD, DMOD / 2, DMOD, DMOD, DMOD);

        ln_kernel<<<MTOK, 256>>>(x, part, p1, nullptr,
                                 ln2w + l * DMOD, ln2b + l * DMOD, h_h, h_l, nullptr);

        gemm_tc<EP_BIAS | EP_GELU, false, 128, true, 2><<<gF, 256, SM_T128>>>(
            h_h, h_l, w1_h + (size_t)l * DMOD * FFD, w1_l + (size_t)l * DMOD * FFD,
            b1 + (size_t)l * FFD, nullptr, nullptr, ff_h, ff_l, MTOK, FFD, DMOD, DMOD, FFD, FFD);

        gemm_tc<0, false, 64, false, 3><<<gD64S, 256, SM_T64>>>(
            ff_h, ff_l, w2_h + (size_t)l * FFD * DMOD, w2_l + (size_t)l * FFD * DMOD,
            nullptr, nullptr, part, nullptr, nullptr, MTOK, DMOD, FFD / 2, FFD, DMOD, DMOD);
    }

    // final LN (fused with last FF2 partials) -> fp16 h only
    ln_kernel<<<MTOK, 256>>>(x, part, p1, b2 + (size_t)(LNUM - 1) * DMOD,
                             lnfw, lnfb, nullptr, nullptr, hf);

    // lm_head: plain fp16 single-MMA GEMM
    dim3 gV(MTOK / 128, (VOC + 127) / 128);
    gemm_f16_lmhead<<<gV, 256, SM_F16>>>(hf, embf, out, MTOK, VOC, DMOD, DMOD, VOC);
}

// round 17
// speedup vs baseline: 2.3367x; 1.3833x over previous
#include <cuda_runtime.h>
#include <cuda_bf16.h>
#include <cuda_fp16.h>
#include <mma.h>
#include <math.h>
#include <cstdint>
#include <cstddef>
using namespace nvcuda;

#define LNUM 6
#define DMOD 768
#define HNUM 12
#define DKH  64
#define FFD  3072
#define VOC  50257
#define SEQ  1024
#define BAT  2
#define MTOK (BAT*SEQ)   // 2048
#define QKVN (3*DMOD)    // 2304

// ---------------- device scratch ----------------
__device__ float g_x  [MTOK*DMOD];
__device__ float g_part[2*MTOK*DMOD];
__device__ __half g_hf  [MTOK*DMOD];      // fp16 LN2 / final-LN output
__device__ __half g_attf[MTOK*DMOD];      // fp16 attention output
__device__ __half g_fff [MTOK*FFD];       // fp16 gelu(ff) output
__device__ __half g_embf[VOC*DMOD];
__device__ __half g_wof [LNUM*DMOD*DMOD];
__device__ __half g_w1f [LNUM*DMOD*FFD];
__device__ __half g_w2f [LNUM*FFD*DMOD];
__device__ __nv_bfloat16 g_qkvh[MTOK*QKVN], g_qkvl[MTOK*QKVN];
__device__ __nv_bfloat16 g_h_h [MTOK*DMOD],  g_h_l [MTOK*DMOD];
__device__ __nv_bfloat16 g_wqkv_h[LNUM*DMOD*QKVN], g_wqkv_l[LNUM*DMOD*QKVN];

// ---------------- helpers ----------------
__device__ __forceinline__ uint32_t smem_u32(const void* p) {
    uint32_t a;
    asm("{ .reg .u64 t; cvta.to.shared.u64 t, %1; cvt.u32.u64 %0, t; }" : "=r"(a) : "l"(p));
    return a;
}
__device__ __forceinline__ void cpa16(uint32_t dst, const void* src) {
    asm volatile("cp.async.cg.shared.global [%0], [%1], 16;" :: "r"(dst), "l"(src));
}
#define CP_COMMIT() asm volatile("cp.async.commit_group;" ::: "memory")
#define CP_WAIT1()  asm volatile("cp.async.wait_group 1;" ::: "memory")

__device__ __forceinline__ void split2(float v, __nv_bfloat16& hi, __nv_bfloat16& lo) {
    hi = __float2bfloat16(v);
    lo = __float2bfloat16(v - __bfloat162float(hi));
}

// ---------------- merged prepass split kernel ----------------
#define N_QKV (LNUM*DMOD*QKVN)
#define N_WO  (LNUM*DMOD*DMOD)
#define N_W1  (LNUM*DMOD*FFD)
#define N_W2  (LNUM*FFD*DMOD)
#define N_EMB (VOC*DMOD)
#define N_SPLIT_TOT (N_QKV + N_WO + N_W1 + N_W2 + N_EMB)

__global__ void split_all_kernel(const float* __restrict__ wq, const float* __restrict__ wk,
                                 const float* __restrict__ wv, const float* __restrict__ wo,
                                 const float* __restrict__ w1, const float* __restrict__ w2,
                                 const float* __restrict__ emb,
                                 __nv_bfloat16* __restrict__ qkv_h, __nv_bfloat16* __restrict__ qkv_l,
                                 __half* __restrict__ wo_f, __half* __restrict__ w1_f,
                                 __half* __restrict__ w2_f, __half* __restrict__ emb_f) {
    int i = blockIdx.x * blockDim.x + threadIdx.x;
    if (i >= N_SPLIT_TOT) return;
    if (i < N_QKV) {
        int l = i / (DMOD * QKVN);
        int rem = i % (DMOD * QKVN);
        int k = rem / QKVN, j = rem % QKVN;
        const float* s = (j < DMOD) ? wq : (j < 2 * DMOD) ? wk : wv;
        float v = s[(size_t)l * DMOD * DMOD + (size_t)k * DMOD + (j % DMOD)];
        split2(v, qkv_h[i], qkv_l[i]);
        return;
    }
    i -= N_QKV;
    if (i < N_WO)  { wo_f[i] = __float2half(wo[i]);  return; }
    i -= N_WO;
    if (i < N_W1)  { w1_f[i] = __float2half(w1[i]);  return; }
    i -= N_W1;
    if (i < N_W2)  { w2_f[i] = __float2half(w2[i]);  return; }
    i -= N_W2;
    emb_f[i] = __float2half(emb[i]);
}

// ---------------- embedding ----------------
__global__ void embed_kernel(const int* __restrict__ ids, const float* __restrict__ emb,
                             const float* __restrict__ pe, float* __restrict__ X) {
    int i = blockIdx.x * blockDim.x + threadIdx.x;
    if (i >= MTOK * DMOD) return;
    int d = i % DMOD, t = i / DMOD, s = t % SEQ;
    X[i] = emb[(size_t)ids[t] * DMOD + d] + pe[s * DMOD + d];
}

// ---------------- fused (split-K reduce) + layernorm ----------------
__global__ void ln_kernel(float* __restrict__ X,
                          const float* __restrict__ p0, const float* __restrict__ p1,
                          const float* __restrict__ pbias,
                          const float* __restrict__ w, const float* __restrict__ bvec,
                          __nv_bfloat16* __restrict__ Yh, __nv_bfloat16* __restrict__ Yl,
                          __half* __restrict__ Yf) {
    __shared__ float red[256];
    int row = blockIdx.x, tid = threadIdx.x;
    float4 xv = make_float4(0.f, 0.f, 0.f, 0.f);
    if (tid < 192) {
        xv = reinterpret_cast<const float4*>(X + (size_t)row * DMOD)[tid];
        if (p0) {
            float4 a = reinterpret_cast<const float4*>(p0 + (size_t)row * DMOD)[tid];
            float4 b = reinterpret_cast<const float4*>(p1 + (size_t)row * DMOD)[tid];
            xv.x += a.x + b.x; xv.y += a.y + b.y; xv.z += a.z + b.z; xv.w += a.w + b.w;
            if (pbias) {
                float4 c = reinterpret_cast<const float4*>(pbias)[tid];
                xv.x += c.x; xv.y += c.y; xv.z += c.z; xv.w += c.w;
            }
            reinterpret_cast<float4*>(X + (size_t)row * DMOD)[tid] = xv;
        }
    }
    float s = xv.x + xv.y + xv.z + xv.w;
    red[tid] = s; __syncthreads();
    for (int o = 128; o > 0; o >>= 1) { if (tid < o) red[tid] += red[tid + o]; __syncthreads(); }
    float mu = red[0] * (1.0f / DMOD); __syncthreads();
    float v = 0.f;
    if (tid < 192) {
        float a = xv.x - mu, b = xv.y - mu, c = xv.z - mu, d = xv.w - mu;
        v = a * a + b * b + c * c + d * d;
    }
    red[tid] = v; __syncthreads();
    for (int o = 128; o > 0; o >>= 1) { if (tid < o) red[tid] += red[tid + o]; __syncthreads(); }
    float rstd = rsqrtf(red[0] * (1.0f / DMOD) + 1e-5f);
    if (tid < 192) {
        float4 wv = reinterpret_cast<const float4*>(w)[tid];
        float4 bv = reinterpret_cast<const float4*>(bvec)[tid];
        float y[4];
        y[0] = (xv.x - mu) * rstd * wv.x + bv.x;
        y[1] = (xv.y - mu) * rstd * wv.y + bv.y;
        y[2] = (xv.z - mu) * rstd * wv.z + bv.z;
        y[3] = (xv.w - mu) * rstd * wv.w + bv.w;
        size_t off = (size_t)row * DMOD + tid * 4;
        if (Yh) {
            __nv_bfloat16 hb[4], lb[4];
            #pragma unroll
            for (int q = 0; q < 4; q++) split2(y[q], hb[q], lb[q]);
            *reinterpret_cast<uint2*>(Yh + off) = *reinterpret_cast<uint2*>(hb);
            *reinterpret_cast<uint2*>(Yl + off) = *reinterpret_cast<uint2*>(lb);
        }
        if (Yf) {
            __half hf[4];
            #pragma unroll
            for (int q = 0; q < 4; q++) hf[q] = __float2half(y[q]);
            *reinterpret_cast<uint2*>(Yf + off) = *reinterpret_cast<uint2*>(hf);
        }
    }
}

#define EP_BIAS 1
#define EP_GELU 2
#define EP_RES  4

__device__ __forceinline__ float gelu_exact(float x) {
    return 0.5f * x * (1.0f + erff(x * 0.70710678118654752f));
}

// ---------------- bf16 3-term GEMM (QKV only) ----------------
template<int EP, bool NG, int TN, bool WH, int MINB>
__global__ void __launch_bounds__(256, MINB)
gemm_tc(const __nv_bfloat16* __restrict__ Ah_g, const __nv_bfloat16* __restrict__ Al_g,
        const __nv_bfloat16* __restrict__ Bh_g, const __nv_bfloat16* __restrict__ Bl_g,
        const float* __restrict__ bias, const float* __restrict__ res,
        float* __restrict__ C, __nv_bfloat16* __restrict__ Chi, __nv_bfloat16* __restrict__ Clo,
        int M, int N, int K, int lda, int ldb, int ldc) {
    constexpr int ALD = 40;
    constexpr int BLD = TN + 8;
    constexpr int ABYTES = 128 * ALD * 2;
    constexpr int BBYTES = 32 * BLD * 2;
    constexpr int STAGEB = 2 * (ABYTES + BBYTES);
    constexpr int NJ = TN / 32;

    extern __shared__ char smem[];
    uint32_t sbase = smem_u32(smem);

    int tid = threadIdx.x, lane = tid & 31, wid = tid >> 5;
    int warp_m = wid & 3, warp_n = wid >> 2;
    int bm = blockIdx.y * 128, bn = blockIdx.x * TN;
    int kbase = blockIdx.z * K;
    int nch = K >> 5;

    wmma::fragment<wmma::accumulator, 16, 16, 16, float> acc[2][NJ];
    #pragma unroll
    for (int i = 0; i < 2; i++)
        #pragma unroll
        for (int j = 0; j < NJ; j++) wmma::fill_fragment(acc[i][j], 0.f);

    auto load_stage = [&](int s, int c) {
        int k0 = kbase + c * 32;
        uint32_t abase = sbase + s * STAGEB;
        #pragma unroll
        for (int hn = 0; hn < 2; hn++) {
            const __nv_bfloat16* g = hn ? Al_g : Ah_g;
            uint32_t db = abase + hn * ABYTES;
            #pragma unroll
            for (int i = 0; i < 2; i++) {
                int cid = tid + i * 256;
                int r = cid >> 2, seg = cid & 3;
                cpa16(db + (uint32_t)(r * ALD + seg * 8) * 2,
                      g + (size_t)(bm + r) * lda + k0 + seg * 8);
            }
        }
        uint32_t bbase = abase + 2 * ABYTES;
        constexpr int CH = TN / 8;
        constexpr int NIT = (32 * CH) / 256;
        #pragma unroll
        for (int hn = 0; hn < 2; hn++) {
            const __nv_bfloat16* g = hn ? Bl_g : Bh_g;
            uint32_t db = bbase + hn * BBYTES;
            #pragma unroll
            for (int i = 0; i < NIT; i++) {
                int cid = tid + i * 256;
                int kr = cid / CH, seg = cid % CH;
                cpa16(db + (uint32_t)(kr * BLD + seg * 8) * 2,
                      g + (size_t)(k0 + kr) * ldb + bn + seg * 8);
            }
        }
        CP_COMMIT();
    };

    auto do_mma = [&](int s) {
        char* base = smem + s * STAGEB;
        __nv_bfloat16* Ah = reinterpret_cast<__nv_bfloat16*>(base);
        __nv_bfloat16* Al = reinterpret_cast<__nv_bfloat16*>(base + ABYTES);
        __nv_bfloat16* Bh = reinterpret_cast<__nv_bfloat16*>(base + 2 * ABYTES);
        __nv_bfloat16* Bl = reinterpret_cast<__nv_bfloat16*>(base + 2 * ABYTES + BBYTES);
        #pragma unroll
        for (int kk = 0; kk < 2; kk++) {
            wmma::fragment<wmma::matrix_a, 16, 16, 16, __nv_bfloat16, wmma::row_major> ah[2], al[2];
            #pragma unroll
            for (int i = 0; i < 2; i++) {
                wmma::load_matrix_sync(ah[i], Ah + (warp_m * 32 + i * 16) * ALD + kk * 16, ALD);
                wmma::load_matrix_sync(al[i], Al + (warp_m * 32 + i * 16) * ALD + kk * 16, ALD);
            }
            #pragma unroll
            for (int j = 0; j < NJ; j++) {
                wmma::fragment<wmma::matrix_b, 16, 16, 16, __nv_bfloat16, wmma::row_major> bh, bl;
                wmma::load_matrix_sync(bh, Bh + (kk * 16) * BLD + warp_n * (TN / 2) + j * 16, BLD);
                wmma::load_matrix_sync(bl, Bl + (kk * 16) * BLD + warp_n * (TN / 2) + j * 16, BLD);
                #pragma unroll
                for (int i = 0; i < 2; i++) {
                    wmma::mma_sync(acc[i][j], ah[i], bh, acc[i][j]);
                    wmma::mma_sync(acc[i][j], ah[i], bl, acc[i][j]);
                    wmma::mma_sync(acc[i][j], al[i], bh, acc[i][j]);
                }
            }
        }
    };

    load_stage(0, 0);
    load_stage(1, 1);
    for (int c = 0; c < nch; c++) {
        CP_WAIT1();
        __syncthreads();
        do_mma(c & 1);
        __syncthreads();
        if (c + 2 < nch) load_stage(c & 1, c + 2);
        else CP_COMMIT();
    }

    size_t coff = (size_t)blockIdx.z * M * ldc;
    float* stg = reinterpret_cast<float*>(smem) + wid * (16 * 20);
    int r = lane >> 1, cb = (lane & 1) * 8;
    #pragma unroll
    for (int i = 0; i < 2; i++) {
        #pragma unroll
        for (int j = 0; j < NJ; j++) {
            wmma::store_matrix_sync(stg, acc[i][j], 20, wmma::mem_row_major);
            __syncwarp();
            int m = bm + warp_m * 32 + i * 16 + r;
            int n0 = bn + warp_n * (TN / 2) + j * 16 + cb;
            float v[8];
            #pragma unroll
            for (int q = 0; q < 8; q++) v[q] = stg[r * 20 + cb + q];
            if (EP & EP_BIAS) {
                float4 b0 = *reinterpret_cast<const float4*>(bias + n0);
                float4 b1 = *reinterpret_cast<const float4*>(bias + n0 + 4);
                v[0]+=b0.x; v[1]+=b0.y; v[2]+=b0.z; v[3]+=b0.w;
                v[4]+=b1.x; v[5]+=b1.y; v[6]+=b1.z; v[7]+=b1.w;
            }
            if (EP & EP_GELU) {
                #pragma unroll
                for (int q = 0; q < 8; q++) v[q] = gelu_exact(v[q]);
            }
            if (WH) {
                __nv_bfloat16 hb[8], lb[8];
                #pragma unroll
                for (int q = 0; q < 8; q++) split2(v[q], hb[q], lb[q]);
                *reinterpret_cast<uint4*>(Chi + (size_t)m * ldc + n0) = *reinterpret_cast<uint4*>(hb);
                *reinterpret_cast<uint4*>(Clo + (size_t)m * ldc + n0) = *reinterpret_cast<uint4*>(lb);
            } else if (NG) {
                #pragma unroll
                for (int q = 0; q < 8; q++)
                    if (n0 + q < N) C[coff + (size_t)m * ldc + n0 + q] = v[q];
            } else {
                float* cp = C + coff + (size_t)m * ldc + n0;
                *reinterpret_cast<float4*>(cp)     = make_float4(v[0], v[1], v[2], v[3]);
                *reinterpret_cast<float4*>(cp + 4) = make_float4(v[4], v[5], v[6], v[7]);
            }
            __syncwarp();
        }
    }
}

// ---------------- fp16 single-MMA GEMM (WO/FF1/FF2/lm_head) ----------------
// BCOL=false: B [K,ldb] row-major. BCOL=true: B [N,ldb] (A@B^T). WHF: write fp16 out.
template<int EP, bool BCOL, bool NG, int TN, bool WHF, int MINB>
__global__ void __launch_bounds__(256, MINB)
gemm_f16(const __half* __restrict__ A, const __half* __restrict__ B,
         const float* __restrict__ bias,
         float* __restrict__ C, __half* __restrict__ Cf,
         int M, int N, int K, int lda, int ldb, int ldc) {
    constexpr int ALD = 40;
    constexpr int BLD = BCOL ? 40 : (TN + 8);
    constexpr int ABYTES = 128 * ALD * 2;
    constexpr int BBYTES = BCOL ? (TN * 40 * 2) : (32 * BLD * 2);
    constexpr int STAGEB = ABYTES + BBYTES;
    constexpr int NJ = TN / 32;

    extern __shared__ char smem[];
    uint32_t sbase = smem_u32(smem);

    int tid = threadIdx.x, lane = tid & 31, wid = tid >> 5;
    int warp_m = wid & 3, warp_n = wid >> 2;
    int bm, bn;
    if (BCOL) { bm = blockIdx.x * 128; bn = blockIdx.y * TN; }   // m fastest: L2 reuse of B
    else      { bm = blockIdx.y * 128; bn = blockIdx.x * TN; }
    int kbase = blockIdx.z * K;
    int nch = K >> 5;

    wmma::fragment<wmma::accumulator, 16, 16, 16, float> acc[2][NJ];
    #pragma unroll
    for (int i = 0; i < 2; i++)
        #pragma unroll
        for (int j = 0; j < NJ; j++) wmma::fill_fragment(acc[i][j], 0.f);

    auto load_stage = [&](int s, int c) {
        int k0 = kbase + c * 32;
        uint32_t abase = sbase + s * STAGEB;
        #pragma unroll
        for (int i = 0; i < 2; i++) {
            int cid = tid + i * 256;
            int r = cid >> 2, seg = cid & 3;
            cpa16(abase + (uint32_t)(r * ALD + seg * 8) * 2,
                  A + (size_t)(bm + r) * lda + k0 + seg * 8);
        }
        uint32_t bbase = abase + ABYTES;
        if (BCOL) {
            constexpr int NITB = (TN * 4) / 256;
            #pragma unroll
            for (int i = 0; i < NITB; i++) {
                int cid = tid + i * 256;
                int r = cid >> 2, seg = cid & 3;
                int gn = bn + r;
                uint32_t d = bbase + (uint32_t)(r * 40 + seg * 8) * 2;
                if (!NG || gn < N)
                    cpa16(d, B + (size_t)gn * ldb + k0 + seg * 8);
                else
                    *reinterpret_cast<uint4*>(smem + (d - sbase)) = make_uint4(0, 0, 0, 0);
            }
        } else {
            constexpr int CH = TN / 8;
            constexpr int NIT = (32 * CH) / 256;
            #pragma unroll
            for (int i = 0; i < NIT; i++) {
                int cid = tid + i * 256;
                int kr = cid / CH, seg = cid % CH;
                cpa16(bbase + (uint32_t)(kr * BLD + seg * 8) * 2,
                      B + (size_t)(k0 + kr) * ldb + bn + seg * 8);
            }
        }
        CP_COMMIT();
    };

    auto do_mma = [&](int s) {
        char* base = smem + s * STAGEB;
        __half* As = reinterpret_cast<__half*>(base);
        __half* Bs = reinterpret_cast<__half*>(base + ABYTES);
        #pragma unroll
        for (int kk = 0; kk < 2; kk++) {
            wmma::fragment<wmma::matrix_a, 16, 16, 16, __half, wmma::row_major> af[2];
            #pragma unroll
            for (int i = 0; i < 2; i++)
                wmma::load_matrix_sync(af[i], As + (warp_m * 32 + i * 16) * ALD + kk * 16, ALD);
            #pragma unroll
            for (int j = 0; j < NJ; j++) {
                if (BCOL) {
                    wmma::fragment<wmma::matrix_b, 16, 16, 16, __half, wmma::col_major> bf;
                    wmma::load_matrix_sync(bf, Bs + (warp_n * (TN / 2) + j * 16) * 40 + kk * 16, 40);
                    #pragma unroll
                    for (int i = 0; i < 2; i++)
                        wmma::mma_sync(acc[i][j], af[i], bf, acc[i][j]);
                } else {
                    wmma::fragment<wmma::matrix_b, 16, 16, 16, __half, wmma::row_major> bf;
                    wmma::load_matrix_sync(bf, Bs + (kk * 16) * BLD + warp_n * (TN / 2) + j * 16, BLD);
                    #pragma unroll
                    for (int i = 0; i < 2; i++)
                        wmma::mma_sync(acc[i][j], af[i], bf, acc[i][j]);
                }
            }
        }
    };

    load_stage(0, 0);
    load_stage(1, 1);
    for (int c = 0; c < nch; c++) {
        CP_WAIT1();
        __syncthreads();
        do_mma(c & 1);
        __syncthreads();
        if (c + 2 < nch) load_stage(c & 1, c + 2);
        else CP_COMMIT();
    }

    size_t coff = (size_t)blockIdx.z * M * ldc;
    float* stg = reinterpret_cast<float*>(smem) + wid * (16 * 20);
    int r = lane >> 1, cb = (lane & 1) * 8;
    #pragma unroll
    for (int i = 0; i < 2; i++) {
        #pragma unroll
        for (int j = 0; j < NJ; j++) {
            wmma::store_matrix_sync(stg, acc[i][j], 20, wmma::mem_row_major);
            __syncwarp();
            int m = bm + warp_m * 32 + i * 16 + r;
            int n0 = bn + warp_n * (TN / 2) + j * 16 + cb;
            float v[8];
            #pragma unroll
            for (int q = 0; q < 8; q++) v[q] = stg[r * 20 + cb + q];
            if (EP & EP_BIAS) {
                float4 b0 = *reinterpret_cast<const float4*>(bias + n0);
                float4 b1 = *reinterpret_cast<const float4*>(bias + n0 + 4);
                v[0]+=b0.x; v[1]+=b0.y; v[2]+=b0.z; v[3]+=b0.w;
                v[4]+=b1.x; v[5]+=b1.y; v[6]+=b1.z; v[7]+=b1.w;
            }
            if (EP & EP_GELU) {
                #pragma unroll
                for (int q = 0; q < 8; q++) v[q] = gelu_exact(v[q]);
            }
            if (WHF) {
                __half hb[8];
                #pragma unroll
                for (int q = 0; q < 8; q++) hb[q] = __float2half(v[q]);
                *reinterpret_cast<uint4*>(Cf + (size_t)m * ldc + n0) = *reinterpret_cast<uint4*>(hb);
            } else if (NG) {
                #pragma unroll
                for (int q = 0; q < 8; q++)
                    if (n0 + q < N) C[coff + (size_t)m * ldc + n0 + q] = v[q];
            } else {
                float* cp = C + coff + (size_t)m * ldc + n0;
                *reinterpret_cast<float4*>(cp)     = make_float4(v[0], v[1], v[2], v[3]);
                *reinterpret_cast<float4*>(cp + 4) = make_float4(v[4], v[5], v[6], v[7]);
            }
            __syncwarp();
        }
    }
}

// ---------------- WMMA flash attention (bf16 3-term, fp32 softmax, fp16 out) ----------------
#define KLD 72
#define SLD 68
#define A_QH 0
#define A_QL (A_QH + 64*KLD*2)
#define A_KH (A_QL + 64*KLD*2)
#define A_KL (A_KH + 64*KLD*2)
#define A_VH (A_KL + 64*KLD*2)
#define A_VL (A_VH + 64*KLD*2)
#define A_PH (A_VL + 64*KLD*2)
#define A_PL (A_PH + 64*KLD*2)
#define A_S  (A_PL + 64*KLD*2)
#define A_O  (A_S + 64*SLD*4)
#define A_M  (A_O + 64*SLD*4)
#define A_L  (A_M + 64*4)
#define A_SC (A_L + 64*4)
#define A_MS (A_SC + 64*4)
#define ATT_SMEM (A_MS + 64*4)

__global__ void __launch_bounds__(256)
attn_kernel(const __nv_bfloat16* __restrict__ QKVh, const __nv_bfloat16* __restrict__ QKVl,
            const int* __restrict__ amask, __half* __restrict__ Of) {
    extern __shared__ char asmem[];
    __nv_bfloat16* Qh = reinterpret_cast<__nv_bfloat16*>(asmem + A_QH);
    __nv_bfloat16* Ql = reinterpret_cast<__nv_bfloat16*>(asmem + A_QL);
    __nv_bfloat16* Kh = reinterpret_cast<__nv_bfloat16*>(asmem + A_KH);
    __nv_bfloat16* Kl = reinterpret_cast<__nv_bfloat16*>(asmem + A_KL);
    __nv_bfloat16* Vh = reinterpret_cast<__nv_bfloat16*>(asmem + A_VH);
    __nv_bfloat16* Vl = reinterpret_cast<__nv_bfloat16*>(asmem + A_VL);
    __nv_bfloat16* Ph = reinterpret_cast<__nv_bfloat16*>(asmem + A_PH);
    __nv_bfloat16* Pl = reinterpret_cast<__nv_bfloat16*>(asmem + A_PL);
    float* S    = reinterpret_cast<float*>(asmem + A_S);
    float* O    = reinterpret_cast<float*>(asmem + A_O);
    float* sm_m = reinterpret_cast<float*>(asmem + A_M);
    float* sm_l = reinterpret_cast<float*>(asmem + A_L);
    float* sm_sc= reinterpret_cast<float*>(asmem + A_SC);
    int*   msk  = reinterpret_cast<int*>(asmem + A_MS);

    int b = blockIdx.z, hh = blockIdx.y;
    int qt = (SEQ / 64 - 1) - blockIdx.x;
    int q0 = qt * 64;
    int tid = threadIdx.x, wid = tid >> 5;
    int wr = wid & 3, wc = wid >> 2;

    for (int idx = tid; idx < 64 * 16; idx += 256) {
        int i = idx >> 4, d4 = idx & 15;
        size_t ga = (size_t)(b * SEQ + q0 + i) * QKVN + hh * DKH + d4 * 4;
        *reinterpret_cast<uint2*>(&Qh[i * KLD + d4 * 4]) = *reinterpret_cast<const uint2*>(&QKVh[ga]);
        *reinterpret_cast<uint2*>(&Ql[i * KLD + d4 * 4]) = *reinterpret_cast<const uint2*>(&QKVl[ga]);
    }
    for (int idx = tid; idx < 64 * SLD; idx += 256) O[idx] = 0.f;
    if (tid < 64) { sm_m[tid] = -1e30f; sm_l[tid] = 0.f; }

    for (int kt = 0; kt <= qt; kt++) {
        int k0 = kt * 64;
        __syncthreads();
        for (int idx = tid; idx < 64 * 16; idx += 256) {
            int j = idx >> 4, d4 = idx & 15;
            size_t gk = (size_t)(b * SEQ + k0 + j) * QKVN + DMOD + hh * DKH + d4 * 4;
            size_t gv = gk + DMOD;
            *reinterpret_cast<uint2*>(&Kh[j * KLD + d4 * 4]) = *reinterpret_cast<const uint2*>(&QKVh[gk]);
            *reinterpret_cast<uint2*>(&Kl[j * KLD + d4 * 4]) = *reinterpret_cast<const uint2*>(&QKVl[gk]);
            *reinterpret_cast<uint2*>(&Vh[j * KLD + d4 * 4]) = *reinterpret_cast<const uint2*>(&QKVh[gv]);
            *reinterpret_cast<uint2*>(&Vl[j * KLD + d4 * 4]) = *reinterpret_cast<const uint2*>(&QKVl[gv]);
        }
        if (tid < 64) msk[tid] = amask[b * SEQ + k0 + tid];
        __syncthreads();

        {
            wmma::fragment<wmma::accumulator, 16, 16, 16, float> sacc[2];
            wmma::fill_fragment(sacc[0], 0.f);
            wmma::fill_fragment(sacc[1], 0.f);
            #pragma unroll
            for (int ks = 0; ks < 4; ks++) {
                wmma::fragment<wmma::matrix_a, 16, 16, 16, __nv_bfloat16, wmma::row_major> a_h, a_l;
                wmma::load_matrix_sync(a_h, Qh + (wr * 16) * KLD + ks * 16, KLD);
                wmma::load_matrix_sync(a_l, Ql + (wr * 16) * KLD + ks * 16, KLD);
                #pragma unroll
                for (int t = 0; t < 2; t++) {
                    wmma::fragment<wmma::matrix_b, 16, 16, 16, __nv_bfloat16, wmma::col_major> b_h, b_l;
                    wmma::load_matrix_sync(b_h, Kh + (wc * 32 + t * 16) * KLD + ks * 16, KLD);
                    wmma::load_matrix_sync(b_l, Kl + (wc * 32 + t * 16) * KLD + ks * 16, KLD);
                    wmma::mma_sync(sacc[t], a_h, b_h, sacc[t]);
                    wmma::mma_sync(sacc[t], a_h, b_l, sacc[t]);
                    wmma::mma_sync(sacc[t], a_l, b_h, sacc[t]);
                }
            }
            #pragma unroll
            for (int t = 0; t < 2; t++)
                wmma::store_matrix_sync(S + (wr * 16) * SLD + wc * 32 + t * 16, sacc[t], SLD, wmma::mem_row_major);
        }
        __syncthreads();

        {
            int row = tid >> 2, qq = tid & 3;
            float sv[16];
            float tmax = -1e30f;
            #pragma unroll
            for (int jj = 0; jj < 16; jj++) {
                int j = qq * 16 + jj;
                float s = S[row * SLD + j] * 0.125f;
                if (msk[j] == 0) s = -1e9f;
                if (kt == qt && j > row) s = -1e9f;
                sv[jj] = s;
                tmax = fmaxf(tmax, s);
            }
            tmax = fmaxf(tmax, __shfl_xor_sync(0xffffffff, tmax, 1));
            tmax = fmaxf(tmax, __shfl_xor_sync(0xffffffff, tmax, 2));
            float mold = sm_m[row];
            float newm = fmaxf(mold, tmax);
            float psum = 0.f;
            __nv_bfloat16 hb[16], lb[16];
            #pragma unroll
            for (int jj = 0; jj < 16; jj++) {
                float p = __expf(sv[jj] - newm);
                psum += p;
                split2(p, hb[jj], lb[jj]);
            }
            *reinterpret_cast<uint4*>(&Ph[row * KLD + qq * 16])     = *reinterpret_cast<uint4*>(hb);
            *reinterpret_cast<uint4*>(&Ph[row * KLD + qq * 16 + 8]) = *reinterpret_cast<uint4*>(hb + 8);
            *reinterpret_cast<uint4*>(&Pl[row * KLD + qq * 16])     = *reinterpret_cast<uint4*>(lb);
            *reinterpret_cast<uint4*>(&Pl[row * KLD + qq * 16 + 8]) = *reinterpret_cast<uint4*>(lb + 8);
            psum += __shfl_xor_sync(0xffffffff, psum, 1);
            psum += __shfl_xor_sync(0xffffffff, psum, 2);
            if (qq == 0) {
                float sc = __expf(mold - newm);
                sm_sc[row] = sc;
                sm_l[row] = sm_l[row] * sc + psum;
                sm_m[row] = newm;
            }
        }
        __syncthreads();

        {
            wmma::fragment<wmma::accumulator, 16, 16, 16, float> oacc[2];
            wmma::fill_fragment(oacc[0], 0.f);
            wmma::fill_fragment(oacc[1], 0.f);
            #pragma unroll
            for (int ks = 0; ks < 4; ks++) {
                wmma::fragment<wmma::matrix_a, 16, 16, 16, __nv_bfloat16, wmma::row_major> a_h, a_l;
                wmma::load_matrix_sync(a_h, Ph + (wr * 16) * KLD + ks * 16, KLD);
                wmma::load_matrix_sync(a_l, Pl + (wr * 16) * KLD + ks * 16, KLD);
                #pragma unroll
                for (int t = 0; t < 2; t++) {
                    wmma::fragment<wmma::matrix_b, 16, 16, 16, __nv_bfloat16, wmma::row_major> b_h, b_l;
                    wmma::load_matrix_sync(b_h, Vh + (ks * 16) * KLD + wc * 32 + t * 16, KLD);
                    wmma::load_matrix_sync(b_l, Vl + (ks * 16) * KLD + wc * 32 + t * 16, KLD);
                    wmma::mma_sync(oacc[t], a_h, b_h, oacc[t]);
                    wmma::mma_sync(oacc[t], a_h, b_l, oacc[t]);
                    wmma::mma_sync(oacc[t], a_l, b_h, oacc[t]);
                }
            }
            #pragma unroll
            for (int t = 0; t < 2; t++)
                wmma::store_matrix_sync(S + (wr * 16) * SLD + wc * 32 + t * 16, oacc[t], SLD, wmma::mem_row_major);
        }
        __syncthreads();

        for (int idx = tid; idx < 4096; idx += 256) {
            int i = idx >> 6, d = idx & 63;
            O[i * SLD + d] = O[i * SLD + d] * sm_sc[i] + S[i * SLD + d];
        }
    }
    __syncthreads();
    for (int idx = tid; idx < 1024; idx += 256) {
        int i = idx >> 4, d4 = (idx & 15) * 4;
        float inv = 1.0f / sm_l[i];
        __half hb[4];
        #pragma unroll
        for (int q = 0; q < 4; q++)
            hb[q] = __float2half(O[i * SLD + d4 + q] * inv);
        size_t off = (size_t)(b * SEQ + q0 + i) * DMOD + hh * DKH + d4;
        *reinterpret_cast<uint2*>(Of + off) = *reinterpret_cast<uint2*>(hb);
    }
}

// ---------------- launch ----------------
extern "C" void kernel_launch(void* const* d_in, const int* in_sizes, int n_in,
                              void* d_out, int out_size) {
    const int*   ids   = (const int*)  d_in[0];
    const int*   amask = (const int*)  d_in[1];
    const float* emb   = (const float*)d_in[2];
    const float* pe    = (const float*)d_in[3];
    const float* wq    = (const float*)d_in[4];
    const float* wk    = (const float*)d_in[5];
    const float* wv    = (const float*)d_in[6];
    const float* wo    = (const float*)d_in[7];
    const float* ln1w  = (const float*)d_in[8];
    const float* ln1b  = (const float*)d_in[9];
    const float* ln2w  = (const float*)d_in[10];
    const float* ln2b  = (const float*)d_in[11];
    const float* w1    = (const float*)d_in[12];
    const float* b1    = (const float*)d_in[13];
    const float* w2    = (const float*)d_in[14];
    const float* b2    = (const float*)d_in[15];
    const float* lnfw  = (const float*)d_in[16];
    const float* lnfb  = (const float*)d_in[17];
    float* out = (float*)d_out;

    float *x, *part;
    __half *hf, *attf, *fff, *embf, *wof, *w1f, *w2f;
    __nv_bfloat16 *qkvh, *qkvl, *h_h, *h_l, *wqkv_h, *wqkv_l;
    cudaGetSymbolAddress((void**)&x,     g_x);
    cudaGetSymbolAddress((void**)&part,  g_part);
    cudaGetSymbolAddress((void**)&hf,    g_hf);
    cudaGetSymbolAddress((void**)&attf,  g_attf);
    cudaGetSymbolAddress((void**)&fff,   g_fff);
    cudaGetSymbolAddress((void**)&embf,  g_embf);
    cudaGetSymbolAddress((void**)&wof,   g_wof);
    cudaGetSymbolAddress((void**)&w1f,   g_w1f);
    cudaGetSymbolAddress((void**)&w2f,   g_w2f);
    cudaGetSymbolAddress((void**)&qkvh,  g_qkvh);  cudaGetSymbolAddress((void**)&qkvl,  g_qkvl);
    cudaGetSymbolAddress((void**)&h_h,   g_h_h);   cudaGetSymbolAddress((void**)&h_l,   g_h_l);
    cudaGetSymbolAddress((void**)&wqkv_h, g_wqkv_h); cudaGetSymbolAddress((void**)&wqkv_l, g_wqkv_l);

    const int SM_T128  = 2 * (2 * (128 * 40 * 2) + 2 * (32 * 136 * 2));   // bf16 TN=128: 75776
    const int SM_F128  = 2 * ((128 * 40 * 2) + (32 * 136 * 2));           // fp16 TN=128 row-B: 37888
    const int SM_F64   = 2 * ((128 * 40 * 2) + (32 * 72 * 2));            // fp16 TN=64 row-B: 29696
    const int SM_FCOL  = 2 * ((128 * 40 * 2) + (128 * 40 * 2));           // fp16 col-B: 40960

    cudaFuncSetAttribute(gemm_tc<0, false, 128, true, 2>,                  cudaFuncAttributeMaxDynamicSharedMemorySize, SM_T128);
    cudaFuncSetAttribute(gemm_f16<0, false, false, 64, false, 3>,          cudaFuncAttributeMaxDynamicSharedMemorySize, SM_F64);
    cudaFuncSetAttribute(gemm_f16<EP_BIAS | EP_GELU, false, false, 128, true, 2>, cudaFuncAttributeMaxDynamicSharedMemorySize, SM_F128);
    cudaFuncSetAttribute(gemm_f16<0, true, true, 128, false, 2>,           cudaFuncAttributeMaxDynamicSharedMemorySize, SM_FCOL);
    cudaFuncSetAttribute(attn_kernel, cudaFuncAttributeMaxDynamicSharedMemorySize, ATT_SMEM);

    split_all_kernel<<<(N_SPLIT_TOT + 255) / 256, 256>>>(
        wq, wk, wv, wo, w1, w2, emb,
        wqkv_h, wqkv_l, wof, w1f, w2f, embf);
    { int n = MTOK * DMOD; embed_kernel<<<(n + 255) / 256, 256>>>(ids, emb, pe, x); }

    dim3 gQKV(QKVN / 128, MTOK / 128);
    dim3 gD64S(DMOD / 64, MTOK / 128, 2);
    dim3 gF(FFD / 128, MTOK / 128);
    float* p1 = part + MTOK * DMOD;

    for (int l = 0; l < LNUM; l++) {
        if (l == 0)
            ln_kernel<<<MTOK, 256>>>(x, nullptr, nullptr, nullptr,
                                     ln1w, ln1b, h_h, h_l, nullptr);
        else
            ln_kernel<<<MTOK, 256>>>(x, part, p1, b2 + (size_t)(l - 1) * DMOD,
                                     ln1w + l * DMOD, ln1b + l * DMOD, h_h, h_l, nullptr);

        gemm_tc<0, false, 128, true, 2><<<gQKV, 256, SM_T128>>>(
            h_h, h_l, wqkv_h + (size_t)l * DMOD * QKVN, wqkv_l + (size_t)l * DMOD * QKVN,
            nullptr, nullptr, nullptr, qkvh, qkvl, MTOK, QKVN, DMOD, DMOD, QKVN, QKVN);

        attn_kernel<<<dim3(SEQ / 64, HNUM, BAT), 256, ATT_SMEM>>>(qkvh, qkvl, amask, attf);

        // WO fp16 split-K=2 -> partials
        gemm_f16<0, false, false, 64, false, 3><<<gD64S, 256, SM_F64>>>(
            attf, wof + (size_t)l * DMOD * DMOD, nullptr, part, nullptr,
            MTOK, DMOD, DMOD / 2, DMOD, DMOD, DMOD);

        // LN2 fused with WO partials -> fp16 h
        ln_kernel<<<MTOK, 256>>>(x, part, p1, nullptr,
                                 ln2w + l * DMOD, ln2b + l * DMOD, nullptr, nullptr, hf);

        // FF1 fp16 -> fp16 gelu output
        gemm_f16<EP_BIAS | EP_GELU, false, false, 128, true, 2><<<gF, 256, SM_F128>>>(
            hf, w1f + (size_t)l * DMOD * FFD, b1 + (size_t)l * FFD, nullptr, fff,
            MTOK, FFD, DMOD, DMOD, FFD, FFD);

        // FF2 fp16 split-K=2 -> partials
        gemm_f16<0, false, false, 64, false, 3><<<gD64S, 256, SM_F64>>>(
            fff, w2f + (size_t)l * FFD * DMOD, nullptr, part, nullptr,
            MTOK, DMOD, FFD / 2, FFD, DMOD, DMOD);
    }

    // final LN fused with last FF2 partials -> fp16
    ln_kernel<<<MTOK, 256>>>(x, part, p1, b2 + (size_t)(LNUM - 1) * DMOD,
                             lnfw, lnfb, nullptr, nullptr, hf);

    // lm_head fp16 (m fastest for L2 reuse of emb)
    dim3 gV(MTOK / 128, (VOC + 127) / 128);
    gemm_f16<0, true, true, 128, false, 2><<<gV, 256, SM_FCOL>>>(
        hf, embf, nullptr, out, nullptr, MTOK, VOC, DMOD, DMOD, DMOD, VOC);
}